// round 10
// baseline (speedup 1.0000x reference)
#include <cuda_runtime.h>
#include <cuda_bf16.h>
#include <math.h>
#include <stdint.h>

#define BATCH 4
#define DIM 128
#define HH 128
#define WW 128
#define HW (HH*WW)           // 16384
#define NP (BATCH*HW)        // 65536
#define HID 512
#define GC1 32
#define GC2 64
#define GC3 32

// ---------------- scratch ----------------
__device__ float g_off[BATCH*18*HW];
__device__ float g_y[BATCH*DIM*HW];            // shuffled concat, NCHW (tf32-rounded)
__device__ float g_t[(size_t)HID*NP];          // GEMM1 out, TRANSPOSED [HID][NP] (tf32-rounded)
__device__ float g_c2[(size_t)DIM*NP];         // GEMM2 out, TRANSPOSED [DIM][NP]
__device__ float g_w1f[DIM*HID];               // rna(scale1[k] * w1[k][n])
__device__ float g_w2t[HID*DIM];               // rna(w2)
__device__ float g_b1f[HID];
__device__ float g_bn1_sum[BATCH*DIM];
__device__ float g_bn1_sq [BATCH*DIM];
__device__ float g_scale1[DIM], g_shift1[DIM];
__device__ float g_bn2_sum[512*DIM];
__device__ float g_bn2_sq [512*DIM];
__device__ float g_scale2[DIM], g_shift2[DIM];

__device__ __forceinline__ float gelu_exact(float v) {
    return 0.5f * v * (1.0f + erff(v * 0.70710678118654752440f));
}
__device__ __forceinline__ uint32_t f2tf32(float f) {
    uint32_t r;
    asm("cvt.rna.tf32.f32 %0, %1;" : "=r"(r) : "f"(f));
    return r;
}
__device__ __forceinline__ float rnd_tf32(float f) { return __uint_as_float(f2tf32(f)); }
__device__ __forceinline__ void mma_tf32(float* c, const uint32_t* a, const uint32_t* b) {
    asm volatile("mma.sync.aligned.m16n8k8.row.col.f32.tf32.tf32.f32 "
        "{%0,%1,%2,%3}, {%4,%5,%6,%7}, {%8,%9}, {%0,%1,%2,%3};"
        : "+f"(c[0]), "+f"(c[1]), "+f"(c[2]), "+f"(c[3])
        : "r"(a[0]), "r"(a[1]), "r"(a[2]), "r"(a[3]), "r"(b[0]), "r"(b[1]));
}
__device__ __forceinline__ uint32_t smem_u32(const void* p) {
    uint32_t a;
    asm("{ .reg .u64 t; cvta.to.shared.u64 t, %1; cvt.u32.u64 %0, t; }" : "=r"(a) : "l"(p));
    return a;
}
#define CP_ASYNC16(dst, src) \
    asm volatile("cp.async.cg.shared.global [%0], [%1], 16;" :: "r"(dst), "l"(src))
#define CP_COMMIT() asm volatile("cp.async.commit_group;" ::: "memory")
#define CP_WAIT0()  asm volatile("cp.async.wait_group 0;" ::: "memory")

#define KSTR 136   // GEMM smem row stride (floats)
#define TSTR 130   // epilogue transpose stride
#define GSMEM (4*32*KSTR*4)   // 69632 B: A0,A1,B0,B1; epilogue ts (66560) overlays

// ======================= implicit-GEMM tensor conv =======================
#define ASTR 136
#define BSTR 40
#define CONV_SMEM ((96*ASTR + 288*BSTR)*4)   // 98304 bytes

template<int NOC, int D, int CBASE, int MODE>
__global__ __launch_bounds__(256) void k_conv_mma(const float* __restrict__ x,
                                                  const float* __restrict__ w,
                                                  const float* __restrict__ bias,
                                                  float* __restrict__ outp) {
    extern __shared__ uint32_t cs[];
    uint32_t* As = cs;               // [96][ASTR]
    uint32_t* Bs = cs + 96*ASTR;     // [288][BSTR]
    int tid = threadIdx.x;
    int lane = tid & 31, wid = tid >> 5;
    int g = lane >> 2, t = lane & 3;
    int warp_m = wid >> 1, warp_n = wid & 1;
    int y = blockIdx.x, b = blockIdx.y;

    for (int i = tid; i < 96*ASTR; i += 256) {
        int r = i / ASTR, c = i - r*ASTR;
        int ky = r >> 5, ic = r & 31;
        int ry = y + (ky - 1)*D;
        int gx = c - D;
        float v = 0.f;
        if (ry >= 0 && ry < 128 && gx >= 0 && gx < 128)
            v = x[(((size_t)b*DIM + CBASE + ic) << 14) + (ry << 7) + gx];
        As[i] = f2tf32(v);
    }
    for (int i = tid; i < 288*32; i += 256) {
        int k = i >> 5, oc = i & 31;
        int tap = k >> 5, ic = k & 31;
        float v = (oc < NOC) ? w[(oc*32 + ic)*9 + tap] : 0.f;
        Bs[k*BSTR + oc] = f2tf32(v);
    }
    __syncthreads();

    float acc[2][2][4] = {};
    int mbase = warp_m*32 + g;
    int nbase = warp_n*16 + g;
    #pragma unroll
    for (int tap = 0; tap < 9; tap++) {
        const int ky = tap / 3, kx = tap % 3;
        #pragma unroll
        for (int k8 = 0; k8 < 4; k8++) {
            int ar = ky*32 + k8*8 + t;
            int bk = tap*32 + k8*8 + t;
            uint32_t a[2][4], bb[2][2];
            #pragma unroll
            for (int mi = 0; mi < 2; mi++) {
                int col = mbase + mi*16 + kx*D;
                a[mi][0] = As[ar*ASTR + col];
                a[mi][1] = As[ar*ASTR + col + 8];
                a[mi][2] = As[(ar + 4)*ASTR + col];
                a[mi][3] = As[(ar + 4)*ASTR + col + 8];
            }
            #pragma unroll
            for (int nt = 0; nt < 2; nt++) {
                bb[nt][0] = Bs[bk*BSTR + nbase + nt*8];
                bb[nt][1] = Bs[(bk + 4)*BSTR + nbase + nt*8];
            }
            #pragma unroll
            for (int mi = 0; mi < 2; mi++)
                #pragma unroll
                for (int nt = 0; nt < 2; nt++)
                    mma_tf32(acc[mi][nt], a[mi], bb[nt]);
        }
    }
    #pragma unroll
    for (int mi = 0; mi < 2; mi++) {
        #pragma unroll
        for (int nt = 0; nt < 2; nt++) {
            int col = warp_n*16 + nt*8 + 2*t;
            #pragma unroll
            for (int cc = 0; cc < 2; cc++) {
                int oc = col + cc;
                if (oc >= NOC) continue;
                float bv = bias[oc];
                int px0 = warp_m*32 + mi*16 + g;
                float v0 = acc[mi][nt][cc] + bv;
                float v1 = acc[mi][nt][cc + 2] + bv;
                size_t base;
                if (MODE == 0) {
                    base = (((size_t)b*18 + oc) << 14) + (y << 7);
                    outp[base + px0]     = v0;
                    outp[base + px0 + 8] = v1;
                } else {
                    base = (((size_t)b*DIM + 65 + 2*oc) << 14) + (y << 7);
                    outp[base + px0]     = rnd_tf32(v0);
                    outp[base + px0 + 8] = rnd_tf32(v1);
                }
            }
        }
    }
}

// ======================= other conv kernels =======================

// depthwise 7x7 v3.  grid (16, 64, 4)
#define DSTR 39
__global__ __launch_bounds__(256) void k_dw7_v3(const float* __restrict__ x,
                                                const float* __restrict__ dww,
                                                const float* __restrict__ dwb) {
    __shared__ float s[38*DSTR];
    __shared__ float w[49];
    int tid = threadIdx.x;
    int b = blockIdx.z;
    int c = blockIdx.y;
    int ty0 = (blockIdx.x >> 2) * 32, tx0 = (blockIdx.x & 3) * 32;
    const float* xp = x + ((size_t)b*DIM + 32 + c)*HW;
    #pragma unroll 6
    for (int i = tid; i < 38*38; i += 256) {
        int sy = i / 38, sx = i - sy*38;
        int gy = ty0 + sy - 3, gx = tx0 + sx - 3;
        float v = 0.f;
        if (gy >= 0 && gy < 128 && gx >= 0 && gx < 128) v = xp[gy*WW + gx];
        s[sy*DSTR + sx] = v;
    }
    if (tid < 49) w[tid] = dww[c*49 + tid];
    __syncthreads();
    int txg = (tid & 7) * 4, ty = tid >> 3;
    float a0 = 0.f, a1 = 0.f, a2 = 0.f, a3 = 0.f;
    #pragma unroll
    for (int ky = 0; ky < 7; ky++) {
        const float* sp = s + (ty + ky)*DSTR + txg;
        float r[10];
        #pragma unroll
        for (int j = 0; j < 10; j++) r[j] = sp[j];
        #pragma unroll
        for (int kx = 0; kx < 7; kx++) {
            float wv = w[ky*7 + kx];
            a0 += r[kx]*wv; a1 += r[kx+1]*wv; a2 += r[kx+2]*wv; a3 += r[kx+3]*wv;
        }
    }
    float bias = dwb[c];
    int oldc = 32 + c;
    int newc = (oldc < 64) ? (2*oldc) : (2*(oldc-64)+1);
    float4 o;
    o.x = rnd_tf32(a0+bias); o.y = rnd_tf32(a1+bias);
    o.z = rnd_tf32(a2+bias); o.w = rnd_tf32(a3+bias);
    *(float4*)(g_y + ((size_t)b*DIM + newc)*HW + (ty0+ty)*WW + tx0+txg) = o;
}

// deformable depthwise v3.  grid (64, 4, 4)
__global__ __launch_bounds__(256) void k_deform_v3(const float* __restrict__ x,
                                                   const float* __restrict__ dfw) {
    __shared__ float wk[8][9];
    int tid = threadIdx.x;
    int b = blockIdx.z;
    int c0 = blockIdx.y * 8;
    int hw = blockIdx.x * 256 + tid;
    if (tid < 72) wk[tid/9][tid%9] = dfw[(c0 + tid/9)*9 + tid%9];
    __syncthreads();
    int h = hw >> 7, wc = hw & 127;
    const float* offb = g_off + (size_t)b*18*HW + hw;
    const float* xb = x + (((size_t)b*DIM + c0) << 14);
    float acc[8] = {};
    #pragma unroll
    for (int k = 0; k < 9; k++) {
        float dy = offb[(2*k  )*HW];
        float dx = offb[(2*k+1)*HW];
        float ys = (float)h - 1.0f + (float)(k/3) + dy;
        float xs = (float)wc - 1.0f + (float)(k%3) + dx;
        float y0 = floorf(ys), x0 = floorf(xs);
        float fy = ys - y0, fx = xs - x0;
        float vy0 = (y0 >= 0.f && y0 <= 127.f) ? 1.f : 0.f;
        float vy1 = (y0 >= -1.f && y0 <= 126.f) ? 1.f : 0.f;
        float vx0 = (x0 >= 0.f && x0 <= 127.f) ? 1.f : 0.f;
        float vx1 = (x0 >= -1.f && x0 <= 126.f) ? 1.f : 0.f;
        float w00 = (1.f-fy)*(1.f-fx) * vy0*vx0;
        float w01 = (1.f-fy)*fx       * vy0*vx1;
        float w10 = fy*(1.f-fx)       * vy1*vx0;
        float w11 = fy*fx             * vy1*vx1;
        int yi0 = min(max((int)y0, 0), 127);
        int yi1 = min(max((int)y0 + 1, 0), 127);
        int xi0 = min(max((int)x0, 0), 127);
        int xi1 = min(max((int)x0 + 1, 0), 127);
        int i00 = yi0*128 + xi0;
        int i01 = yi0*128 + xi1;
        int i10 = yi1*128 + xi0;
        int i11 = yi1*128 + xi1;
        #pragma unroll
        for (int cl = 0; cl < 8; cl++) {
            const float* xp = xb + (cl << 14);
            float sv = w00*xp[i00] + w01*xp[i01] + w10*xp[i10] + w11*xp[i11];
            acc[cl] += sv * wk[cl][k];
        }
    }
    #pragma unroll
    for (int cl = 0; cl < 8; cl++)
        g_y[(((size_t)b*DIM + 2*(c0+cl)) << 14) + hw] = rnd_tf32(acc[cl]);
}

// ======================= BN1 + folds =======================
__global__ void k_bn1_part() {
    int bc = blockIdx.x;
    const float* p = g_y + (size_t)bc*HW;
    float s = 0.f, q = 0.f;
    for (int i = threadIdx.x; i < HW; i += 256) { float v = p[i]; s += v; q += v*v; }
    __shared__ float ss[256], qs[256];
    ss[threadIdx.x] = s; qs[threadIdx.x] = q;
    __syncthreads();
    for (int st = 128; st > 0; st >>= 1) {
        if (threadIdx.x < st) { ss[threadIdx.x] += ss[threadIdx.x+st]; qs[threadIdx.x] += qs[threadIdx.x+st]; }
        __syncthreads();
    }
    if (threadIdx.x == 0) { g_bn1_sum[bc] = ss[0]; g_bn1_sq[bc] = qs[0]; }
}
__global__ __launch_bounds__(512) void k_bn1_fold(const float* __restrict__ g,
                                                  const float* __restrict__ be,
                                                  const float* __restrict__ w1,
                                                  const float* __restrict__ b1) {
    __shared__ float sh_shift[DIM];
    int tid = threadIdx.x;
    if (tid < DIM) {
        float s = 0.f, q = 0.f;
        #pragma unroll
        for (int b = 0; b < BATCH; b++) { s += g_bn1_sum[b*DIM + tid]; q += g_bn1_sq[b*DIM + tid]; }
        float mean = s * (1.0f/NP);
        float var  = q * (1.0f/NP) - mean*mean;
        float rstd = rsqrtf(var + 1e-5f);
        float sc = g[tid] * rstd;
        float sh = be[tid] - mean * sc;
        g_scale1[tid] = sc;
        g_shift1[tid] = sh;
        sh_shift[tid] = sh;
    }
    __syncthreads();
    float bf = b1[tid];
    for (int k = 0; k < DIM; k++)
        bf += sh_shift[k] * w1[k*HID + tid];
    g_b1f[tid] = bf;
}
// fold scale1 into w1 rows (rna) + pre-round w2.  grid 128 x 512
__global__ __launch_bounds__(512) void k_fold_w(const float* __restrict__ w1,
                                                const float* __restrict__ w2) {
    int k = blockIdx.x;           // 0..127
    int n = threadIdx.x;          // 0..511
    float sc = g_scale1[k];
    g_w1f[k*HID + n] = rnd_tf32(w1[k*HID + n] * sc);
    // w2 rows 4k..4k+3 (each DIM=128 wide): 512 elements
    int idx = k*512 + n;
    g_w2t[idx] = rnd_tf32(w2[idx]);
}

// ======================= cp.async tf32 GEMMs (2-stage pipeline) =======================
// smem: A0 | A1 | B0 | B1, each 32 rows x KSTR.  All operands pre-rounded to tf32.
__global__ __launch_bounds__(256) void k_gemm1() {
    extern __shared__ uint32_t sm4[];
    float* ts = (float*)sm4;
    uint32_t sbase = smem_u32(sm4);
    int tid = threadIdx.x;
    int lane = tid & 31, wid = tid >> 5;
    int g = lane >> 2, t = lane & 3;
    int warp_m = wid >> 2, warp_n = wid & 3;
    int p0 = blockIdx.y * 128, n0 = blockIdx.x * 128;
    int cb = (p0 >> 14) * DIM;
    int hw0 = p0 & (HW-1);
    int sr = tid >> 3;                 // unused helper
    (void)sr;

    // per-thread cp.async segments: s = tid + l*256 -> row s>>5, col4 (s&31)*4
    auto issue = [&](int kt, int bufsel) {
        uint32_t abuf = sbase + (uint32_t)bufsel*32*KSTR*4;
        uint32_t bbuf = sbase + (uint32_t)(2 + bufsel)*32*KSTR*4;
        #pragma unroll
        for (int l = 0; l < 4; l++) {
            int s = tid + l*256;
            int r = s >> 5, c4 = (s & 31) << 2;
            CP_ASYNC16(abuf + (uint32_t)(r*KSTR + c4)*4,
                       g_y + (size_t)(cb + kt + r)*HW + hw0 + c4);
        }
        #pragma unroll
        for (int l = 0; l < 4; l++) {
            int s = tid + l*256;
            int r = s >> 5, c4 = (s & 31) << 2;
            CP_ASYNC16(bbuf + (uint32_t)(r*KSTR + c4)*4,
                       g_w1f + (size_t)(kt + r)*HID + n0 + c4);
        }
        CP_COMMIT();
    };

    float acc[4][4][4] = {};
    issue(0, 0);
    for (int kc = 0; kc < 4; kc++) {
        CP_WAIT0();
        __syncthreads();
        if (kc < 3) issue((kc+1)*32, (kc+1) & 1);
        const uint32_t* Ac = sm4 + (kc & 1)*32*KSTR;
        const uint32_t* Bc = sm4 + (2 + (kc & 1))*32*KSTR;
        #pragma unroll
        for (int ks = 0; ks < 4; ks++) {
            uint32_t a[4][4], b[4][2];
            #pragma unroll
            for (int mi = 0; mi < 4; mi++) {
                int row = warp_m*64 + mi*16 + g;
                a[mi][0] = Ac[(ks*8 + t    )*KSTR + row];
                a[mi][1] = Ac[(ks*8 + t    )*KSTR + row + 8];
                a[mi][2] = Ac[(ks*8 + t + 4)*KSTR + row];
                a[mi][3] = Ac[(ks*8 + t + 4)*KSTR + row + 8];
            }
            #pragma unroll
            for (int nf = 0; nf < 4; nf++) {
                int col = warp_n*32 + nf*8 + g;
                b[nf][0] = Bc[(ks*8 + t    )*KSTR + col];
                b[nf][1] = Bc[(ks*8 + t + 4)*KSTR + col];
            }
            #pragma unroll
            for (int mi = 0; mi < 4; mi++)
                #pragma unroll
                for (int nf = 0; nf < 4; nf++)
                    mma_tf32(acc[mi][nf], a[mi], b[nf]);
        }
    }
    __syncthreads();
    // epilogue: bias + gelu, tf32-round, smem transpose, coalesced transposed store
    #pragma unroll
    for (int mi = 0; mi < 4; mi++) {
        int row = warp_m*64 + mi*16 + g;
        #pragma unroll
        for (int nf = 0; nf < 4; nf++) {
            int col = warp_n*32 + nf*8 + 2*t;
            float b0v = g_b1f[n0 + col], b1v = g_b1f[n0 + col + 1];
            ts[row*TSTR + col]       = rnd_tf32(gelu_exact(acc[mi][nf][0] + b0v));
            ts[row*TSTR + col + 1]   = rnd_tf32(gelu_exact(acc[mi][nf][1] + b1v));
            ts[(row+8)*TSTR + col]   = rnd_tf32(gelu_exact(acc[mi][nf][2] + b0v));
            ts[(row+8)*TSTR + col+1] = rnd_tf32(gelu_exact(acc[mi][nf][3] + b1v));
        }
    }
    __syncthreads();
    #pragma unroll
    for (int l = 0; l < 64; l++) {
        int i = tid + l*256;
        int n = i >> 7, p = i & 127;
        g_t[(size_t)(n0 + n)*NP + p0 + p] = ts[p*TSTR + n];
    }
}

// GEMM2 + fused BN2 partials (cp.async 2-stage)
__global__ __launch_bounds__(256) void k_gemm2(const float* __restrict__ b2) {
    extern __shared__ uint32_t sm4[];
    float* ts = (float*)sm4;
    __shared__ float rs[256], rq[256];
    uint32_t sbase = smem_u32(sm4);
    int tid = threadIdx.x;
    int lane = tid & 31, wid = tid >> 5;
    int g = lane >> 2, t = lane & 3;
    int warp_m = wid >> 2, warp_n = wid & 3;
    int p0 = blockIdx.x * 128;

    auto issue = [&](int kt, int bufsel) {
        uint32_t abuf = sbase + (uint32_t)bufsel*32*KSTR*4;
        uint32_t bbuf = sbase + (uint32_t)(2 + bufsel)*32*KSTR*4;
        #pragma unroll
        for (int l = 0; l < 4; l++) {
            int s = tid + l*256;
            int r = s >> 5, c4 = (s & 31) << 2;
            CP_ASYNC16(abuf + (uint32_t)(r*KSTR + c4)*4,
                       g_t + (size_t)(kt + r)*NP + p0 + c4);
        }
        #pragma unroll
        for (int l = 0; l < 4; l++) {
            int s = tid + l*256;
            int r = s >> 5, c4 = (s & 31) << 2;
            CP_ASYNC16(bbuf + (uint32_t)(r*KSTR + c4)*4,
                       g_w2t + (size_t)(kt + r)*DIM + c4);
        }
        CP_COMMIT();
    };

    float acc[4][4][4] = {};
    issue(0, 0);
    for (int kc = 0; kc < 16; kc++) {
        CP_WAIT0();
        __syncthreads();
        if (kc < 15) issue((kc+1)*32, (kc+1) & 1);
        const uint32_t* Ac = sm4 + (kc & 1)*32*KSTR;
        const uint32_t* Bc = sm4 + (2 + (kc & 1))*32*KSTR;
        #pragma unroll
        for (int ks = 0; ks < 4; ks++) {
            uint32_t a[4][4], b[4][2];
            #pragma unroll
            for (int mi = 0; mi < 4; mi++) {
                int row = warp_m*64 + mi*16 + g;
                a[mi][0] = Ac[(ks*8 + t    )*KSTR + row];
                a[mi][1] = Ac[(ks*8 + t    )*KSTR + row + 8];
                a[mi][2] = Ac[(ks*8 + t + 4)*KSTR + row];
                a[mi][3] = Ac[(ks*8 + t + 4)*KSTR + row + 8];
            }
            #pragma unroll
            for (int nf = 0; nf < 4; nf++) {
                int col = warp_n*32 + nf*8 + g;
                b[nf][0] = Bc[(ks*8 + t    )*KSTR + col];
                b[nf][1] = Bc[(ks*8 + t + 4)*KSTR + col];
            }
            #pragma unroll
            for (int mi = 0; mi < 4; mi++)
                #pragma unroll
                for (int nf = 0; nf < 4; nf++)
                    mma_tf32(acc[mi][nf], a[mi], b[nf]);
        }
    }
    __syncthreads();
    #pragma unroll
    for (int mi = 0; mi < 4; mi++) {
        int row = warp_m*64 + mi*16 + g;
        #pragma unroll
        for (int nf = 0; nf < 4; nf++) {
            int col = warp_n*32 + nf*8 + 2*t;
            float b0v = b2[col], b1v = b2[col + 1];
            ts[row*TSTR + col]       = acc[mi][nf][0] + b0v;
            ts[row*TSTR + col + 1]   = acc[mi][nf][1] + b1v;
            ts[(row+8)*TSTR + col]   = acc[mi][nf][2] + b0v;
            ts[(row+8)*TSTR + col+1] = acc[mi][nf][3] + b1v;
        }
    }
    __syncthreads();
    #pragma unroll
    for (int l = 0; l < 64; l++) {
        int i = tid + l*256;
        int n = i >> 7, p = i & 127;
        g_c2[(size_t)n*NP + p0 + p] = ts[p*TSTR + n];
    }
    {
        int n = tid & 127;
        int ph = tid >> 7;
        float s = 0.f, q = 0.f;
        for (int p = ph; p < 128; p += 2) {
            float v = ts[p*TSTR + n];
            s += v; q += v*v;
        }
        rs[tid] = s; rq[tid] = q;
        __syncthreads();
        if (tid < 128) {
            g_bn2_sum[blockIdx.x*128 + tid] = rs[tid] + rs[tid+128];
            g_bn2_sq [blockIdx.x*128 + tid] = rq[tid] + rq[tid+128];
        }
    }
}

// ======================= BN2 final + output =======================
__global__ void k_bn2_final(const float* __restrict__ g, const float* __restrict__ be) {
    int c = blockIdx.x;
    int tid = threadIdx.x;
    __shared__ float ss[128], qs[128];
    float s = 0.f, q = 0.f;
    for (int i = tid; i < 512; i += 128) {
        s += g_bn2_sum[i*128 + c];
        q += g_bn2_sq [i*128 + c];
    }
    ss[tid] = s; qs[tid] = q;
    __syncthreads();
    for (int st = 64; st > 0; st >>= 1) {
        if (tid < st) { ss[tid] += ss[tid+st]; qs[tid] += qs[tid+st]; }
        __syncthreads();
    }
    if (tid == 0) {
        float mean = ss[0] * (1.0f/NP);
        float var  = qs[0] * (1.0f/NP) - mean*mean;
        float rstd = rsqrtf(var + 1e-5f);
        float sc = g[c] * rstd;
        g_scale2[c] = sc;
        g_shift2[c] = be[c] - mean * sc;
    }
}
__global__ void k_final(const float* __restrict__ x, float* __restrict__ out) {
    int i = blockIdx.x * 256 + threadIdx.x;
    int b = i >> 21;
    int c = (i >> 14) & 127;
    int hw = i & 16383;
    float v = g_c2[(size_t)c*NP + (b<<14) + hw] * g_scale2[c] + g_shift2[c];
    out[i] = gelu_exact(x[i] + v);
}

// ================================ launch ================================
extern "C" void kernel_launch(void* const* d_in, const int* in_sizes, int n_in,
                              void* d_out, int out_size) {
    const float* x        = (const float*)d_in[0];
    const float* offset_w = (const float*)d_in[1];
    const float* offset_b = (const float*)d_in[2];
    const float* deform_w = (const float*)d_in[3];
    const float* dw_w     = (const float*)d_in[4];
    const float* dw_b     = (const float*)d_in[5];
    const float* dw2_w    = (const float*)d_in[6];
    const float* dw2_b    = (const float*)d_in[7];
    const float* bn1_g    = (const float*)d_in[8];
    const float* bn1_b    = (const float*)d_in[9];
    const float* w1       = (const float*)d_in[10];
    const float* b1       = (const float*)d_in[11];
    const float* w2       = (const float*)d_in[12];
    const float* b2       = (const float*)d_in[13];
    const float* bn2_g    = (const float*)d_in[14];
    const float* bn2_b    = (const float*)d_in[15];
    float* out = (float*)d_out;

    static int inited = 0;
    static cudaStream_t sA, sB, sC;
    static cudaEvent_t e0, eA, eB, eC;
    if (!inited) {
        cudaFuncSetAttribute(k_gemm1, cudaFuncAttributeMaxDynamicSharedMemorySize, GSMEM);
        cudaFuncSetAttribute(k_gemm2, cudaFuncAttributeMaxDynamicSharedMemorySize, GSMEM);
        cudaFuncSetAttribute(k_conv_mma<18,1,0,0>, cudaFuncAttributeMaxDynamicSharedMemorySize, CONV_SMEM);
        cudaFuncSetAttribute(k_conv_mma<32,2,96,1>, cudaFuncAttributeMaxDynamicSharedMemorySize, CONV_SMEM);
        cudaStreamCreateWithFlags(&sA, cudaStreamNonBlocking);
        cudaStreamCreateWithFlags(&sB, cudaStreamNonBlocking);
        cudaStreamCreateWithFlags(&sC, cudaStreamNonBlocking);
        cudaEventCreateWithFlags(&e0, cudaEventDisableTiming);
        cudaEventCreateWithFlags(&eA, cudaEventDisableTiming);
        cudaEventCreateWithFlags(&eB, cudaEventDisableTiming);
        cudaEventCreateWithFlags(&eC, cudaEventDisableTiming);
        inited = 1;
    }

    float* goffp; cudaGetSymbolAddress((void**)&goffp, g_off);
    float* gyp;   cudaGetSymbolAddress((void**)&gyp, g_y);

    dim3 blk256(256);
    cudaEventRecord(e0, 0);
    cudaStreamWaitEvent(sA, e0, 0);
    k_conv_mma<18,1,0,0> <<<dim3(128, BATCH), blk256, CONV_SMEM, sA>>>(x, offset_w, offset_b, goffp);
    k_deform_v3          <<<dim3(64, 4, BATCH), blk256, 0, sA>>>(x, deform_w);
    cudaEventRecord(eA, sA);
    cudaStreamWaitEvent(sB, e0, 0);
    k_conv_mma<32,2,96,1><<<dim3(128, BATCH), blk256, CONV_SMEM, sB>>>(x, dw2_w, dw2_b, gyp);
    cudaEventRecord(eB, sB);
    cudaStreamWaitEvent(sC, e0, 0);
    k_dw7_v3             <<<dim3(16, GC2, BATCH), blk256, 0, sC>>>(x, dw_w, dw_b);
    cudaEventRecord(eC, sC);
    cudaStreamWaitEvent(0, eA, 0);
    cudaStreamWaitEvent(0, eB, 0);
    cudaStreamWaitEvent(0, eC, 0);

    k_bn1_part<<<BATCH*DIM, blk256>>>();
    k_bn1_fold<<<1, 512>>>(bn1_g, bn1_b, w1, b1);
    k_fold_w  <<<128, 512>>>(w1, w2);

    k_gemm1<<<dim3(HID/128, NP/128), 256, GSMEM>>>();
    k_gemm2<<<NP/128, 256, GSMEM>>>(b2);

    k_bn2_final<<<DIM, 128>>>(bn2_g, bn2_b);
    k_final<<<(size_t)NP*DIM/256, blk256>>>(x, out);
}

// round 11
// speedup vs baseline: 1.4681x; 1.4681x over previous
#include <cuda_runtime.h>
#include <cuda_bf16.h>
#include <math.h>
#include <stdint.h>

#define BATCH 4
#define DIM 128
#define HH 128
#define WW 128
#define HW (HH*WW)           // 16384
#define NP (BATCH*HW)        // 65536
#define HID 512
#define GC1 32
#define GC2 64
#define GC3 32

// ---------------- scratch ----------------
__device__ float g_off[BATCH*18*HW];
__device__ float g_y[BATCH*DIM*HW];            // shuffled concat, NCHW
__device__ float g_t[(size_t)HID*NP];          // GEMM1 out, TRANSPOSED [HID][NP]
__device__ float g_c2[(size_t)DIM*NP];         // GEMM2 out, TRANSPOSED [DIM][NP]
__device__ float g_b1f[HID];
__device__ float g_bn1_sum[BATCH*DIM];
__device__ float g_bn1_sq [BATCH*DIM];
__device__ float g_scale1[DIM], g_shift1[DIM];
__device__ float g_bn2_sum[512*DIM];
__device__ float g_bn2_sq [512*DIM];
__device__ float g_scale2[DIM], g_shift2[DIM];

__device__ __forceinline__ float gelu_exact(float v) {
    return 0.5f * v * (1.0f + erff(v * 0.70710678118654752440f));
}
__device__ __forceinline__ uint32_t f2tf32(float f) {
    uint32_t r;
    asm("cvt.rna.tf32.f32 %0, %1;" : "=r"(r) : "f"(f));
    return r;
}
__device__ __forceinline__ void mma_tf32(float* c, const uint32_t* a, const uint32_t* b) {
    asm volatile("mma.sync.aligned.m16n8k8.row.col.f32.tf32.tf32.f32 "
        "{%0,%1,%2,%3}, {%4,%5,%6,%7}, {%8,%9}, {%0,%1,%2,%3};"
        : "+f"(c[0]), "+f"(c[1]), "+f"(c[2]), "+f"(c[3])
        : "r"(a[0]), "r"(a[1]), "r"(a[2]), "r"(a[3]), "r"(b[0]), "r"(b[1]));
}

#define KSTR 136   // GEMM smem row stride
#define TSTR 130   // epilogue transpose stride
#define GSMEM (128*TSTR*4)   // 66560 bytes

// ======================= implicit-GEMM tensor conv =======================
#define ASTR 136
#define BSTR 40
#define CONV_SMEM ((96*ASTR + 288*BSTR)*4)   // 98304 bytes

template<int NOC, int D, int CBASE, int MODE>
__global__ __launch_bounds__(256) void k_conv_mma(const float* __restrict__ x,
                                                  const float* __restrict__ w,
                                                  const float* __restrict__ bias,
                                                  float* __restrict__ outp) {
    extern __shared__ uint32_t cs[];
    uint32_t* As = cs;               // [96][ASTR]
    uint32_t* Bs = cs + 96*ASTR;     // [288][BSTR]
    int tid = threadIdx.x;
    int lane = tid & 31, wid = tid >> 5;
    int g = lane >> 2, t = lane & 3;
    int warp_m = wid >> 1, warp_n = wid & 1;
    int y = blockIdx.x, b = blockIdx.y;

    for (int i = tid; i < 96*ASTR; i += 256) {
        int r = i / ASTR, c = i - r*ASTR;
        int ky = r >> 5, ic = r & 31;
        int ry = y + (ky - 1)*D;
        int gx = c - D;
        float v = 0.f;
        if (ry >= 0 && ry < 128 && gx >= 0 && gx < 128)
            v = x[(((size_t)b*DIM + CBASE + ic) << 14) + (ry << 7) + gx];
        As[i] = f2tf32(v);
    }
    for (int i = tid; i < 288*32; i += 256) {
        int k = i >> 5, oc = i & 31;
        int tap = k >> 5, ic = k & 31;
        float v = (oc < NOC) ? w[(oc*32 + ic)*9 + tap] : 0.f;
        Bs[k*BSTR + oc] = f2tf32(v);
    }
    __syncthreads();

    float acc[2][2][4] = {};
    int mbase = warp_m*32 + g;
    int nbase = warp_n*16 + g;
    #pragma unroll
    for (int tap = 0; tap < 9; tap++) {
        const int ky = tap / 3, kx = tap % 3;
        #pragma unroll
        for (int k8 = 0; k8 < 4; k8++) {
            int ar = ky*32 + k8*8 + t;
            int bk = tap*32 + k8*8 + t;
            uint32_t a[2][4], bb[2][2];
            #pragma unroll
            for (int mi = 0; mi < 2; mi++) {
                int col = mbase + mi*16 + kx*D;
                a[mi][0] = As[ar*ASTR + col];
                a[mi][1] = As[ar*ASTR + col + 8];
                a[mi][2] = As[(ar + 4)*ASTR + col];
                a[mi][3] = As[(ar + 4)*ASTR + col + 8];
            }
            #pragma unroll
            for (int nt = 0; nt < 2; nt++) {
                bb[nt][0] = Bs[bk*BSTR + nbase + nt*8];
                bb[nt][1] = Bs[(bk + 4)*BSTR + nbase + nt*8];
            }
            #pragma unroll
            for (int mi = 0; mi < 2; mi++)
                #pragma unroll
                for (int nt = 0; nt < 2; nt++)
                    mma_tf32(acc[mi][nt], a[mi], bb[nt]);
        }
    }
    #pragma unroll
    for (int mi = 0; mi < 2; mi++) {
        #pragma unroll
        for (int nt = 0; nt < 2; nt++) {
            int col = warp_n*16 + nt*8 + 2*t;
            #pragma unroll
            for (int cc = 0; cc < 2; cc++) {
                int oc = col + cc;
                if (oc >= NOC) continue;
                float bv = bias[oc];
                int px0 = warp_m*32 + mi*16 + g;
                size_t base;
                if (MODE == 0) base = (((size_t)b*18 + oc) << 14) + (y << 7);
                else           base = (((size_t)b*DIM + 65 + 2*oc) << 14) + (y << 7);
                outp[base + px0]     = acc[mi][nt][cc]     + bv;
                outp[base + px0 + 8] = acc[mi][nt][cc + 2] + bv;
            }
        }
    }
}

// ======================= other conv kernels =======================

// depthwise 7x7 v3.  grid (16, 64, 4)
#define DSTR 39
__global__ __launch_bounds__(256) void k_dw7_v3(const float* __restrict__ x,
                                                const float* __restrict__ dww,
                                                const float* __restrict__ dwb) {
    __shared__ float s[38*DSTR];
    __shared__ float w[49];
    int tid = threadIdx.x;
    int b = blockIdx.z;
    int c = blockIdx.y;
    int ty0 = (blockIdx.x >> 2) * 32, tx0 = (blockIdx.x & 3) * 32;
    const float* xp = x + ((size_t)b*DIM + 32 + c)*HW;
    #pragma unroll 6
    for (int i = tid; i < 38*38; i += 256) {
        int sy = i / 38, sx = i - sy*38;
        int gy = ty0 + sy - 3, gx = tx0 + sx - 3;
        float v = 0.f;
        if (gy >= 0 && gy < 128 && gx >= 0 && gx < 128) v = xp[gy*WW + gx];
        s[sy*DSTR + sx] = v;
    }
    if (tid < 49) w[tid] = dww[c*49 + tid];
    __syncthreads();
    int txg = (tid & 7) * 4, ty = tid >> 3;
    float a0 = 0.f, a1 = 0.f, a2 = 0.f, a3 = 0.f;
    #pragma unroll
    for (int ky = 0; ky < 7; ky++) {
        const float* sp = s + (ty + ky)*DSTR + txg;
        float r[10];
        #pragma unroll
        for (int j = 0; j < 10; j++) r[j] = sp[j];
        #pragma unroll
        for (int kx = 0; kx < 7; kx++) {
            float wv = w[ky*7 + kx];
            a0 += r[kx]*wv; a1 += r[kx+1]*wv; a2 += r[kx+2]*wv; a3 += r[kx+3]*wv;
        }
    }
    float bias = dwb[c];
    int oldc = 32 + c;
    int newc = (oldc < 64) ? (2*oldc) : (2*(oldc-64)+1);
    float4 o; o.x = a0+bias; o.y = a1+bias; o.z = a2+bias; o.w = a3+bias;
    *(float4*)(g_y + ((size_t)b*DIM + newc)*HW + (ty0+ty)*WW + tx0+txg) = o;
}

// deformable depthwise v3.  grid (64, 4, 4)
__global__ __launch_bounds__(256) void k_deform_v3(const float* __restrict__ x,
                                                   const float* __restrict__ dfw) {
    __shared__ float wk[8][9];
    int tid = threadIdx.x;
    int b = blockIdx.z;
    int c0 = blockIdx.y * 8;
    int hw = blockIdx.x * 256 + tid;
    if (tid < 72) wk[tid/9][tid%9] = dfw[(c0 + tid/9)*9 + tid%9];
    __syncthreads();
    int h = hw >> 7, wc = hw & 127;
    const float* offb = g_off + (size_t)b*18*HW + hw;
    const float* xb = x + (((size_t)b*DIM + c0) << 14);
    float acc[8] = {};
    #pragma unroll
    for (int k = 0; k < 9; k++) {
        float dy = offb[(2*k  )*HW];
        float dx = offb[(2*k+1)*HW];
        float ys = (float)h - 1.0f + (float)(k/3) + dy;
        float xs = (float)wc - 1.0f + (float)(k%3) + dx;
        float y0 = floorf(ys), x0 = floorf(xs);
        float fy = ys - y0, fx = xs - x0;
        float vy0 = (y0 >= 0.f && y0 <= 127.f) ? 1.f : 0.f;
        float vy1 = (y0 >= -1.f && y0 <= 126.f) ? 1.f : 0.f;
        float vx0 = (x0 >= 0.f && x0 <= 127.f) ? 1.f : 0.f;
        float vx1 = (x0 >= -1.f && x0 <= 126.f) ? 1.f : 0.f;
        float w00 = (1.f-fy)*(1.f-fx) * vy0*vx0;
        float w01 = (1.f-fy)*fx       * vy0*vx1;
        float w10 = fy*(1.f-fx)       * vy1*vx0;
        float w11 = fy*fx             * vy1*vx1;
        int yi0 = min(max((int)y0, 0), 127);
        int yi1 = min(max((int)y0 + 1, 0), 127);
        int xi0 = min(max((int)x0, 0), 127);
        int xi1 = min(max((int)x0 + 1, 0), 127);
        int i00 = yi0*128 + xi0;
        int i01 = yi0*128 + xi1;
        int i10 = yi1*128 + xi0;
        int i11 = yi1*128 + xi1;
        #pragma unroll
        for (int cl = 0; cl < 8; cl++) {
            const float* xp = xb + (cl << 14);
            float sv = w00*xp[i00] + w01*xp[i01] + w10*xp[i10] + w11*xp[i11];
            acc[cl] += sv * wk[cl][k];
        }
    }
    #pragma unroll
    for (int cl = 0; cl < 8; cl++)
        g_y[(((size_t)b*DIM + 2*(c0+cl)) << 14) + hw] = acc[cl];
}

// ======================= BN1 (split by producer) =======================
// MODE 0: 32 channels written by deform (even 0..62).  grid BATCH*32
// MODE 1: 96 channels written by dw7+dil3.             grid BATCH*96
template<int MODE>
__global__ __launch_bounds__(256) void k_bn1_part(void) {
    int nch = (MODE == 0) ? 32 : 96;
    int b = blockIdx.x / nch;
    int j = blockIdx.x % nch;
    int c;
    if (MODE == 0) c = 2*j;
    else           c = (j < 64) ? (2*j + 1) : (64 + 2*(j - 64));
    const float4* p = (const float4*)(g_y + (((size_t)b*DIM + c) << 14));
    float s = 0.f, q = 0.f;
    for (int i = threadIdx.x; i < HW/4; i += 256) {
        float4 v = p[i];
        s += v.x + v.y + v.z + v.w;
        q += v.x*v.x + v.y*v.y + v.z*v.z + v.w*v.w;
    }
    __shared__ float ss[256], qs[256];
    ss[threadIdx.x] = s; qs[threadIdx.x] = q;
    __syncthreads();
    for (int st = 128; st > 0; st >>= 1) {
        if (threadIdx.x < st) { ss[threadIdx.x] += ss[threadIdx.x+st]; qs[threadIdx.x] += qs[threadIdx.x+st]; }
        __syncthreads();
    }
    if (threadIdx.x == 0) { g_bn1_sum[b*DIM + c] = ss[0]; g_bn1_sq[b*DIM + c] = qs[0]; }
}

// fused: BN1 finalize (threads 0-127) + b1 bias fold (all 512 threads)
__global__ __launch_bounds__(512) void k_bn1_fold(const float* __restrict__ g,
                                                  const float* __restrict__ be,
                                                  const float* __restrict__ w1,
                                                  const float* __restrict__ b1) {
    __shared__ float sh_shift[DIM];
    int tid = threadIdx.x;
    if (tid < DIM) {
        float s = 0.f, q = 0.f;
        #pragma unroll
        for (int b = 0; b < BATCH; b++) { s += g_bn1_sum[b*DIM + tid]; q += g_bn1_sq[b*DIM + tid]; }
        float mean = s * (1.0f/NP);
        float var  = q * (1.0f/NP) - mean*mean;
        float rstd = rsqrtf(var + 1e-5f);
        float sc = g[tid] * rstd;
        float sh = be[tid] - mean * sc;
        g_scale1[tid] = sc;
        g_shift1[tid] = sh;
        sh_shift[tid] = sh;
    }
    __syncthreads();
    float bf = b1[tid];
    for (int k = 0; k < DIM; k++)
        bf += sh_shift[k] * w1[k*HID + tid];
    g_b1f[tid] = bf;
}

// ======================= tf32 mma.sync GEMMs (R8 form) =======================
__global__ __launch_bounds__(256) void k_gemm1(const float* __restrict__ w1) {
    extern __shared__ uint32_t sm4[];
    uint32_t* As = sm4;
    uint32_t* Bs = sm4 + 32*KSTR;
    float* ts = (float*)sm4;
    int tid = threadIdx.x;
    int lane = tid & 31, wid = tid >> 5;
    int g = lane >> 2, t = lane & 3;
    int warp_m = wid >> 2, warp_n = wid & 3;
    int p0 = blockIdx.y * 128, n0 = blockIdx.x * 128;
    int cb = (p0 >> 14) * DIM;
    int hw0 = p0 & (HW-1);

    int ka = tid >> 5, p4 = (tid & 31) << 2;
    float acc[4][4][4] = {};
    {
        #pragma unroll
        for (int l = 0; l < 4; l++) {
            int k = ka + l*8;
            float sc = g_scale1[k];
            float4 v = *(const float4*)(g_y + (size_t)(cb + k)*HW + hw0 + p4);
            uint32_t* d = As + k*KSTR + p4;
            d[0] = f2tf32(v.x*sc); d[1] = f2tf32(v.y*sc); d[2] = f2tf32(v.z*sc); d[3] = f2tf32(v.w*sc);
        }
        #pragma unroll
        for (int l = 0; l < 4; l++) {
            int k = ka + l*8;
            float4 v = *(const float4*)(w1 + (size_t)k*HID + n0 + p4);
            uint32_t* d = Bs + k*KSTR + p4;
            d[0] = f2tf32(v.x); d[1] = f2tf32(v.y); d[2] = f2tf32(v.z); d[3] = f2tf32(v.w);
        }
    }
    __syncthreads();
    for (int kc = 0; kc < 4; kc++) {
        float4 pa[4];
        if (kc < 3) {
            int kt = (kc+1)*32;
            #pragma unroll
            for (int l = 0; l < 4; l++)
                pa[l] = *(const float4*)(g_y + (size_t)(cb + kt + ka + l*8)*HW + hw0 + p4);
        }
        #pragma unroll
        for (int ks = 0; ks < 4; ks++) {
            uint32_t a[4][4], b[4][2];
            #pragma unroll
            for (int mi = 0; mi < 4; mi++) {
                int row = warp_m*64 + mi*16 + g;
                a[mi][0] = As[(ks*8 + t    )*KSTR + row];
                a[mi][1] = As[(ks*8 + t    )*KSTR + row + 8];
                a[mi][2] = As[(ks*8 + t + 4)*KSTR + row];
                a[mi][3] = As[(ks*8 + t + 4)*KSTR + row + 8];
            }
            #pragma unroll
            for (int nt = 0; nt < 4; nt++) {
                int col = warp_n*32 + nt*8 + g;
                b[nt][0] = Bs[(ks*8 + t    )*KSTR + col];
                b[nt][1] = Bs[(ks*8 + t + 4)*KSTR + col];
            }
            #pragma unroll
            for (int mi = 0; mi < 4; mi++)
                #pragma unroll
                for (int nt = 0; nt < 4; nt++)
                    mma_tf32(acc[mi][nt], a[mi], b[nt]);
        }
        __syncthreads();
        if (kc < 3) {
            int kt = (kc+1)*32;
            #pragma unroll
            for (int l = 0; l < 4; l++) {
                float sc = g_scale1[kt + ka + l*8];
                uint32_t* d = As + (ka + l*8)*KSTR + p4;
                d[0] = f2tf32(pa[l].x*sc); d[1] = f2tf32(pa[l].y*sc);
                d[2] = f2tf32(pa[l].z*sc); d[3] = f2tf32(pa[l].w*sc);
            }
            #pragma unroll
            for (int l = 0; l < 4; l++) {
                int k = ka + l*8;
                float4 v = *(const float4*)(w1 + (size_t)(kt + k)*HID + n0 + p4);
                uint32_t* d = Bs + k*KSTR + p4;
                d[0] = f2tf32(v.x); d[1] = f2tf32(v.y); d[2] = f2tf32(v.z); d[3] = f2tf32(v.w);
            }
            __syncthreads();
        }
    }
    #pragma unroll
    for (int mi = 0; mi < 4; mi++) {
        int row = warp_m*64 + mi*16 + g;
        #pragma unroll
        for (int nt = 0; nt < 4; nt++) {
            int col = warp_n*32 + nt*8 + 2*t;
            float b0v = g_b1f[n0 + col], b1v = g_b1f[n0 + col + 1];
            ts[row*TSTR + col]       = gelu_exact(acc[mi][nt][0] + b0v);
            ts[row*TSTR + col + 1]   = gelu_exact(acc[mi][nt][1] + b1v);
            ts[(row+8)*TSTR + col]   = gelu_exact(acc[mi][nt][2] + b0v);
            ts[(row+8)*TSTR + col+1] = gelu_exact(acc[mi][nt][3] + b1v);
        }
    }
    __syncthreads();
    #pragma unroll
    for (int l = 0; l < 64; l++) {
        int i = tid + l*256;
        int n = i >> 7, p = i & 127;
        g_t[(size_t)(n0 + n)*NP + p0 + p] = ts[p*TSTR + n];
    }
}

// GEMM2 + fused BN2 partials
__global__ __launch_bounds__(256) void k_gemm2(const float* __restrict__ w2,
                                               const float* __restrict__ b2) {
    extern __shared__ uint32_t sm4[];
    uint32_t* As = sm4;
    uint32_t* Bs = sm4 + 32*KSTR;
    float* ts = (float*)sm4;
    __shared__ float rs[256], rq[256];
    int tid = threadIdx.x;
    int lane = tid & 31, wid = tid >> 5;
    int g = lane >> 2, t = lane & 3;
    int warp_m = wid >> 2, warp_n = wid & 3;
    int p0 = blockIdx.x * 128;

    int ka = tid >> 5, p4 = (tid & 31) << 2;
    float acc[4][4][4] = {};
    {
        #pragma unroll
        for (int l = 0; l < 4; l++) {
            int k = ka + l*8;
            float4 v = *(const float4*)(g_t + (size_t)k*NP + p0 + p4);
            uint32_t* d = As + k*KSTR + p4;
            d[0] = f2tf32(v.x); d[1] = f2tf32(v.y); d[2] = f2tf32(v.z); d[3] = f2tf32(v.w);
        }
        #pragma unroll
        for (int l = 0; l < 4; l++) {
            int k = ka + l*8;
            float4 v = *(const float4*)(w2 + (size_t)k*DIM + p4);
            uint32_t* d = Bs + k*KSTR + p4;
            d[0] = f2tf32(v.x); d[1] = f2tf32(v.y); d[2] = f2tf32(v.z); d[3] = f2tf32(v.w);
        }
    }
    __syncthreads();
    for (int kc = 0; kc < 16; kc++) {
        float4 pa[4];
        if (kc < 15) {
            int kt = (kc+1)*32;
            #pragma unroll
            for (int l = 0; l < 4; l++)
                pa[l] = *(const float4*)(g_t + (size_t)(kt + ka + l*8)*NP + p0 + p4);
        }
        #pragma unroll
        for (int ks = 0; ks < 4; ks++) {
            uint32_t a[4][4], b[4][2];
            #pragma unroll
            for (int mi = 0; mi < 4; mi++) {
                int row = warp_m*64 + mi*16 + g;
                a[mi][0] = As[(ks*8 + t    )*KSTR + row];
                a[mi][1] = As[(ks*8 + t    )*KSTR + row + 8];
                a[mi][2] = As[(ks*8 + t + 4)*KSTR + row];
                a[mi][3] = As[(ks*8 + t + 4)*KSTR + row + 8];
            }
            #pragma unroll
            for (int nt = 0; nt < 4; nt++) {
                int col = warp_n*32 + nt*8 + g;
                b[nt][0] = Bs[(ks*8 + t    )*KSTR + col];
                b[nt][1] = Bs[(ks*8 + t + 4)*KSTR + col];
            }
            #pragma unroll
            for (int mi = 0; mi < 4; mi++)
                #pragma unroll
                for (int nt = 0; nt < 4; nt++)
                    mma_tf32(acc[mi][nt], a[mi], b[nt]);
        }
        __syncthreads();
        if (kc < 15) {
            int kt = (kc+1)*32;
            #pragma unroll
            for (int l = 0; l < 4; l++) {
                uint32_t* d = As + (ka + l*8)*KSTR + p4;
                d[0] = f2tf32(pa[l].x); d[1] = f2tf32(pa[l].y);
                d[2] = f2tf32(pa[l].z); d[3] = f2tf32(pa[l].w);
            }
            #pragma unroll
            for (int l = 0; l < 4; l++) {
                int k = ka + l*8;
                float4 v = *(const float4*)(w2 + (size_t)(kt + k)*DIM + p4);
                uint32_t* d = Bs + k*KSTR + p4;
                d[0] = f2tf32(v.x); d[1] = f2tf32(v.y); d[2] = f2tf32(v.z); d[3] = f2tf32(v.w);
            }
            __syncthreads();
        }
    }
    #pragma unroll
    for (int mi = 0; mi < 4; mi++) {
        int row = warp_m*64 + mi*16 + g;
        #pragma unroll
        for (int nt = 0; nt < 4; nt++) {
            int col = warp_n*32 + nt*8 + 2*t;
            float b0v = b2[col], b1v = b2[col + 1];
            ts[row*TSTR + col]       = acc[mi][nt][0] + b0v;
            ts[row*TSTR + col + 1]   = acc[mi][nt][1] + b1v;
            ts[(row+8)*TSTR + col]   = acc[mi][nt][2] + b0v;
            ts[(row+8)*TSTR + col+1] = acc[mi][nt][3] + b1v;
        }
    }
    __syncthreads();
    #pragma unroll
    for (int l = 0; l < 64; l++) {
        int i = tid + l*256;
        int n = i >> 7, p = i & 127;
        g_c2[(size_t)n*NP + p0 + p] = ts[p*TSTR + n];
    }
    {
        int n = tid & 127;
        int ph = tid >> 7;
        float s = 0.f, q = 0.f;
        for (int p = ph; p < 128; p += 2) {
            float v = ts[p*TSTR + n];
            s += v; q += v*v;
        }
        rs[tid] = s; rq[tid] = q;
        __syncthreads();
        if (tid < 128) {
            g_bn2_sum[blockIdx.x*128 + tid] = rs[tid] + rs[tid+128];
            g_bn2_sq [blockIdx.x*128 + tid] = rq[tid] + rq[tid+128];
        }
    }
}

// ======================= BN2 final + output =======================
__global__ void k_bn2_final(const float* __restrict__ g, const float* __restrict__ be) {
    int c = blockIdx.x;
    int tid = threadIdx.x;
    __shared__ float ss[128], qs[128];
    float s = 0.f, q = 0.f;
    for (int i = tid; i < 512; i += 128) {
        s += g_bn2_sum[i*128 + c];
        q += g_bn2_sq [i*128 + c];
    }
    ss[tid] = s; qs[tid] = q;
    __syncthreads();
    for (int st = 64; st > 0; st >>= 1) {
        if (tid < st) { ss[tid] += ss[tid+st]; qs[tid] += qs[tid+st]; }
        __syncthreads();
    }
    if (tid == 0) {
        float mean = ss[0] * (1.0f/NP);
        float var  = qs[0] * (1.0f/NP) - mean*mean;
        float rstd = rsqrtf(var + 1e-5f);
        float sc = g[c] * rstd;
        g_scale2[c] = sc;
        g_shift2[c] = be[c] - mean * sc;
    }
}
// vectorized final: 4 px/thread.  grid NP*DIM/1024
__global__ __launch_bounds__(256) void k_final_v2(const float* __restrict__ x, float* __restrict__ out) {
    int i4 = blockIdx.x * 256 + threadIdx.x;   // float4 index
    int i = i4 << 2;
    int b = i >> 21;
    int c = (i >> 14) & 127;
    int hw = i & 16383;
    float sc = g_scale2[c], sh = g_shift2[c];
    float4 v = *(const float4*)(g_c2 + (size_t)c*NP + (b<<14) + hw);
    float4 xv = *(const float4*)(x + i);
    float4 o;
    o.x = gelu_exact(xv.x + v.x*sc + sh);
    o.y = gelu_exact(xv.y + v.y*sc + sh);
    o.z = gelu_exact(xv.z + v.z*sc + sh);
    o.w = gelu_exact(xv.w + v.w*sc + sh);
    *(float4*)(out + i) = o;
}

// ================================ launch ================================
extern "C" void kernel_launch(void* const* d_in, const int* in_sizes, int n_in,
                              void* d_out, int out_size) {
    const float* x        = (const float*)d_in[0];
    const float* offset_w = (const float*)d_in[1];
    const float* offset_b = (const float*)d_in[2];
    const float* deform_w = (const float*)d_in[3];
    const float* dw_w     = (const float*)d_in[4];
    const float* dw_b     = (const float*)d_in[5];
    const float* dw2_w    = (const float*)d_in[6];
    const float* dw2_b    = (const float*)d_in[7];
    const float* bn1_g    = (const float*)d_in[8];
    const float* bn1_b    = (const float*)d_in[9];
    const float* w1       = (const float*)d_in[10];
    const float* b1       = (const float*)d_in[11];
    const float* w2       = (const float*)d_in[12];
    const float* b2       = (const float*)d_in[13];
    const float* bn2_g    = (const float*)d_in[14];
    const float* bn2_b    = (const float*)d_in[15];
    float* out = (float*)d_out;

    static int inited = 0;
    static cudaStream_t sA, sB, sC;
    static cudaEvent_t e0, eA, eB, eC, eBC;
    if (!inited) {
        cudaFuncSetAttribute(k_gemm1, cudaFuncAttributeMaxDynamicSharedMemorySize, GSMEM);
        cudaFuncSetAttribute(k_gemm2, cudaFuncAttributeMaxDynamicSharedMemorySize, GSMEM);
        cudaFuncSetAttribute(k_conv_mma<18,1,0,0>, cudaFuncAttributeMaxDynamicSharedMemorySize, CONV_SMEM);
        cudaFuncSetAttribute(k_conv_mma<32,2,96,1>, cudaFuncAttributeMaxDynamicSharedMemorySize, CONV_SMEM);
        cudaStreamCreateWithFlags(&sA, cudaStreamNonBlocking);
        cudaStreamCreateWithFlags(&sB, cudaStreamNonBlocking);
        cudaStreamCreateWithFlags(&sC, cudaStreamNonBlocking);
        cudaEventCreateWithFlags(&e0, cudaEventDisableTiming);
        cudaEventCreateWithFlags(&eA, cudaEventDisableTiming);
        cudaEventCreateWithFlags(&eB, cudaEventDisableTiming);
        cudaEventCreateWithFlags(&eC, cudaEventDisableTiming);
        cudaEventCreateWithFlags(&eBC, cudaEventDisableTiming);
        inited = 1;
    }

    float* goffp; cudaGetSymbolAddress((void**)&goffp, g_off);
    float* gyp;   cudaGetSymbolAddress((void**)&gyp, g_y);

    dim3 blk256(256);
    cudaEventRecord(e0, 0);
    // branch A: offset conv -> deform (even channels 0..62)
    cudaStreamWaitEvent(sA, e0, 0);
    k_conv_mma<18,1,0,0> <<<dim3(128, BATCH), blk256, CONV_SMEM, sA>>>(x, offset_w, offset_b, goffp);
    k_deform_v3          <<<dim3(64, 4, BATCH), blk256, 0, sA>>>(x, deform_w);
    // branch B: dilated conv (odd channels 65..127)
    cudaStreamWaitEvent(sB, e0, 0);
    k_conv_mma<32,2,96,1><<<dim3(128, BATCH), blk256, CONV_SMEM, sB>>>(x, dw2_w, dw2_b, gyp);
    cudaEventRecord(eB, sB);
    // branch C: dw7 (odd 1..63 + even 64..126)
    cudaStreamWaitEvent(sC, e0, 0);
    k_dw7_v3             <<<dim3(16, GC2, BATCH), blk256, 0, sC>>>(x, dw_w, dw_b);
    cudaEventRecord(eC, sC);

    // bn1 over dw7+dil3 channels: runs on sB once both B and C done (overlaps deform)
    cudaStreamWaitEvent(sB, eC, 0);
    k_bn1_part<1><<<BATCH*96, blk256, 0, sB>>>();
    cudaEventRecord(eBC, sB);
    // bn1 over deform channels: on sA right after deform
    k_bn1_part<0><<<BATCH*32, blk256, 0, sA>>>();
    cudaEventRecord(eA, sA);

    // join
    cudaStreamWaitEvent(0, eA, 0);
    cudaStreamWaitEvent(0, eBC, 0);
    cudaStreamWaitEvent(0, eB, 0);

    k_bn1_fold<<<1, 512>>>(bn1_g, bn1_b, w1, b1);

    k_gemm1<<<dim3(HID/128, NP/128), 256, GSMEM>>>(w1);
    k_gemm2<<<NP/128, 256, GSMEM>>>(w2, b2);

    k_bn2_final<<<DIM, 128>>>(bn2_g, bn2_b);
    k_final_v2<<<(size_t)NP*DIM/1024, blk256>>>(x, out);
}

// round 12
// speedup vs baseline: 1.6131x; 1.0987x over previous
#include <cuda_runtime.h>
#include <cuda_bf16.h>
#include <cuda_fp16.h>
#include <math.h>
#include <stdint.h>

#define BATCH 4
#define DIM 128
#define HH 128
#define WW 128
#define HW (HH*WW)           // 16384
#define NP (BATCH*HW)        // 65536
#define HID 512
#define GC1 32
#define GC2 64
#define GC3 32

// ---------------- scratch ----------------
__device__ float g_off[BATCH*18*HW];
__device__ float g_y[BATCH*DIM*HW];            // shuffled concat, NCHW
__device__ uint32_t g_t2[(size_t)(HID/2)*NP];  // GEMM1 out, half2 packed by n-pairs, [HID/2][NP]
__device__ float g_c2[(size_t)DIM*NP];         // GEMM2 out, TRANSPOSED [DIM][NP]
__device__ float g_b1f[HID];
__device__ float g_bn1_sum[BATCH*DIM];
__device__ float g_bn1_sq [BATCH*DIM];
__device__ float g_scale1[DIM], g_shift1[DIM];
__device__ float g_bn2_sum[512*DIM];
__device__ float g_bn2_sq [512*DIM];
__device__ float g_scale2[DIM], g_shift2[DIM];

__device__ __forceinline__ float gelu_exact(float v) {
    return 0.5f * v * (1.0f + erff(v * 0.70710678118654752440f));
}
__device__ __forceinline__ uint32_t f2tf32(float f) {
    uint32_t r;
    asm("cvt.rna.tf32.f32 %0, %1;" : "=r"(r) : "f"(f));
    return r;
}
__device__ __forceinline__ void mma_tf32(float* c, const uint32_t* a, const uint32_t* b) {
    asm volatile("mma.sync.aligned.m16n8k8.row.col.f32.tf32.tf32.f32 "
        "{%0,%1,%2,%3}, {%4,%5,%6,%7}, {%8,%9}, {%0,%1,%2,%3};"
        : "+f"(c[0]), "+f"(c[1]), "+f"(c[2]), "+f"(c[3])
        : "r"(a[0]), "r"(a[1]), "r"(a[2]), "r"(a[3]), "r"(b[0]), "r"(b[1]));
}
__device__ __forceinline__ void mma_f16(float* c, const uint32_t* a, const uint32_t* b) {
    asm volatile("mma.sync.aligned.m16n8k16.row.col.f32.f16.f16.f32 "
        "{%0,%1,%2,%3}, {%4,%5,%6,%7}, {%8,%9}, {%0,%1,%2,%3};"
        : "+f"(c[0]), "+f"(c[1]), "+f"(c[2]), "+f"(c[3])
        : "r"(a[0]), "r"(a[1]), "r"(a[2]), "r"(a[3]), "r"(b[0]), "r"(b[1]));
}
__device__ __forceinline__ uint32_t pack_h2(float lo, float hi) {
    __half2 h = __floats2half2_rn(lo, hi);
    return *reinterpret_cast<uint32_t*>(&h);
}

#define TSTR 130   // epilogue transpose stride
#define GSMEM (128*TSTR*4)   // 66560 bytes (ts dominates; fp16 tiles overlay)
#define AS2 68     // gemm1 full-A stride (u32 half2 units): banks (4*row + c) all distinct
#define BS2 20     // B / gemm2-A chunk stride (u32): banks (20*row + c) distinct

// ======================= implicit-GEMM tensor conv =======================
#define ASTR 136
#define BSTR 40
#define CONV_SMEM ((96*ASTR + 288*BSTR)*4)   // 98304 bytes

template<int NOC, int D, int CBASE, int MODE>
__global__ __launch_bounds__(256) void k_conv_mma(const float* __restrict__ x,
                                                  const float* __restrict__ w,
                                                  const float* __restrict__ bias,
                                                  float* __restrict__ outp) {
    extern __shared__ uint32_t cs[];
    uint32_t* As = cs;               // [96][ASTR]
    uint32_t* Bs = cs + 96*ASTR;     // [288][BSTR]
    int tid = threadIdx.x;
    int lane = tid & 31, wid = tid >> 5;
    int g = lane >> 2, t = lane & 3;
    int warp_m = wid >> 1, warp_n = wid & 1;
    int y = blockIdx.x, b = blockIdx.y;

    for (int i = tid; i < 96*ASTR; i += 256) {
        int r = i / ASTR, c = i - r*ASTR;
        int ky = r >> 5, ic = r & 31;
        int ry = y + (ky - 1)*D;
        int gx = c - D;
        float v = 0.f;
        if (ry >= 0 && ry < 128 && gx >= 0 && gx < 128)
            v = x[(((size_t)b*DIM + CBASE + ic) << 14) + (ry << 7) + gx];
        As[i] = f2tf32(v);
    }
    for (int i = tid; i < 288*32; i += 256) {
        int k = i >> 5, oc = i & 31;
        int tap = k >> 5, ic = k & 31;
        float v = (oc < NOC) ? w[(oc*32 + ic)*9 + tap] : 0.f;
        Bs[k*BSTR + oc] = f2tf32(v);
    }
    __syncthreads();

    float acc[2][2][4] = {};
    int mbase = warp_m*32 + g;
    int nbase = warp_n*16 + g;
    #pragma unroll
    for (int tap = 0; tap < 9; tap++) {
        const int ky = tap / 3, kx = tap % 3;
        #pragma unroll
        for (int k8 = 0; k8 < 4; k8++) {
            int ar = ky*32 + k8*8 + t;
            int bk = tap*32 + k8*8 + t;
            uint32_t a[2][4], bb[2][2];
            #pragma unroll
            for (int mi = 0; mi < 2; mi++) {
                int col = mbase + mi*16 + kx*D;
                a[mi][0] = As[ar*ASTR + col];
                a[mi][1] = As[ar*ASTR + col + 8];
                a[mi][2] = As[(ar + 4)*ASTR + col];
                a[mi][3] = As[(ar + 4)*ASTR + col + 8];
            }
            #pragma unroll
            for (int nt = 0; nt < 2; nt++) {
                bb[nt][0] = Bs[bk*BSTR + nbase + nt*8];
                bb[nt][1] = Bs[(bk + 4)*BSTR + nbase + nt*8];
            }
            #pragma unroll
            for (int mi = 0; mi < 2; mi++)
                #pragma unroll
                for (int nt = 0; nt < 2; nt++)
                    mma_tf32(acc[mi][nt], a[mi], bb[nt]);
        }
    }
    #pragma unroll
    for (int mi = 0; mi < 2; mi++) {
        #pragma unroll
        for (int nt = 0; nt < 2; nt++) {
            int col = warp_n*16 + nt*8 + 2*t;
            #pragma unroll
            for (int cc = 0; cc < 2; cc++) {
                int oc = col + cc;
                if (oc >= NOC) continue;
                float bv = bias[oc];
                int px0 = warp_m*32 + mi*16 + g;
                size_t base;
                if (MODE == 0) base = (((size_t)b*18 + oc) << 14) + (y << 7);
                else           base = (((size_t)b*DIM + 65 + 2*oc) << 14) + (y << 7);
                outp[base + px0]     = acc[mi][nt][cc]     + bv;
                outp[base + px0 + 8] = acc[mi][nt][cc + 2] + bv;
            }
        }
    }
}

// ======================= other conv kernels =======================

// depthwise 7x7 v3.  grid (16, 64, 4)
#define DSTR 39
__global__ __launch_bounds__(256) void k_dw7_v3(const float* __restrict__ x,
                                                const float* __restrict__ dww,
                                                const float* __restrict__ dwb) {
    __shared__ float s[38*DSTR];
    __shared__ float w[49];
    int tid = threadIdx.x;
    int b = blockIdx.z;
    int c = blockIdx.y;
    int ty0 = (blockIdx.x >> 2) * 32, tx0 = (blockIdx.x & 3) * 32;
    const float* xp = x + ((size_t)b*DIM + 32 + c)*HW;
    #pragma unroll 6
    for (int i = tid; i < 38*38; i += 256) {
        int sy = i / 38, sx = i - sy*38;
        int gy = ty0 + sy - 3, gx = tx0 + sx - 3;
        float v = 0.f;
        if (gy >= 0 && gy < 128 && gx >= 0 && gx < 128) v = xp[gy*WW + gx];
        s[sy*DSTR + sx] = v;
    }
    if (tid < 49) w[tid] = dww[c*49 + tid];
    __syncthreads();
    int txg = (tid & 7) * 4, ty = tid >> 3;
    float a0 = 0.f, a1 = 0.f, a2 = 0.f, a3 = 0.f;
    #pragma unroll
    for (int ky = 0; ky < 7; ky++) {
        const float* sp = s + (ty + ky)*DSTR + txg;
        float r[10];
        #pragma unroll
        for (int j = 0; j < 10; j++) r[j] = sp[j];
        #pragma unroll
        for (int kx = 0; kx < 7; kx++) {
            float wv = w[ky*7 + kx];
            a0 += r[kx]*wv; a1 += r[kx+1]*wv; a2 += r[kx+2]*wv; a3 += r[kx+3]*wv;
        }
    }
    float bias = dwb[c];
    int oldc = 32 + c;
    int newc = (oldc < 64) ? (2*oldc) : (2*(oldc-64)+1);
    float4 o; o.x = a0+bias; o.y = a1+bias; o.z = a2+bias; o.w = a3+bias;
    *(float4*)(g_y + ((size_t)b*DIM + newc)*HW + (ty0+ty)*WW + tx0+txg) = o;
}

// deformable depthwise v3.  grid (64, 4, 4)
__global__ __launch_bounds__(256) void k_deform_v3(const float* __restrict__ x,
                                                   const float* __restrict__ dfw) {
    __shared__ float wk[8][9];
    int tid = threadIdx.x;
    int b = blockIdx.z;
    int c0 = blockIdx.y * 8;
    int hw = blockIdx.x * 256 + tid;
    if (tid < 72) wk[tid/9][tid%9] = dfw[(c0 + tid/9)*9 + tid%9];
    __syncthreads();
    int h = hw >> 7, wc = hw & 127;
    const float* offb = g_off + (size_t)b*18*HW + hw;
    const float* xb = x + (((size_t)b*DIM + c0) << 14);
    float acc[8] = {};
    #pragma unroll
    for (int k = 0; k < 9; k++) {
        float dy = offb[(2*k  )*HW];
        float dx = offb[(2*k+1)*HW];
        float ys = (float)h - 1.0f + (float)(k/3) + dy;
        float xs = (float)wc - 1.0f + (float)(k%3) + dx;
        float y0 = floorf(ys), x0 = floorf(xs);
        float fy = ys - y0, fx = xs - x0;
        float vy0 = (y0 >= 0.f && y0 <= 127.f) ? 1.f : 0.f;
        float vy1 = (y0 >= -1.f && y0 <= 126.f) ? 1.f : 0.f;
        float vx0 = (x0 >= 0.f && x0 <= 127.f) ? 1.f : 0.f;
        float vx1 = (x0 >= -1.f && x0 <= 126.f) ? 1.f : 0.f;
        float w00 = (1.f-fy)*(1.f-fx) * vy0*vx0;
        float w01 = (1.f-fy)*fx       * vy0*vx1;
        float w10 = fy*(1.f-fx)       * vy1*vx0;
        float w11 = fy*fx             * vy1*vx1;
        int yi0 = min(max((int)y0, 0), 127);
        int yi1 = min(max((int)y0 + 1, 0), 127);
        int xi0 = min(max((int)x0, 0), 127);
        int xi1 = min(max((int)x0 + 1, 0), 127);
        int i00 = yi0*128 + xi0;
        int i01 = yi0*128 + xi1;
        int i10 = yi1*128 + xi0;
        int i11 = yi1*128 + xi1;
        #pragma unroll
        for (int cl = 0; cl < 8; cl++) {
            const float* xp = xb + (cl << 14);
            float sv = w00*xp[i00] + w01*xp[i01] + w10*xp[i10] + w11*xp[i11];
            acc[cl] += sv * wk[cl][k];
        }
    }
    #pragma unroll
    for (int cl = 0; cl < 8; cl++)
        g_y[(((size_t)b*DIM + 2*(c0+cl)) << 14) + hw] = acc[cl];
}

// ======================= BN1 (split by producer) =======================
template<int MODE>
__global__ __launch_bounds__(256) void k_bn1_part(void) {
    int nch = (MODE == 0) ? 32 : 96;
    int b = blockIdx.x / nch;
    int j = blockIdx.x % nch;
    int c;
    if (MODE == 0) c = 2*j;
    else           c = (j < 64) ? (2*j + 1) : (64 + 2*(j - 64));
    const float4* p = (const float4*)(g_y + (((size_t)b*DIM + c) << 14));
    float s = 0.f, q = 0.f;
    for (int i = threadIdx.x; i < HW/4; i += 256) {
        float4 v = p[i];
        s += v.x + v.y + v.z + v.w;
        q += v.x*v.x + v.y*v.y + v.z*v.z + v.w*v.w;
    }
    __shared__ float ss[256], qs[256];
    ss[threadIdx.x] = s; qs[threadIdx.x] = q;
    __syncthreads();
    for (int st = 128; st > 0; st >>= 1) {
        if (threadIdx.x < st) { ss[threadIdx.x] += ss[threadIdx.x+st]; qs[threadIdx.x] += qs[threadIdx.x+st]; }
        __syncthreads();
    }
    if (threadIdx.x == 0) { g_bn1_sum[b*DIM + c] = ss[0]; g_bn1_sq[b*DIM + c] = qs[0]; }
}

__global__ __launch_bounds__(512) void k_bn1_fold(const float* __restrict__ g,
                                                  const float* __restrict__ be,
                                                  const float* __restrict__ w1,
                                                  const float* __restrict__ b1) {
    __shared__ float sh_shift[DIM];
    int tid = threadIdx.x;
    if (tid < DIM) {
        float s = 0.f, q = 0.f;
        #pragma unroll
        for (int b = 0; b < BATCH; b++) { s += g_bn1_sum[b*DIM + tid]; q += g_bn1_sq[b*DIM + tid]; }
        float mean = s * (1.0f/NP);
        float var  = q * (1.0f/NP) - mean*mean;
        float rstd = rsqrtf(var + 1e-5f);
        float sc = g[tid] * rstd;
        float sh = be[tid] - mean * sc;
        g_scale1[tid] = sc;
        g_shift1[tid] = sh;
        sh_shift[tid] = sh;
    }
    __syncthreads();
    float bf = b1[tid];
    for (int k = 0; k < DIM; k++)
        bf += sh_shift[k] * w1[k*HID + tid];
    g_b1f[tid] = bf;
}

// ======================= fp16 mma GEMMs =======================
// GEMM1: A full-resident [128 px][64 k2] half2 (K=128), B per-chunk [128 n][16 k2].
__global__ __launch_bounds__(256) void k_gemm1(const float* __restrict__ w1) {
    extern __shared__ uint32_t sm4[];
    uint32_t* Af = sm4;                 // [128][AS2]
    uint32_t* Bc = sm4 + 128*AS2;       // [128][BS2]
    float* ts = (float*)sm4;
    int tid = threadIdx.x;
    int lane = tid & 31, wid = tid >> 5;
    int g = lane >> 2, t = lane & 3;
    int warp_m = wid >> 2, warp_n = wid & 3;
    int p0 = blockIdx.y * 128, n0 = blockIdx.x * 128;
    int cb = (p0 >> 14) * DIM;
    int hw0 = p0 & (HW-1);

    // fill full A (BN1 scale fused), half2 by k-pairs
    #pragma unroll
    for (int l = 0; l < 32; l++) {
        int i = tid + l*256;
        int px = i & 127, k2 = i >> 7;
        float v0 = g_y[(size_t)(cb + 2*k2    )*HW + hw0 + px] * g_scale1[2*k2];
        float v1 = g_y[(size_t)(cb + 2*k2 + 1)*HW + hw0 + px] * g_scale1[2*k2 + 1];
        Af[px*AS2 + k2] = pack_h2(v0, v1);
    }
    // fill B chunk 0
    #pragma unroll
    for (int l = 0; l < 8; l++) {
        int i = tid + l*256;
        int n = i & 127, k2 = i >> 7;
        float v0 = w1[(size_t)(2*k2    )*HID + n0 + n];
        float v1 = w1[(size_t)(2*k2 + 1)*HID + n0 + n];
        Bc[n*BS2 + k2] = pack_h2(v0, v1);
    }
    __syncthreads();

    float acc[4][4][4] = {};
    for (int kc = 0; kc < 4; kc++) {
        #pragma unroll
        for (int kst = 0; kst < 2; kst++) {
            int k2A = kc*16 + kst*8;
            int k2B = kst*8;
            uint32_t a[4][4], b[4][2];
            #pragma unroll
            for (int mi = 0; mi < 4; mi++) {
                int row = warp_m*64 + mi*16 + g;
                a[mi][0] = Af[row*AS2 + k2A + t];
                a[mi][1] = Af[(row+8)*AS2 + k2A + t];
                a[mi][2] = Af[row*AS2 + k2A + t + 4];
                a[mi][3] = Af[(row+8)*AS2 + k2A + t + 4];
            }
            #pragma unroll
            for (int nf = 0; nf < 4; nf++) {
                int col = warp_n*32 + nf*8 + g;
                b[nf][0] = Bc[col*BS2 + k2B + t];
                b[nf][1] = Bc[col*BS2 + k2B + t + 4];
            }
            #pragma unroll
            for (int mi = 0; mi < 4; mi++)
                #pragma unroll
                for (int nf = 0; nf < 4; nf++)
                    mma_f16(acc[mi][nf], a[mi], b[nf]);
        }
        __syncthreads();
        if (kc < 3) {
            int kt = (kc+1)*32;
            #pragma unroll
            for (int l = 0; l < 8; l++) {
                int i = tid + l*256;
                int n = i & 127, k2 = i >> 7;
                float v0 = w1[(size_t)(kt + 2*k2    )*HID + n0 + n];
                float v1 = w1[(size_t)(kt + 2*k2 + 1)*HID + n0 + n];
                Bc[n*BS2 + k2] = pack_h2(v0, v1);
            }
            __syncthreads();
        }
    }
    // epilogue: bias + gelu -> ts (float), then half2-packed transposed store
    #pragma unroll
    for (int mi = 0; mi < 4; mi++) {
        int row = warp_m*64 + mi*16 + g;
        #pragma unroll
        for (int nf = 0; nf < 4; nf++) {
            int col = warp_n*32 + nf*8 + 2*t;
            float b0v = g_b1f[n0 + col], b1v = g_b1f[n0 + col + 1];
            ts[row*TSTR + col]       = gelu_exact(acc[mi][nf][0] + b0v);
            ts[row*TSTR + col + 1]   = gelu_exact(acc[mi][nf][1] + b1v);
            ts[(row+8)*TSTR + col]   = gelu_exact(acc[mi][nf][2] + b0v);
            ts[(row+8)*TSTR + col+1] = gelu_exact(acc[mi][nf][3] + b1v);
        }
    }
    __syncthreads();
    #pragma unroll
    for (int l = 0; l < 32; l++) {
        int i = tid + l*256;
        int n2 = i >> 7, p = i & 127;
        uint32_t h = pack_h2(ts[p*TSTR + 2*n2], ts[p*TSTR + 2*n2 + 1]);
        g_t2[(size_t)((n0 >> 1) + n2)*NP + p0 + p] = h;
    }
}

// GEMM2 + fused BN2 partials.  A from g_t2 (pre-packed u32), chunked K with A-prefetch.
__global__ __launch_bounds__(256) void k_gemm2(const float* __restrict__ w2,
                                               const float* __restrict__ b2) {
    extern __shared__ uint32_t sm4[];
    uint32_t* Ac = sm4;                 // [128 px][BS2=20] (16 k2 per chunk)
    uint32_t* Bc = sm4 + 128*BS2;       // [128 n][BS2]
    float* ts = (float*)sm4;
    __shared__ float rs[256], rq[256];
    int tid = threadIdx.x;
    int lane = tid & 31, wid = tid >> 5;
    int g = lane >> 2, t = lane & 3;
    int warp_m = wid >> 2, warp_n = wid & 3;
    int p0 = blockIdx.x * 128;

    int pxa = tid & 127, k2a = tid >> 7;   // each thread: 8 (px,k2) slots, k2 = k2a + 2*l

    // initial fills
    #pragma unroll
    for (int l = 0; l < 8; l++) {
        int i = tid + l*256;
        int px = i & 127, k2 = i >> 7;
        Ac[px*BS2 + k2] = g_t2[(size_t)k2*NP + p0 + px];
    }
    #pragma unroll
    for (int l = 0; l < 8; l++) {
        int i = tid + l*256;
        int n = i & 127, k2 = i >> 7;
        float v0 = w2[(size_t)(2*k2    )*DIM + n];
        float v1 = w2[(size_t)(2*k2 + 1)*DIM + n];
        Bc[n*BS2 + k2] = pack_h2(v0, v1);
    }
    __syncthreads();

    float acc[4][4][4] = {};
    for (int kc = 0; kc < 16; kc++) {
        uint32_t pa[8];
        if (kc < 15) {
            int kt2 = (kc+1)*16;
            #pragma unroll
            for (int l = 0; l < 8; l++) {
                int i = tid + l*256;
                int px = i & 127, k2 = i >> 7;
                pa[l] = g_t2[(size_t)(kt2 + k2)*NP + p0 + px];
            }
        }
        #pragma unroll
        for (int kst = 0; kst < 2; kst++) {
            int k2b = kst*8;
            uint32_t a[4][4], b[4][2];
            #pragma unroll
            for (int mi = 0; mi < 4; mi++) {
                int row = warp_m*64 + mi*16 + g;
                a[mi][0] = Ac[row*BS2 + k2b + t];
                a[mi][1] = Ac[(row+8)*BS2 + k2b + t];
                a[mi][2] = Ac[row*BS2 + k2b + t + 4];
                a[mi][3] = Ac[(row+8)*BS2 + k2b + t + 4];
            }
            #pragma unroll
            for (int nf = 0; nf < 4; nf++) {
                int col = warp_n*32 + nf*8 + g;
                b[nf][0] = Bc[col*BS2 + k2b + t];
                b[nf][1] = Bc[col*BS2 + k2b + t + 4];
            }
            #pragma unroll
            for (int mi = 0; mi < 4; mi++)
                #pragma unroll
                for (int nf = 0; nf < 4; nf++)
                    mma_f16(acc[mi][nf], a[mi], b[nf]);
        }
        __syncthreads();
        if (kc < 15) {
            int kt = (kc+1)*32;
            #pragma unroll
            for (int l = 0; l < 8; l++) {
                int i = tid + l*256;
                int px = i & 127, k2 = i >> 7;
                Ac[px*BS2 + k2] = pa[l];
            }
            #pragma unroll
            for (int l = 0; l < 8; l++) {
                int i = tid + l*256;
                int n = i & 127, k2 = i >> 7;
                float v0 = w2[(size_t)(kt + 2*k2    )*DIM + n];
                float v1 = w2[(size_t)(kt + 2*k2 + 1)*DIM + n];
                Bc[n*BS2 + k2] = pack_h2(v0, v1);
            }
            __syncthreads();
        }
    }
    (void)pxa; (void)k2a;
    // epilogue
    #pragma unroll
    for (int mi = 0; mi < 4; mi++) {
        int row = warp_m*64 + mi*16 + g;
        #pragma unroll
        for (int nf = 0; nf < 4; nf++) {
            int col = warp_n*32 + nf*8 + 2*t;
            float b0v = b2[col], b1v = b2[col + 1];
            ts[row*TSTR + col]       = acc[mi][nf][0] + b0v;
            ts[row*TSTR + col + 1]   = acc[mi][nf][1] + b1v;
            ts[(row+8)*TSTR + col]   = acc[mi][nf][2] + b0v;
            ts[(row+8)*TSTR + col+1] = acc[mi][nf][3] + b1v;
        }
    }
    __syncthreads();
    #pragma unroll
    for (int l = 0; l < 64; l++) {
        int i = tid + l*256;
        int n = i >> 7, p = i & 127;
        g_c2[(size_t)n*NP + p0 + p] = ts[p*TSTR + n];
    }
    {
        int n = tid & 127;
        int ph = tid >> 7;
        float s = 0.f, q = 0.f;
        for (int p = ph; p < 128; p += 2) {
            float v = ts[p*TSTR + n];
            s += v; q += v*v;
        }
        rs[tid] = s; rq[tid] = q;
        __syncthreads();
        if (tid < 128) {
            g_bn2_sum[blockIdx.x*128 + tid] = rs[tid] + rs[tid+128];
            g_bn2_sq [blockIdx.x*128 + tid] = rq[tid] + rq[tid+128];
        }
    }
}

// ======================= BN2 final + output =======================
__global__ void k_bn2_final(const float* __restrict__ g, const float* __restrict__ be) {
    int c = blockIdx.x;
    int tid = threadIdx.x;
    __shared__ float ss[128], qs[128];
    float s = 0.f, q = 0.f;
    for (int i = tid; i < 512; i += 128) {
        s += g_bn2_sum[i*128 + c];
        q += g_bn2_sq [i*128 + c];
    }
    ss[tid] = s; qs[tid] = q;
    __syncthreads();
    for (int st = 64; st > 0; st >>= 1) {
        if (tid < st) { ss[tid] += ss[tid+st]; qs[tid] += qs[tid+st]; }
        __syncthreads();
    }
    if (tid == 0) {
        float mean = ss[0] * (1.0f/NP);
        float var  = qs[0] * (1.0f/NP) - mean*mean;
        float rstd = rsqrtf(var + 1e-5f);
        float sc = g[c] * rstd;
        g_scale2[c] = sc;
        g_shift2[c] = be[c] - mean * sc;
    }
}
__global__ __launch_bounds__(256) void k_final_v2(const float* __restrict__ x, float* __restrict__ out) {
    int i4 = blockIdx.x * 256 + threadIdx.x;
    int i = i4 << 2;
    int b = i >> 21;
    int c = (i >> 14) & 127;
    int hw = i & 16383;
    float sc = g_scale2[c], sh = g_shift2[c];
    float4 v = *(const float4*)(g_c2 + (size_t)c*NP + (b<<14) + hw);
    float4 xv = *(const float4*)(x + i);
    float4 o;
    o.x = gelu_exact(xv.x + v.x*sc + sh);
    o.y = gelu_exact(xv.y + v.y*sc + sh);
    o.z = gelu_exact(xv.z + v.z*sc + sh);
    o.w = gelu_exact(xv.w + v.w*sc + sh);
    *(float4*)(out + i) = o;
}

// ================================ launch ================================
extern "C" void kernel_launch(void* const* d_in, const int* in_sizes, int n_in,
                              void* d_out, int out_size) {
    const float* x        = (const float*)d_in[0];
    const float* offset_w = (const float*)d_in[1];
    const float* offset_b = (const float*)d_in[2];
    const float* deform_w = (const float*)d_in[3];
    const float* dw_w     = (const float*)d_in[4];
    const float* dw_b     = (const float*)d_in[5];
    const float* dw2_w    = (const float*)d_in[6];
    const float* dw2_b    = (const float*)d_in[7];
    const float* bn1_g    = (const float*)d_in[8];
    const float* bn1_b    = (const float*)d_in[9];
    const float* w1       = (const float*)d_in[10];
    const float* b1       = (const float*)d_in[11];
    const float* w2       = (const float*)d_in[12];
    const float* b2       = (const float*)d_in[13];
    const float* bn2_g    = (const float*)d_in[14];
    const float* bn2_b    = (const float*)d_in[15];
    float* out = (float*)d_out;

    static int inited = 0;
    static cudaStream_t sA, sB, sC;
    static cudaEvent_t e0, eA, eB, eC, eBC;
    if (!inited) {
        cudaFuncSetAttribute(k_gemm1, cudaFuncAttributeMaxDynamicSharedMemorySize, GSMEM);
        cudaFuncSetAttribute(k_gemm2, cudaFuncAttributeMaxDynamicSharedMemorySize, GSMEM);
        cudaFuncSetAttribute(k_conv_mma<18,1,0,0>, cudaFuncAttributeMaxDynamicSharedMemorySize, CONV_SMEM);
        cudaFuncSetAttribute(k_conv_mma<32,2,96,1>, cudaFuncAttributeMaxDynamicSharedMemorySize, CONV_SMEM);
        cudaStreamCreateWithFlags(&sA, cudaStreamNonBlocking);
        cudaStreamCreateWithFlags(&sB, cudaStreamNonBlocking);
        cudaStreamCreateWithFlags(&sC, cudaStreamNonBlocking);
        cudaEventCreateWithFlags(&e0, cudaEventDisableTiming);
        cudaEventCreateWithFlags(&eA, cudaEventDisableTiming);
        cudaEventCreateWithFlags(&eB, cudaEventDisableTiming);
        cudaEventCreateWithFlags(&eC, cudaEventDisableTiming);
        cudaEventCreateWithFlags(&eBC, cudaEventDisableTiming);
        inited = 1;
    }

    float* goffp; cudaGetSymbolAddress((void**)&goffp, g_off);
    float* gyp;   cudaGetSymbolAddress((void**)&gyp, g_y);

    dim3 blk256(256);
    cudaEventRecord(e0, 0);
    cudaStreamWaitEvent(sA, e0, 0);
    k_conv_mma<18,1,0,0> <<<dim3(128, BATCH), blk256, CONV_SMEM, sA>>>(x, offset_w, offset_b, goffp);
    k_deform_v3          <<<dim3(64, 4, BATCH), blk256, 0, sA>>>(x, deform_w);
    cudaStreamWaitEvent(sB, e0, 0);
    k_conv_mma<32,2,96,1><<<dim3(128, BATCH), blk256, CONV_SMEM, sB>>>(x, dw2_w, dw2_b, gyp);
    cudaEventRecord(eB, sB);
    cudaStreamWaitEvent(sC, e0, 0);
    k_dw7_v3             <<<dim3(16, GC2, BATCH), blk256, 0, sC>>>(x, dw_w, dw_b);
    cudaEventRecord(eC, sC);

    cudaStreamWaitEvent(sB, eC, 0);
    k_bn1_part<1><<<BATCH*96, blk256, 0, sB>>>();
    cudaEventRecord(eBC, sB);
    k_bn1_part<0><<<BATCH*32, blk256, 0, sA>>>();
    cudaEventRecord(eA, sA);

    cudaStreamWaitEvent(0, eA, 0);
    cudaStreamWaitEvent(0, eBC, 0);
    cudaStreamWaitEvent(0, eB, 0);

    k_bn1_fold<<<1, 512>>>(bn1_g, bn1_b, w1, b1);

    k_gemm1<<<dim3(HID/128, NP/128), 256, GSMEM>>>(w1);
    k_gemm2<<<NP/128, 256, GSMEM>>>(w2, b2);

    k_bn2_final<<<DIM, 128>>>(bn2_g, bn2_b);
    k_final_v2<<<(size_t)NP*DIM/1024, blk256>>>(x, out);
}

// round 13
// speedup vs baseline: 1.7170x; 1.0644x over previous
#include <cuda_runtime.h>
#include <cuda_bf16.h>
#include <cuda_fp16.h>
#include <math.h>
#include <stdint.h>

#define BATCH 4
#define DIM 128
#define HH 128
#define WW 128
#define HW (HH*WW)           // 16384
#define NP (BATCH*HW)        // 65536
#define HID 512
#define GC1 32
#define GC2 64
#define GC3 32

// ---------------- scratch ----------------
__device__ float g_off[BATCH*18*HW];
__device__ float g_y[BATCH*DIM*HW];            // shuffled concat, NCHW
__device__ uint32_t g_t2[(size_t)(HID/2)*NP];  // GEMM1 out, half2 packed by n-pairs, [HID/2][NP]
__device__ float g_c2[(size_t)DIM*NP];         // GEMM2 out, TRANSPOSED [DIM][NP]
__device__ float g_b1f[HID];
__device__ float g_bn1_sum[BATCH*DIM];
__device__ float g_bn1_sq [BATCH*DIM];
__device__ float g_scale1[DIM], g_shift1[DIM];
__device__ float g_bn2_sum[512*DIM];
__device__ float g_bn2_sq [512*DIM];
__device__ float g_scale2[DIM], g_shift2[DIM];

__device__ __forceinline__ float gelu_exact(float v) {
    return 0.5f * v * (1.0f + erff(v * 0.70710678118654752440f));
}
__device__ __forceinline__ void mma_f16(float* c, const uint32_t* a, const uint32_t* b) {
    asm volatile("mma.sync.aligned.m16n8k16.row.col.f32.f16.f16.f32 "
        "{%0,%1,%2,%3}, {%4,%5,%6,%7}, {%8,%9}, {%0,%1,%2,%3};"
        : "+f"(c[0]), "+f"(c[1]), "+f"(c[2]), "+f"(c[3])
        : "r"(a[0]), "r"(a[1]), "r"(a[2]), "r"(a[3]), "r"(b[0]), "r"(b[1]));
}
__device__ __forceinline__ uint32_t pack_h2(float lo, float hi) {
    __half2 h = __floats2half2_rn(lo, hi);
    return *reinterpret_cast<uint32_t*>(&h);
}

#define TSTR 130   // epilogue transpose stride
#define GSMEM (128*TSTR*4)   // 66560 bytes
#define AS2 68     // gemm1 full-A stride (u32)
#define BS2 20     // GEMM B / gemm2-A chunk stride (u32)

// ======================= fp16 implicit-GEMM conv =======================
// A: [m' 0..135][k2 0..47] half2 pairs along ic, m' = gx + D.  stride 52.
// B: [oc 0..31][k2 0..143] (9 taps x 16 ic2).  stride 148.
#define CAS 52
#define CBS 148
#define CONV_SMEM ((136*CAS + 32*CBS)*4)   // 47232 bytes

template<int NOC, int D, int CBASE, int MODE>
__global__ __launch_bounds__(256) void k_conv_h(const float* __restrict__ x,
                                                const float* __restrict__ w,
                                                const float* __restrict__ bias,
                                                float* __restrict__ outp) {
    extern __shared__ uint32_t cs[];
    uint32_t* Af = cs;               // [136][CAS]
    uint32_t* Bf = cs + 136*CAS;     // [32][CBS]
    int tid = threadIdx.x;
    int lane = tid & 31, wid = tid >> 5;
    int g = lane >> 2, t = lane & 3;
    int warp_m = wid >> 1, warp_n = wid & 1;
    int y = blockIdx.x, b = blockIdx.y;

    // fill A: coalesced over m'
    for (int i = tid; i < 48*136; i += 256) {
        int k2 = i / 136, mp = i - k2*136;
        int ky = k2 >> 4, ic2 = k2 & 15;
        int ry = y + (ky - 1)*D;
        int gx = mp - D;
        float v0 = 0.f, v1 = 0.f;
        if (ry >= 0 && ry < 128 && gx >= 0 && gx < 128) {
            size_t base = (((size_t)b*DIM + CBASE + 2*ic2) << 14) + (ry << 7) + gx;
            v0 = x[base];
            v1 = x[base + HW];
        }
        Af[mp*CAS + k2] = pack_h2(v0, v1);
    }
    // fill B
    for (int i = tid; i < 144*32; i += 256) {
        int k2g = i >> 5, oc = i & 31;
        int tap = k2g / 16, ic2 = k2g & 15;
        float v0 = 0.f, v1 = 0.f;
        if (oc < NOC) {
            v0 = w[(oc*32 + 2*ic2    )*9 + tap];
            v1 = w[(oc*32 + 2*ic2 + 1)*9 + tap];
        }
        Bf[oc*CBS + k2g] = pack_h2(v0, v1);
    }
    __syncthreads();

    float acc[2][2][4] = {};
    int mbase = warp_m*32 + g;
    int nbase = warp_n*16 + g;
    #pragma unroll
    for (int tap = 0; tap < 9; tap++) {
        const int ky = tap / 3, kx = tap % 3;
        #pragma unroll
        for (int kst = 0; kst < 2; kst++) {
            int aB = ky*16 + kst*8;
            int bB = tap*16 + kst*8;
            uint32_t a[2][4], bb[2][2];
            #pragma unroll
            for (int mi = 0; mi < 2; mi++) {
                int col = mbase + mi*16 + kx*D;
                a[mi][0] = Af[col*CAS + aB + t];
                a[mi][1] = Af[(col+8)*CAS + aB + t];
                a[mi][2] = Af[col*CAS + aB + t + 4];
                a[mi][3] = Af[(col+8)*CAS + aB + t + 4];
            }
            #pragma unroll
            for (int nt = 0; nt < 2; nt++) {
                int n = nbase + nt*8;
                bb[nt][0] = Bf[n*CBS + bB + t];
                bb[nt][1] = Bf[n*CBS + bB + t + 4];
            }
            #pragma unroll
            for (int mi = 0; mi < 2; mi++)
                #pragma unroll
                for (int nt = 0; nt < 2; nt++)
                    mma_f16(acc[mi][nt], a[mi], bb[nt]);
        }
    }
    #pragma unroll
    for (int mi = 0; mi < 2; mi++) {
        #pragma unroll
        for (int nt = 0; nt < 2; nt++) {
            int col = warp_n*16 + nt*8 + 2*t;
            #pragma unroll
            for (int cc = 0; cc < 2; cc++) {
                int oc = col + cc;
                if (oc >= NOC) continue;
                float bv = bias[oc];
                int px0 = warp_m*32 + mi*16 + g;
                size_t base;
                if (MODE == 0) base = (((size_t)b*18 + oc) << 14) + (y << 7);
                else           base = (((size_t)b*DIM + 65 + 2*oc) << 14) + (y << 7);
                outp[base + px0]     = acc[mi][nt][cc]     + bv;
                outp[base + px0 + 8] = acc[mi][nt][cc + 2] + bv;
            }
        }
    }
}

// ======================= other conv kernels =======================

// depthwise 7x7 v3.  grid (16, 64, 4)
#define DSTR 39
__global__ __launch_bounds__(256) void k_dw7_v3(const float* __restrict__ x,
                                                const float* __restrict__ dww,
                                                const float* __restrict__ dwb) {
    __shared__ float s[38*DSTR];
    __shared__ float w[49];
    int tid = threadIdx.x;
    int b = blockIdx.z;
    int c = blockIdx.y;
    int ty0 = (blockIdx.x >> 2) * 32, tx0 = (blockIdx.x & 3) * 32;
    const float* xp = x + ((size_t)b*DIM + 32 + c)*HW;
    #pragma unroll 6
    for (int i = tid; i < 38*38; i += 256) {
        int sy = i / 38, sx = i - sy*38;
        int gy = ty0 + sy - 3, gx = tx0 + sx - 3;
        float v = 0.f;
        if (gy >= 0 && gy < 128 && gx >= 0 && gx < 128) v = xp[gy*WW + gx];
        s[sy*DSTR + sx] = v;
    }
    if (tid < 49) w[tid] = dww[c*49 + tid];
    __syncthreads();
    int txg = (tid & 7) * 4, ty = tid >> 3;
    float a0 = 0.f, a1 = 0.f, a2 = 0.f, a3 = 0.f;
    #pragma unroll
    for (int ky = 0; ky < 7; ky++) {
        const float* sp = s + (ty + ky)*DSTR + txg;
        float r[10];
        #pragma unroll
        for (int j = 0; j < 10; j++) r[j] = sp[j];
        #pragma unroll
        for (int kx = 0; kx < 7; kx++) {
            float wv = w[ky*7 + kx];
            a0 += r[kx]*wv; a1 += r[kx+1]*wv; a2 += r[kx+2]*wv; a3 += r[kx+3]*wv;
        }
    }
    float bias = dwb[c];
    int oldc = 32 + c;
    int newc = (oldc < 64) ? (2*oldc) : (2*(oldc-64)+1);
    float4 o; o.x = a0+bias; o.y = a1+bias; o.z = a2+bias; o.w = a3+bias;
    *(float4*)(g_y + ((size_t)b*DIM + newc)*HW + (ty0+ty)*WW + tx0+txg) = o;
}

// deformable depthwise v3.  grid (64, 4, 4)
__global__ __launch_bounds__(256) void k_deform_v3(const float* __restrict__ x,
                                                   const float* __restrict__ dfw) {
    __shared__ float wk[8][9];
    int tid = threadIdx.x;
    int b = blockIdx.z;
    int c0 = blockIdx.y * 8;
    int hw = blockIdx.x * 256 + tid;
    if (tid < 72) wk[tid/9][tid%9] = dfw[(c0 + tid/9)*9 + tid%9];
    __syncthreads();
    int h = hw >> 7, wc = hw & 127;
    const float* offb = g_off + (size_t)b*18*HW + hw;
    const float* xb = x + (((size_t)b*DIM + c0) << 14);
    float acc[8] = {};
    #pragma unroll
    for (int k = 0; k < 9; k++) {
        float dy = offb[(2*k  )*HW];
        float dx = offb[(2*k+1)*HW];
        float ys = (float)h - 1.0f + (float)(k/3) + dy;
        float xs = (float)wc - 1.0f + (float)(k%3) + dx;
        float y0 = floorf(ys), x0 = floorf(xs);
        float fy = ys - y0, fx = xs - x0;
        float vy0 = (y0 >= 0.f && y0 <= 127.f) ? 1.f : 0.f;
        float vy1 = (y0 >= -1.f && y0 <= 126.f) ? 1.f : 0.f;
        float vx0 = (x0 >= 0.f && x0 <= 127.f) ? 1.f : 0.f;
        float vx1 = (x0 >= -1.f && x0 <= 126.f) ? 1.f : 0.f;
        float w00 = (1.f-fy)*(1.f-fx) * vy0*vx0;
        float w01 = (1.f-fy)*fx       * vy0*vx1;
        float w10 = fy*(1.f-fx)       * vy1*vx0;
        float w11 = fy*fx             * vy1*vx1;
        int yi0 = min(max((int)y0, 0), 127);
        int yi1 = min(max((int)y0 + 1, 0), 127);
        int xi0 = min(max((int)x0, 0), 127);
        int xi1 = min(max((int)x0 + 1, 0), 127);
        int i00 = yi0*128 + xi0;
        int i01 = yi0*128 + xi1;
        int i10 = yi1*128 + xi0;
        int i11 = yi1*128 + xi1;
        #pragma unroll
        for (int cl = 0; cl < 8; cl++) {
            const float* xp = xb + (cl << 14);
            float sv = w00*xp[i00] + w01*xp[i01] + w10*xp[i10] + w11*xp[i11];
            acc[cl] += sv * wk[cl][k];
        }
    }
    #pragma unroll
    for (int cl = 0; cl < 8; cl++)
        g_y[(((size_t)b*DIM + 2*(c0+cl)) << 14) + hw] = acc[cl];
}

// ======================= BN1 (split by producer) =======================
template<int MODE>
__global__ __launch_bounds__(256) void k_bn1_part(void) {
    int nch = (MODE == 0) ? 32 : 96;
    int b = blockIdx.x / nch;
    int j = blockIdx.x % nch;
    int c;
    if (MODE == 0) c = 2*j;
    else           c = (j < 64) ? (2*j + 1) : (64 + 2*(j - 64));
    const float4* p = (const float4*)(g_y + (((size_t)b*DIM + c) << 14));
    float s = 0.f, q = 0.f;
    for (int i = threadIdx.x; i < HW/4; i += 256) {
        float4 v = p[i];
        s += v.x + v.y + v.z + v.w;
        q += v.x*v.x + v.y*v.y + v.z*v.z + v.w*v.w;
    }
    __shared__ float ss[256], qs[256];
    ss[threadIdx.x] = s; qs[threadIdx.x] = q;
    __syncthreads();
    for (int st = 128; st > 0; st >>= 1) {
        if (threadIdx.x < st) { ss[threadIdx.x] += ss[threadIdx.x+st]; qs[threadIdx.x] += qs[threadIdx.x+st]; }
        __syncthreads();
    }
    if (threadIdx.x == 0) { g_bn1_sum[b*DIM + c] = ss[0]; g_bn1_sq[b*DIM + c] = qs[0]; }
}

__global__ __launch_bounds__(512) void k_bn1_fold(const float* __restrict__ g,
                                                  const float* __restrict__ be,
                                                  const float* __restrict__ w1,
                                                  const float* __restrict__ b1) {
    __shared__ float sh_shift[DIM];
    int tid = threadIdx.x;
    if (tid < DIM) {
        float s = 0.f, q = 0.f;
        #pragma unroll
        for (int b = 0; b < BATCH; b++) { s += g_bn1_sum[b*DIM + tid]; q += g_bn1_sq[b*DIM + tid]; }
        float mean = s * (1.0f/NP);
        float var  = q * (1.0f/NP) - mean*mean;
        float rstd = rsqrtf(var + 1e-5f);
        float sc = g[tid] * rstd;
        float sh = be[tid] - mean * sc;
        g_scale1[tid] = sc;
        g_shift1[tid] = sh;
        sh_shift[tid] = sh;
    }
    __syncthreads();
    float bf = b1[tid];
    for (int k = 0; k < DIM; k++)
        bf += sh_shift[k] * w1[k*HID + tid];
    g_b1f[tid] = bf;
}

// ======================= fp16 mma GEMMs (R12 form) =======================
__global__ __launch_bounds__(256) void k_gemm1(const float* __restrict__ w1) {
    extern __shared__ uint32_t sm4[];
    uint32_t* Af = sm4;                 // [128][AS2]
    uint32_t* Bc = sm4 + 128*AS2;       // [128][BS2]
    float* ts = (float*)sm4;
    int tid = threadIdx.x;
    int lane = tid & 31, wid = tid >> 5;
    int g = lane >> 2, t = lane & 3;
    int warp_m = wid >> 2, warp_n = wid & 3;
    int p0 = blockIdx.y * 128, n0 = blockIdx.x * 128;
    int cb = (p0 >> 14) * DIM;
    int hw0 = p0 & (HW-1);

    #pragma unroll
    for (int l = 0; l < 32; l++) {
        int i = tid + l*256;
        int px = i & 127, k2 = i >> 7;
        float v0 = g_y[(size_t)(cb + 2*k2    )*HW + hw0 + px] * g_scale1[2*k2];
        float v1 = g_y[(size_t)(cb + 2*k2 + 1)*HW + hw0 + px] * g_scale1[2*k2 + 1];
        Af[px*AS2 + k2] = pack_h2(v0, v1);
    }
    #pragma unroll
    for (int l = 0; l < 8; l++) {
        int i = tid + l*256;
        int n = i & 127, k2 = i >> 7;
        float v0 = w1[(size_t)(2*k2    )*HID + n0 + n];
        float v1 = w1[(size_t)(2*k2 + 1)*HID + n0 + n];
        Bc[n*BS2 + k2] = pack_h2(v0, v1);
    }
    __syncthreads();

    float acc[4][4][4] = {};
    for (int kc = 0; kc < 4; kc++) {
        #pragma unroll
        for (int kst = 0; kst < 2; kst++) {
            int k2A = kc*16 + kst*8;
            int k2B = kst*8;
            uint32_t a[4][4], b[4][2];
            #pragma unroll
            for (int mi = 0; mi < 4; mi++) {
                int row = warp_m*64 + mi*16 + g;
                a[mi][0] = Af[row*AS2 + k2A + t];
                a[mi][1] = Af[(row+8)*AS2 + k2A + t];
                a[mi][2] = Af[row*AS2 + k2A + t + 4];
                a[mi][3] = Af[(row+8)*AS2 + k2A + t + 4];
            }
            #pragma unroll
            for (int nf = 0; nf < 4; nf++) {
                int col = warp_n*32 + nf*8 + g;
                b[nf][0] = Bc[col*BS2 + k2B + t];
                b[nf][1] = Bc[col*BS2 + k2B + t + 4];
            }
            #pragma unroll
            for (int mi = 0; mi < 4; mi++)
                #pragma unroll
                for (int nf = 0; nf < 4; nf++)
                    mma_f16(acc[mi][nf], a[mi], b[nf]);
        }
        __syncthreads();
        if (kc < 3) {
            int kt = (kc+1)*32;
            #pragma unroll
            for (int l = 0; l < 8; l++) {
                int i = tid + l*256;
                int n = i & 127, k2 = i >> 7;
                float v0 = w1[(size_t)(kt + 2*k2    )*HID + n0 + n];
                float v1 = w1[(size_t)(kt + 2*k2 + 1)*HID + n0 + n];
                Bc[n*BS2 + k2] = pack_h2(v0, v1);
            }
            __syncthreads();
        }
    }
    #pragma unroll
    for (int mi = 0; mi < 4; mi++) {
        int row = warp_m*64 + mi*16 + g;
        #pragma unroll
        for (int nf = 0; nf < 4; nf++) {
            int col = warp_n*32 + nf*8 + 2*t;
            float b0v = g_b1f[n0 + col], b1v = g_b1f[n0 + col + 1];
            ts[row*TSTR + col]       = gelu_exact(acc[mi][nf][0] + b0v);
            ts[row*TSTR + col + 1]   = gelu_exact(acc[mi][nf][1] + b1v);
            ts[(row+8)*TSTR + col]   = gelu_exact(acc[mi][nf][2] + b0v);
            ts[(row+8)*TSTR + col+1] = gelu_exact(acc[mi][nf][3] + b1v);
        }
    }
    __syncthreads();
    #pragma unroll
    for (int l = 0; l < 32; l++) {
        int i = tid + l*256;
        int n2 = i >> 7, p = i & 127;
        uint32_t h = pack_h2(ts[p*TSTR + 2*n2], ts[p*TSTR + 2*n2 + 1]);
        g_t2[(size_t)((n0 >> 1) + n2)*NP + p0 + p] = h;
    }
}

__global__ __launch_bounds__(256) void k_gemm2(const float* __restrict__ w2,
                                               const float* __restrict__ b2) {
    extern __shared__ uint32_t sm4[];
    uint32_t* Ac = sm4;                 // [128][BS2]
    uint32_t* Bc = sm4 + 128*BS2;       // [128][BS2]
    float* ts = (float*)sm4;
    __shared__ float rs[256], rq[256];
    int tid = threadIdx.x;
    int lane = tid & 31, wid = tid >> 5;
    int g = lane >> 2, t = lane & 3;
    int warp_m = wid >> 2, warp_n = wid & 3;
    int p0 = blockIdx.x * 128;

    #pragma unroll
    for (int l = 0; l < 8; l++) {
        int i = tid + l*256;
        int px = i & 127, k2 = i >> 7;
        Ac[px*BS2 + k2] = g_t2[(size_t)k2*NP + p0 + px];
    }
    #pragma unroll
    for (int l = 0; l < 8; l++) {
        int i = tid + l*256;
        int n = i & 127, k2 = i >> 7;
        float v0 = w2[(size_t)(2*k2    )*DIM + n];
        float v1 = w2[(size_t)(2*k2 + 1)*DIM + n];
        Bc[n*BS2 + k2] = pack_h2(v0, v1);
    }
    __syncthreads();

    float acc[4][4][4] = {};
    for (int kc = 0; kc < 16; kc++) {
        uint32_t pa[8];
        if (kc < 15) {
            int kt2 = (kc+1)*16;
            #pragma unroll
            for (int l = 0; l < 8; l++) {
                int i = tid + l*256;
                int px = i & 127, k2 = i >> 7;
                pa[l] = g_t2[(size_t)(kt2 + k2)*NP + p0 + px];
            }
        }
        #pragma unroll
        for (int kst = 0; kst < 2; kst++) {
            int k2b = kst*8;
            uint32_t a[4][4], b[4][2];
            #pragma unroll
            for (int mi = 0; mi < 4; mi++) {
                int row = warp_m*64 + mi*16 + g;
                a[mi][0] = Ac[row*BS2 + k2b + t];
                a[mi][1] = Ac[(row+8)*BS2 + k2b + t];
                a[mi][2] = Ac[row*BS2 + k2b + t + 4];
                a[mi][3] = Ac[(row+8)*BS2 + k2b + t + 4];
            }
            #pragma unroll
            for (int nf = 0; nf < 4; nf++) {
                int col = warp_n*32 + nf*8 + g;
                b[nf][0] = Bc[col*BS2 + k2b + t];
                b[nf][1] = Bc[col*BS2 + k2b + t + 4];
            }
            #pragma unroll
            for (int mi = 0; mi < 4; mi++)
                #pragma unroll
                for (int nf = 0; nf < 4; nf++)
                    mma_f16(acc[mi][nf], a[mi], b[nf]);
        }
        __syncthreads();
        if (kc < 15) {
            int kt = (kc+1)*32;
            #pragma unroll
            for (int l = 0; l < 8; l++) {
                int i = tid + l*256;
                int px = i & 127, k2 = i >> 7;
                Ac[px*BS2 + k2] = pa[l];
            }
            #pragma unroll
            for (int l = 0; l < 8; l++) {
                int i = tid + l*256;
                int n = i & 127, k2 = i >> 7;
                float v0 = w2[(size_t)(kt + 2*k2    )*DIM + n];
                float v1 = w2[(size_t)(kt + 2*k2 + 1)*DIM + n];
                Bc[n*BS2 + k2] = pack_h2(v0, v1);
            }
            __syncthreads();
        }
    }
    #pragma unroll
    for (int mi = 0; mi < 4; mi++) {
        int row = warp_m*64 + mi*16 + g;
        #pragma unroll
        for (int nf = 0; nf < 4; nf++) {
            int col = warp_n*32 + nf*8 + 2*t;
            float b0v = b2[col], b1v = b2[col + 1];
            ts[row*TSTR + col]       = acc[mi][nf][0] + b0v;
            ts[row*TSTR + col + 1]   = acc[mi][nf][1] + b1v;
            ts[(row+8)*TSTR + col]   = acc[mi][nf][2] + b0v;
            ts[(row+8)*TSTR + col+1] = acc[mi][nf][3] + b1v;
        }
    }
    __syncthreads();
    #pragma unroll
    for (int l = 0; l < 64; l++) {
        int i = tid + l*256;
        int n = i >> 7, p = i & 127;
        g_c2[(size_t)n*NP + p0 + p] = ts[p*TSTR + n];
    }
    {
        int n = tid & 127;
        int ph = tid >> 7;
        float s = 0.f, q = 0.f;
        for (int p = ph; p < 128; p += 2) {
            float v = ts[p*TSTR + n];
            s += v; q += v*v;
        }
        rs[tid] = s; rq[tid] = q;
        __syncthreads();
        if (tid < 128) {
            g_bn2_sum[blockIdx.x*128 + tid] = rs[tid] + rs[tid+128];
            g_bn2_sq [blockIdx.x*128 + tid] = rq[tid] + rq[tid+128];
        }
    }
}

// ======================= BN2 final + output =======================
__global__ void k_bn2_final(const float* __restrict__ g, const float* __restrict__ be) {
    int c = blockIdx.x;
    int tid = threadIdx.x;
    __shared__ float ss[128], qs[128];
    float s = 0.f, q = 0.f;
    for (int i = tid; i < 512; i += 128) {
        s += g_bn2_sum[i*128 + c];
        q += g_bn2_sq [i*128 + c];
    }
    ss[tid] = s; qs[tid] = q;
    __syncthreads();
    for (int st = 64; st > 0; st >>= 1) {
        if (tid < st) { ss[tid] += ss[tid+st]; qs[tid] += qs[tid+st]; }
        __syncthreads();
    }
    if (tid == 0) {
        float mean = ss[0] * (1.0f/NP);
        float var  = qs[0] * (1.0f/NP) - mean*mean;
        float rstd = rsqrtf(var + 1e-5f);
        float sc = g[c] * rstd;
        g_scale2[c] = sc;
        g_shift2[c] = be[c] - mean * sc;
    }
}
__global__ __launch_bounds__(256) void k_final_v2(const float* __restrict__ x, float* __restrict__ out) {
    int i4 = blockIdx.x * 256 + threadIdx.x;
    int i = i4 << 2;
    int b = i >> 21;
    int c = (i >> 14) & 127;
    int hw = i & 16383;
    float sc = g_scale2[c], sh = g_shift2[c];
    float4 v = *(const float4*)(g_c2 + (size_t)c*NP + (b<<14) + hw);
    float4 xv = *(const float4*)(x + i);
    float4 o;
    o.x = gelu_exact(xv.x + v.x*sc + sh);
    o.y = gelu_exact(xv.y + v.y*sc + sh);
    o.z = gelu_exact(xv.z + v.z*sc + sh);
    o.w = gelu_exact(xv.w + v.w*sc + sh);
    *(float4*)(out + i) = o;
}

// ================================ launch ================================
extern "C" void kernel_launch(void* const* d_in, const int* in_sizes, int n_in,
                              void* d_out, int out_size) {
    const float* x        = (const float*)d_in[0];
    const float* offset_w = (const float*)d_in[1];
    const float* offset_b = (const float*)d_in[2];
    const float* deform_w = (const float*)d_in[3];
    const float* dw_w     = (const float*)d_in[4];
    const float* dw_b     = (const float*)d_in[5];
    const float* dw2_w    = (const float*)d_in[6];
    const float* dw2_b    = (const float*)d_in[7];
    const float* bn1_g    = (const float*)d_in[8];
    const float* bn1_b    = (const float*)d_in[9];
    const float* w1       = (const float*)d_in[10];
    const float* b1       = (const float*)d_in[11];
    const float* w2       = (const float*)d_in[12];
    const float* b2       = (const float*)d_in[13];
    const float* bn2_g    = (const float*)d_in[14];
    const float* bn2_b    = (const float*)d_in[15];
    float* out = (float*)d_out;

    static int inited = 0;
    static cudaStream_t sA, sB, sC;
    static cudaEvent_t e0, eA, eB, eC, eBC;
    if (!inited) {
        cudaFuncSetAttribute(k_gemm1, cudaFuncAttributeMaxDynamicSharedMemorySize, GSMEM);
        cudaFuncSetAttribute(k_gemm2, cudaFuncAttributeMaxDynamicSharedMemorySize, GSMEM);
        cudaFuncSetAttribute(k_conv_h<18,1,0,0>, cudaFuncAttributeMaxDynamicSharedMemorySize, CONV_SMEM);
        cudaFuncSetAttribute(k_conv_h<32,2,96,1>, cudaFuncAttributeMaxDynamicSharedMemorySize, CONV_SMEM);
        cudaStreamCreateWithFlags(&sA, cudaStreamNonBlocking);
        cudaStreamCreateWithFlags(&sB, cudaStreamNonBlocking);
        cudaStreamCreateWithFlags(&sC, cudaStreamNonBlocking);
        cudaEventCreateWithFlags(&e0, cudaEventDisableTiming);
        cudaEventCreateWithFlags(&eA, cudaEventDisableTiming);
        cudaEventCreateWithFlags(&eB, cudaEventDisableTiming);
        cudaEventCreateWithFlags(&eC, cudaEventDisableTiming);
        cudaEventCreateWithFlags(&eBC, cudaEventDisableTiming);
        inited = 1;
    }

    float* goffp; cudaGetSymbolAddress((void**)&goffp, g_off);
    float* gyp;   cudaGetSymbolAddress((void**)&gyp, g_y);

    dim3 blk256(256);
    cudaEventRecord(e0, 0);
    cudaStreamWaitEvent(sA, e0, 0);
    k_conv_h<18,1,0,0> <<<dim3(128, BATCH), blk256, CONV_SMEM, sA>>>(x, offset_w, offset_b, goffp);
    k_deform_v3        <<<dim3(64, 4, BATCH), blk256, 0, sA>>>(x, deform_w);
    cudaStreamWaitEvent(sB, e0, 0);
    k_conv_h<32,2,96,1><<<dim3(128, BATCH), blk256, CONV_SMEM, sB>>>(x, dw2_w, dw2_b, gyp);
    cudaEventRecord(eB, sB);
    cudaStreamWaitEvent(sC, e0, 0);
    k_dw7_v3           <<<dim3(16, GC2, BATCH), blk256, 0, sC>>>(x, dw_w, dw_b);
    cudaEventRecord(eC, sC);

    cudaStreamWaitEvent(sB, eC, 0);
    k_bn1_part<1><<<BATCH*96, blk256, 0, sB>>>();
    cudaEventRecord(eBC, sB);
    k_bn1_part<0><<<BATCH*32, blk256, 0, sA>>>();
    cudaEventRecord(eA, sA);

    cudaStreamWaitEvent(0, eA, 0);
    cudaStreamWaitEvent(0, eBC, 0);
    cudaStreamWaitEvent(0, eB, 0);

    k_bn1_fold<<<1, 512>>>(bn1_g, bn1_b, w1, b1);

    k_gemm1<<<dim3(HID/128, NP/128), 256, GSMEM>>>(w1);
    k_gemm2<<<NP/128, 256, GSMEM>>>(w2, b2);

    k_bn2_final<<<DIM, 128>>>(bn2_g, bn2_b);
    k_final_v2<<<(size_t)NP*DIM/1024, blk256>>>(x, out);
}

// round 14
// speedup vs baseline: 1.7255x; 1.0050x over previous
#include <cuda_runtime.h>
#include <cuda_bf16.h>
#include <cuda_fp16.h>
#include <math.h>
#include <stdint.h>

#define BATCH 4
#define DIM 128
#define HH 128
#define WW 128
#define HW (HH*WW)           // 16384
#define NP (BATCH*HW)        // 65536
#define HID 512
#define GC1 32
#define GC2 64
#define GC3 32

// ---------------- scratch ----------------
__device__ float g_off[BATCH*18*HW];
__device__ float g_y[BATCH*DIM*HW];            // shuffled concat, NCHW
__device__ uint32_t g_t2[(size_t)(HID/2)*NP];  // GEMM1 out, half2 packed by n-pairs, [HID/2][NP]
__device__ float g_c2[(size_t)DIM*NP];         // GEMM2 out, TRANSPOSED [DIM][NP]
__device__ float g_b1f[HID];
__device__ float g_bn1_sum[BATCH*DIM];
__device__ float g_bn1_sq [BATCH*DIM];
__device__ float g_scale1[DIM], g_shift1[DIM];
__device__ float g_bn2_sum[512*DIM];
__device__ float g_bn2_sq [512*DIM];
__device__ float g_scale2[DIM], g_shift2[DIM];

__device__ __forceinline__ float gelu_exact(float v) {
    return 0.5f * v * (1.0f + erff(v * 0.70710678118654752440f));
}
__device__ __forceinline__ void mma_f16(float* c, const uint32_t* a, const uint32_t* b) {
    asm volatile("mma.sync.aligned.m16n8k16.row.col.f32.f16.f16.f32 "
        "{%0,%1,%2,%3}, {%4,%5,%6,%7}, {%8,%9}, {%0,%1,%2,%3};"
        : "+f"(c[0]), "+f"(c[1]), "+f"(c[2]), "+f"(c[3])
        : "r"(a[0]), "r"(a[1]), "r"(a[2]), "r"(a[3]), "r"(b[0]), "r"(b[1]));
}
__device__ __forceinline__ uint32_t pack_h2(float lo, float hi) {
    __half2 h = __floats2half2_rn(lo, hi);
    return *reinterpret_cast<uint32_t*>(&h);
}

#define TSTR 130   // epilogue transpose stride
#define AS2 68     // gemm1 full-A stride (u32)
#define BS2 20     // GEMM B / gemm2-A chunk stride (u32)
// gemm1: Af | Bc | ts  (A persistent across the 4 N-tiles)
#define G1SMEM ((128*AS2 + 128*BS2)*4 + 128*TSTR*4)   // 34816+10240+66560 = 111616
// gemm2: tiles overlay ts as before
#define G2SMEM (128*TSTR*4)   // 66560

// ======================= fp16 implicit-GEMM conv =======================
#define CAS 52
#define CBS 148
#define CONV_SMEM ((136*CAS + 32*CBS)*4)   // 47232 bytes

template<int NOC, int D, int CBASE, int MODE>
__global__ __launch_bounds__(256) void k_conv_h(const float* __restrict__ x,
                                                const float* __restrict__ w,
                                                const float* __restrict__ bias,
                                                float* __restrict__ outp) {
    extern __shared__ uint32_t cs[];
    uint32_t* Af = cs;               // [136][CAS]
    uint32_t* Bf = cs + 136*CAS;     // [32][CBS]
    int tid = threadIdx.x;
    int lane = tid & 31, wid = tid >> 5;
    int g = lane >> 2, t = lane & 3;
    int warp_m = wid >> 1, warp_n = wid & 1;
    int y = blockIdx.x, b = blockIdx.y;

    for (int i = tid; i < 48*136; i += 256) {
        int k2 = i / 136, mp = i - k2*136;
        int ky = k2 >> 4, ic2 = k2 & 15;
        int ry = y + (ky - 1)*D;
        int gx = mp - D;
        float v0 = 0.f, v1 = 0.f;
        if (ry >= 0 && ry < 128 && gx >= 0 && gx < 128) {
            size_t base = (((size_t)b*DIM + CBASE + 2*ic2) << 14) + (ry << 7) + gx;
            v0 = x[base];
            v1 = x[base + HW];
        }
        Af[mp*CAS + k2] = pack_h2(v0, v1);
    }
    for (int i = tid; i < 144*32; i += 256) {
        int k2g = i >> 5, oc = i & 31;
        int tap = k2g / 16, ic2 = k2g & 15;
        float v0 = 0.f, v1 = 0.f;
        if (oc < NOC) {
            v0 = w[(oc*32 + 2*ic2    )*9 + tap];
            v1 = w[(oc*32 + 2*ic2 + 1)*9 + tap];
        }
        Bf[oc*CBS + k2g] = pack_h2(v0, v1);
    }
    __syncthreads();

    float acc[2][2][4] = {};
    int mbase = warp_m*32 + g;
    int nbase = warp_n*16 + g;
    #pragma unroll
    for (int tap = 0; tap < 9; tap++) {
        const int ky = tap / 3, kx = tap % 3;
        #pragma unroll
        for (int kst = 0; kst < 2; kst++) {
            int aB = ky*16 + kst*8;
            int bB = tap*16 + kst*8;
            uint32_t a[2][4], bb[2][2];
            #pragma unroll
            for (int mi = 0; mi < 2; mi++) {
                int col = mbase + mi*16 + kx*D;
                a[mi][0] = Af[col*CAS + aB + t];
                a[mi][1] = Af[(col+8)*CAS + aB + t];
                a[mi][2] = Af[col*CAS + aB + t + 4];
                a[mi][3] = Af[(col+8)*CAS + aB + t + 4];
            }
            #pragma unroll
            for (int nt = 0; nt < 2; nt++) {
                int n = nbase + nt*8;
                bb[nt][0] = Bf[n*CBS + bB + t];
                bb[nt][1] = Bf[n*CBS + bB + t + 4];
            }
            #pragma unroll
            for (int mi = 0; mi < 2; mi++)
                #pragma unroll
                for (int nt = 0; nt < 2; nt++)
                    mma_f16(acc[mi][nt], a[mi], bb[nt]);
        }
    }
    #pragma unroll
    for (int mi = 0; mi < 2; mi++) {
        #pragma unroll
        for (int nt = 0; nt < 2; nt++) {
            int col = warp_n*16 + nt*8 + 2*t;
            #pragma unroll
            for (int cc = 0; cc < 2; cc++) {
                int oc = col + cc;
                if (oc >= NOC) continue;
                float bv = bias[oc];
                int px0 = warp_m*32 + mi*16 + g;
                size_t base;
                if (MODE == 0) base = (((size_t)b*18 + oc) << 14) + (y << 7);
                else           base = (((size_t)b*DIM + 65 + 2*oc) << 14) + (y << 7);
                outp[base + px0]     = acc[mi][nt][cc]     + bv;
                outp[base + px0 + 8] = acc[mi][nt][cc + 2] + bv;
            }
        }
    }
}

// ======================= other conv kernels =======================

// depthwise 7x7 v3.  grid (16, 64, 4)
#define DSTR 39
__global__ __launch_bounds__(256) void k_dw7_v3(const float* __restrict__ x,
                                                const float* __restrict__ dww,
                                                const float* __restrict__ dwb) {
    __shared__ float s[38*DSTR];
    __shared__ float w[49];
    int tid = threadIdx.x;
    int b = blockIdx.z;
    int c = blockIdx.y;
    int ty0 = (blockIdx.x >> 2) * 32, tx0 = (blockIdx.x & 3) * 32;
    const float* xp = x + ((size_t)b*DIM + 32 + c)*HW;
    #pragma unroll 6
    for (int i = tid; i < 38*38; i += 256) {
        int sy = i / 38, sx = i - sy*38;
        int gy = ty0 + sy - 3, gx = tx0 + sx - 3;
        float v = 0.f;
        if (gy >= 0 && gy < 128 && gx >= 0 && gx < 128) v = xp[gy*WW + gx];
        s[sy*DSTR + sx] = v;
    }
    if (tid < 49) w[tid] = dww[c*49 + tid];
    __syncthreads();
    int txg = (tid & 7) * 4, ty = tid >> 3;
    float a0 = 0.f, a1 = 0.f, a2 = 0.f, a3 = 0.f;
    #pragma unroll
    for (int ky = 0; ky < 7; ky++) {
        const float* sp = s + (ty + ky)*DSTR + txg;
        float r[10];
        #pragma unroll
        for (int j = 0; j < 10; j++) r[j] = sp[j];
        #pragma unroll
        for (int kx = 0; kx < 7; kx++) {
            float wv = w[ky*7 + kx];
            a0 += r[kx]*wv; a1 += r[kx+1]*wv; a2 += r[kx+2]*wv; a3 += r[kx+3]*wv;
        }
    }
    float bias = dwb[c];
    int oldc = 32 + c;
    int newc = (oldc < 64) ? (2*oldc) : (2*(oldc-64)+1);
    float4 o; o.x = a0+bias; o.y = a1+bias; o.z = a2+bias; o.w = a3+bias;
    *(float4*)(g_y + ((size_t)b*DIM + newc)*HW + (ty0+ty)*WW + tx0+txg) = o;
}

// deformable depthwise v3.  grid (64, 4, 4)
__global__ __launch_bounds__(256) void k_deform_v3(const float* __restrict__ x,
                                                   const float* __restrict__ dfw) {
    __shared__ float wk[8][9];
    int tid = threadIdx.x;
    int b = blockIdx.z;
    int c0 = blockIdx.y * 8;
    int hw = blockIdx.x * 256 + tid;
    if (tid < 72) wk[tid/9][tid%9] = dfw[(c0 + tid/9)*9 + tid%9];
    __syncthreads();
    int h = hw >> 7, wc = hw & 127;
    const float* offb = g_off + (size_t)b*18*HW + hw;
    const float* xb = x + (((size_t)b*DIM + c0) << 14);
    float acc[8] = {};
    #pragma unroll
    for (int k = 0; k < 9; k++) {
        float dy = offb[(2*k  )*HW];
        float dx = offb[(2*k+1)*HW];
        float ys = (float)h - 1.0f + (float)(k/3) + dy;
        float xs = (float)wc - 1.0f + (float)(k%3) + dx;
        float y0 = floorf(ys), x0 = floorf(xs);
        float fy = ys - y0, fx = xs - x0;
        float vy0 = (y0 >= 0.f && y0 <= 127.f) ? 1.f : 0.f;
        float vy1 = (y0 >= -1.f && y0 <= 126.f) ? 1.f : 0.f;
        float vx0 = (x0 >= 0.f && x0 <= 127.f) ? 1.f : 0.f;
        float vx1 = (x0 >= -1.f && x0 <= 126.f) ? 1.f : 0.f;
        float w00 = (1.f-fy)*(1.f-fx) * vy0*vx0;
        float w01 = (1.f-fy)*fx       * vy0*vx1;
        float w10 = fy*(1.f-fx)       * vy1*vx0;
        float w11 = fy*fx             * vy1*vx1;
        int yi0 = min(max((int)y0, 0), 127);
        int yi1 = min(max((int)y0 + 1, 0), 127);
        int xi0 = min(max((int)x0, 0), 127);
        int xi1 = min(max((int)x0 + 1, 0), 127);
        int i00 = yi0*128 + xi0;
        int i01 = yi0*128 + xi1;
        int i10 = yi1*128 + xi0;
        int i11 = yi1*128 + xi1;
        #pragma unroll
        for (int cl = 0; cl < 8; cl++) {
            const float* xp = xb + (cl << 14);
            float sv = w00*xp[i00] + w01*xp[i01] + w10*xp[i10] + w11*xp[i11];
            acc[cl] += sv * wk[cl][k];
        }
    }
    #pragma unroll
    for (int cl = 0; cl < 8; cl++)
        g_y[(((size_t)b*DIM + 2*(c0+cl)) << 14) + hw] = acc[cl];
}

// ======================= BN1 (split by producer) =======================
template<int MODE>
__global__ __launch_bounds__(256) void k_bn1_part(void) {
    int nch = (MODE == 0) ? 32 : 96;
    int b = blockIdx.x / nch;
    int j = blockIdx.x % nch;
    int c;
    if (MODE == 0) c = 2*j;
    else           c = (j < 64) ? (2*j + 1) : (64 + 2*(j - 64));
    const float4* p = (const float4*)(g_y + (((size_t)b*DIM + c) << 14));
    float s = 0.f, q = 0.f;
    for (int i = threadIdx.x; i < HW/4; i += 256) {
        float4 v = p[i];
        s += v.x + v.y + v.z + v.w;
        q += v.x*v.x + v.y*v.y + v.z*v.z + v.w*v.w;
    }
    __shared__ float ss[256], qs[256];
    ss[threadIdx.x] = s; qs[threadIdx.x] = q;
    __syncthreads();
    for (int st = 128; st > 0; st >>= 1) {
        if (threadIdx.x < st) { ss[threadIdx.x] += ss[threadIdx.x+st]; qs[threadIdx.x] += qs[threadIdx.x+st]; }
        __syncthreads();
    }
    if (threadIdx.x == 0) { g_bn1_sum[b*DIM + c] = ss[0]; g_bn1_sq[b*DIM + c] = qs[0]; }
}

__global__ __launch_bounds__(512) void k_bn1_fold(const float* __restrict__ g,
                                                  const float* __restrict__ be,
                                                  const float* __restrict__ w1,
                                                  const float* __restrict__ b1) {
    __shared__ float sh_shift[DIM];
    int tid = threadIdx.x;
    if (tid < DIM) {
        float s = 0.f, q = 0.f;
        #pragma unroll
        for (int b = 0; b < BATCH; b++) { s += g_bn1_sum[b*DIM + tid]; q += g_bn1_sq[b*DIM + tid]; }
        float mean = s * (1.0f/NP);
        float var  = q * (1.0f/NP) - mean*mean;
        float rstd = rsqrtf(var + 1e-5f);
        float sc = g[tid] * rstd;
        float sh = be[tid] - mean * sc;
        g_scale1[tid] = sc;
        g_shift1[tid] = sh;
        sh_shift[tid] = sh;
    }
    __syncthreads();
    float bf = b1[tid];
    for (int k = 0; k < DIM; k++)
        bf += sh_shift[k] * w1[k*HID + tid];
    g_b1f[tid] = bf;
}

// ======================= fp16 mma GEMMs =======================
// GEMM1 v2: persistent A across all 4 N-tiles.  grid 512.
// smem: Af [128][AS2] | Bc [128][BS2] | ts float[128][TSTR]
__global__ __launch_bounds__(256) void k_gemm1(const float* __restrict__ w1) {
    extern __shared__ uint32_t sm4[];
    uint32_t* Af = sm4;                       // 8704 u32
    uint32_t* Bc = sm4 + 128*AS2;             // 2560 u32
    float* ts = (float*)(sm4 + 128*AS2 + 128*BS2);
    int tid = threadIdx.x;
    int lane = tid & 31, wid = tid >> 5;
    int g = lane >> 2, t = lane & 3;
    int warp_m = wid >> 2, warp_n = wid & 3;
    int p0 = blockIdx.x * 128;
    int cb = (p0 >> 14) * DIM;
    int hw0 = p0 & (HW-1);

    // fill full A once (BN1 scale fused)
    #pragma unroll
    for (int l = 0; l < 32; l++) {
        int i = tid + l*256;
        int px = i & 127, k2 = i >> 7;
        float v0 = g_y[(size_t)(cb + 2*k2    )*HW + hw0 + px] * g_scale1[2*k2];
        float v1 = g_y[(size_t)(cb + 2*k2 + 1)*HW + hw0 + px] * g_scale1[2*k2 + 1];
        Af[px*AS2 + k2] = pack_h2(v0, v1);
    }

    for (int nt = 0; nt < 4; nt++) {
        int n0 = nt * 128;
        float acc[4][4][4] = {};
        for (int kc = 0; kc < 4; kc++) {
            __syncthreads();   // prior readers of Bc / ts done
            int kt = kc*32;
            #pragma unroll
            for (int l = 0; l < 8; l++) {
                int i = tid + l*256;
                int n = i & 127, k2 = i >> 7;
                float v0 = w1[(size_t)(kt + 2*k2    )*HID + n0 + n];
                float v1 = w1[(size_t)(kt + 2*k2 + 1)*HID + n0 + n];
                Bc[n*BS2 + k2] = pack_h2(v0, v1);
            }
            __syncthreads();
            #pragma unroll
            for (int kst = 0; kst < 2; kst++) {
                int k2A = kc*16 + kst*8;
                int k2B = kst*8;
                uint32_t a[4][4], b[4][2];
                #pragma unroll
                for (int mi = 0; mi < 4; mi++) {
                    int row = warp_m*64 + mi*16 + g;
                    a[mi][0] = Af[row*AS2 + k2A + t];
                    a[mi][1] = Af[(row+8)*AS2 + k2A + t];
                    a[mi][2] = Af[row*AS2 + k2A + t + 4];
                    a[mi][3] = Af[(row+8)*AS2 + k2A + t + 4];
                }
                #pragma unroll
                for (int nf = 0; nf < 4; nf++) {
                    int col = warp_n*32 + nf*8 + g;
                    b[nf][0] = Bc[col*BS2 + k2B + t];
                    b[nf][1] = Bc[col*BS2 + k2B + t + 4];
                }
                #pragma unroll
                for (int mi = 0; mi < 4; mi++)
                    #pragma unroll
                    for (int nf = 0; nf < 4; nf++)
                        mma_f16(acc[mi][nf], a[mi], b[nf]);
            }
        }
        // epilogue: bias + gelu -> ts, transpose, half2-packed store
        #pragma unroll
        for (int mi = 0; mi < 4; mi++) {
            int row = warp_m*64 + mi*16 + g;
            #pragma unroll
            for (int nf = 0; nf < 4; nf++) {
                int col = warp_n*32 + nf*8 + 2*t;
                float b0v = g_b1f[n0 + col], b1v = g_b1f[n0 + col + 1];
                ts[row*TSTR + col]       = gelu_exact(acc[mi][nf][0] + b0v);
                ts[row*TSTR + col + 1]   = gelu_exact(acc[mi][nf][1] + b1v);
                ts[(row+8)*TSTR + col]   = gelu_exact(acc[mi][nf][2] + b0v);
                ts[(row+8)*TSTR + col+1] = gelu_exact(acc[mi][nf][3] + b1v);
            }
        }
        __syncthreads();
        #pragma unroll
        for (int l = 0; l < 32; l++) {
            int i = tid + l*256;
            int n2 = i >> 7, p = i & 127;
            uint32_t h = pack_h2(ts[p*TSTR + 2*n2], ts[p*TSTR + 2*n2 + 1]);
            g_t2[(size_t)((n0 >> 1) + n2)*NP + p0 + p] = h;
        }
    }
}

// GEMM2 + fused BN2 partials (R12/R13 form, unchanged)
__global__ __launch_bounds__(256) void k_gemm2(const float* __restrict__ w2,
                                               const float* __restrict__ b2) {
    extern __shared__ uint32_t sm4[];
    uint32_t* Ac = sm4;                 // [128][BS2]
    uint32_t* Bc = sm4 + 128*BS2;       // [128][BS2]
    float* ts = (float*)sm4;
    __shared__ float rs[256], rq[256];
    int tid = threadIdx.x;
    int lane = tid & 31, wid = tid >> 5;
    int g = lane >> 2, t = lane & 3;
    int warp_m = wid >> 2, warp_n = wid & 3;
    int p0 = blockIdx.x * 128;

    #pragma unroll
    for (int l = 0; l < 8; l++) {
        int i = tid + l*256;
        int px = i & 127, k2 = i >> 7;
        Ac[px*BS2 + k2] = g_t2[(size_t)k2*NP + p0 + px];
    }
    #pragma unroll
    for (int l = 0; l < 8; l++) {
        int i = tid + l*256;
        int n = i & 127, k2 = i >> 7;
        float v0 = w2[(size_t)(2*k2    )*DIM + n];
        float v1 = w2[(size_t)(2*k2 + 1)*DIM + n];
        Bc[n*BS2 + k2] = pack_h2(v0, v1);
    }
    __syncthreads();

    float acc[4][4][4] = {};
    for (int kc = 0; kc < 16; kc++) {
        uint32_t pa[8];
        if (kc < 15) {
            int kt2 = (kc+1)*16;
            #pragma unroll
            for (int l = 0; l < 8; l++) {
                int i = tid + l*256;
                int px = i & 127, k2 = i >> 7;
                pa[l] = g_t2[(size_t)(kt2 + k2)*NP + p0 + px];
            }
        }
        #pragma unroll
        for (int kst = 0; kst < 2; kst++) {
            int k2b = kst*8;
            uint32_t a[4][4], b[4][2];
            #pragma unroll
            for (int mi = 0; mi < 4; mi++) {
                int row = warp_m*64 + mi*16 + g;
                a[mi][0] = Ac[row*BS2 + k2b + t];
                a[mi][1] = Ac[(row+8)*BS2 + k2b + t];
                a[mi][2] = Ac[row*BS2 + k2b + t + 4];
                a[mi][3] = Ac[(row+8)*BS2 + k2b + t + 4];
            }
            #pragma unroll
            for (int nf = 0; nf < 4; nf++) {
                int col = warp_n*32 + nf*8 + g;
                b[nf][0] = Bc[col*BS2 + k2b + t];
                b[nf][1] = Bc[col*BS2 + k2b + t + 4];
            }
            #pragma unroll
            for (int mi = 0; mi < 4; mi++)
                #pragma unroll
                for (int nf = 0; nf < 4; nf++)
                    mma_f16(acc[mi][nf], a[mi], b[nf]);
        }
        __syncthreads();
        if (kc < 15) {
            int kt = (kc+1)*32;
            #pragma unroll
            for (int l = 0; l < 8; l++) {
                int i = tid + l*256;
                int px = i & 127, k2 = i >> 7;
                Ac[px*BS2 + k2] = pa[l];
            }
            #pragma unroll
            for (int l = 0; l < 8; l++) {
                int i = tid + l*256;
                int n = i & 127, k2 = i >> 7;
                float v0 = w2[(size_t)(kt + 2*k2    )*DIM + n];
                float v1 = w2[(size_t)(kt + 2*k2 + 1)*DIM + n];
                Bc[n*BS2 + k2] = pack_h2(v0, v1);
            }
            __syncthreads();
        }
    }
    #pragma unroll
    for (int mi = 0; mi < 4; mi++) {
        int row = warp_m*64 + mi*16 + g;
        #pragma unroll
        for (int nf = 0; nf < 4; nf++) {
            int col = warp_n*32 + nf*8 + 2*t;
            float b0v = b2[col], b1v = b2[col + 1];
            ts[row*TSTR + col]       = acc[mi][nf][0] + b0v;
            ts[row*TSTR + col + 1]   = acc[mi][nf][1] + b1v;
            ts[(row+8)*TSTR + col]   = acc[mi][nf][2] + b0v;
            ts[(row+8)*TSTR + col+1] = acc[mi][nf][3] + b1v;
        }
    }
    __syncthreads();
    #pragma unroll
    for (int l = 0; l < 64; l++) {
        int i = tid + l*256;
        int n = i >> 7, p = i & 127;
        g_c2[(size_t)n*NP + p0 + p] = ts[p*TSTR + n];
    }
    {
        int n = tid & 127;
        int ph = tid >> 7;
        float s = 0.f, q = 0.f;
        for (int p = ph; p < 128; p += 2) {
            float v = ts[p*TSTR + n];
            s += v; q += v*v;
        }
        rs[tid] = s; rq[tid] = q;
        __syncthreads();
        if (tid < 128) {
            g_bn2_sum[blockIdx.x*128 + tid] = rs[tid] + rs[tid+128];
            g_bn2_sq [blockIdx.x*128 + tid] = rq[tid] + rq[tid+128];
        }
    }
}

// ======================= BN2 final + output =======================
__global__ void k_bn2_final(const float* __restrict__ g, const float* __restrict__ be) {
    int c = blockIdx.x;
    int tid = threadIdx.x;
    __shared__ float ss[128], qs[128];
    float s = 0.f, q = 0.f;
    for (int i = tid; i < 512; i += 128) {
        s += g_bn2_sum[i*128 + c];
        q += g_bn2_sq [i*128 + c];
    }
    ss[tid] = s; qs[tid] = q;
    __syncthreads();
    for (int st = 64; st > 0; st >>= 1) {
        if (tid < st) { ss[tid] += ss[tid+st]; qs[tid] += qs[tid+st]; }
        __syncthreads();
    }
    if (tid == 0) {
        float mean = ss[0] * (1.0f/NP);
        float var  = qs[0] * (1.0f/NP) - mean*mean;
        float rstd = rsqrtf(var + 1e-5f);
        float sc = g[c] * rstd;
        g_scale2[c] = sc;
        g_shift2[c] = be[c] - mean * sc;
    }
}
__global__ __launch_bounds__(256) void k_final_v2(const float* __restrict__ x, float* __restrict__ out) {
    int i4 = blockIdx.x * 256 + threadIdx.x;
    int i = i4 << 2;
    int b = i >> 21;
    int c = (i >> 14) & 127;
    int hw = i & 16383;
    float sc = g_scale2[c], sh = g_shift2[c];
    float4 v = *(const float4*)(g_c2 + (size_t)c*NP + (b<<14) + hw);
    float4 xv = *(const float4*)(x + i);
    float4 o;
    o.x = gelu_exact(xv.x + v.x*sc + sh);
    o.y = gelu_exact(xv.y + v.y*sc + sh);
    o.z = gelu_exact(xv.z + v.z*sc + sh);
    o.w = gelu_exact(xv.w + v.w*sc + sh);
    *(float4*)(out + i) = o;
}

// ================================ launch ================================
extern "C" void kernel_launch(void* const* d_in, const int* in_sizes, int n_in,
                              void* d_out, int out_size) {
    const float* x        = (const float*)d_in[0];
    const float* offset_w = (const float*)d_in[1];
    const float* offset_b = (const float*)d_in[2];
    const float* deform_w = (const float*)d_in[3];
    const float* dw_w     = (const float*)d_in[4];
    const float* dw_b     = (const float*)d_in[5];
    const float* dw2_w    = (const float*)d_in[6];
    const float* dw2_b    = (const float*)d_in[7];
    const float* bn1_g    = (const float*)d_in[8];
    const float* bn1_b    = (const float*)d_in[9];
    const float* w1       = (const float*)d_in[10];
    const float* b1       = (const float*)d_in[11];
    const float* w2       = (const float*)d_in[12];
    const float* b2       = (const float*)d_in[13];
    const float* bn2_g    = (const float*)d_in[14];
    const float* bn2_b    = (const float*)d_in[15];
    float* out = (float*)d_out;

    static int inited = 0;
    static cudaStream_t sA, sB, sC;
    static cudaEvent_t e0, eA, eB, eC, eBC;
    if (!inited) {
        cudaFuncSetAttribute(k_gemm1, cudaFuncAttributeMaxDynamicSharedMemorySize, G1SMEM);
        cudaFuncSetAttribute(k_gemm2, cudaFuncAttributeMaxDynamicSharedMemorySize, G2SMEM);
        cudaFuncSetAttribute(k_conv_h<18,1,0,0>, cudaFuncAttributeMaxDynamicSharedMemorySize, CONV_SMEM);
        cudaFuncSetAttribute(k_conv_h<32,2,96,1>, cudaFuncAttributeMaxDynamicSharedMemorySize, CONV_SMEM);
        cudaStreamCreateWithFlags(&sA, cudaStreamNonBlocking);
        cudaStreamCreateWithFlags(&sB, cudaStreamNonBlocking);
        cudaStreamCreateWithFlags(&sC, cudaStreamNonBlocking);
        cudaEventCreateWithFlags(&e0, cudaEventDisableTiming);
        cudaEventCreateWithFlags(&eA, cudaEventDisableTiming);
        cudaEventCreateWithFlags(&eB, cudaEventDisableTiming);
        cudaEventCreateWithFlags(&eC, cudaEventDisableTiming);
        cudaEventCreateWithFlags(&eBC, cudaEventDisableTiming);
        inited = 1;
    }

    float* goffp; cudaGetSymbolAddress((void**)&goffp, g_off);
    float* gyp;   cudaGetSymbolAddress((void**)&gyp, g_y);

    dim3 blk256(256);
    cudaEventRecord(e0, 0);
    cudaStreamWaitEvent(sA, e0, 0);
    k_conv_h<18,1,0,0> <<<dim3(128, BATCH), blk256, CONV_SMEM, sA>>>(x, offset_w, offset_b, goffp);
    k_deform_v3        <<<dim3(64, 4, BATCH), blk256, 0, sA>>>(x, deform_w);
    cudaStreamWaitEvent(sB, e0, 0);
    k_conv_h<32,2,96,1><<<dim3(128, BATCH), blk256, CONV_SMEM, sB>>>(x, dw2_w, dw2_b, gyp);
    cudaEventRecord(eB, sB);
    cudaStreamWaitEvent(sC, e0, 0);
    k_dw7_v3           <<<dim3(16, GC2, BATCH), blk256, 0, sC>>>(x, dw_w, dw_b);
    cudaEventRecord(eC, sC);

    cudaStreamWaitEvent(sB, eC, 0);
    k_bn1_part<1><<<BATCH*96, blk256, 0, sB>>>();
    cudaEventRecord(eBC, sB);
    k_bn1_part<0><<<BATCH*32, blk256, 0, sA>>>();
    cudaEventRecord(eA, sA);

    cudaStreamWaitEvent(0, eA, 0);
    cudaStreamWaitEvent(0, eBC, 0);
    cudaStreamWaitEvent(0, eB, 0);

    k_bn1_fold<<<1, 512>>>(bn1_g, bn1_b, w1, b1);

    k_gemm1<<<NP/128, 256, G1SMEM>>>(w1);
    k_gemm2<<<NP/128, 256, G2SMEM>>>(w2, b2);

    k_bn2_final<<<DIM, 128>>>(bn2_g, bn2_b);
    k_final_v2<<<(size_t)NP*DIM/1024, blk256>>>(x, out);
}

// round 16
// speedup vs baseline: 1.7623x; 1.0213x over previous
#include <cuda_runtime.h>
#include <cuda_bf16.h>
#include <cuda_fp16.h>
#include <math.h>
#include <stdint.h>

#define BATCH 4
#define DIM 128
#define HH 128
#define WW 128
#define HW (HH*WW)           // 16384
#define NP (BATCH*HW)        // 65536
#define HID 512
#define GC1 32
#define GC2 64
#define GC3 32

// ---------------- scratch ----------------
__device__ float g_off[BATCH*18*HW];
__device__ float g_y[BATCH*DIM*HW];            // shuffled concat, NCHW
__device__ uint32_t g_t2[(size_t)(HID/2)*NP];  // GEMM1 out, half2 packed by n-pairs
__device__ float g_c2[(size_t)DIM*NP];         // GEMM2 out, TRANSPOSED [DIM][NP]
__device__ uint32_t g_w1h[(DIM/2)*HID];        // w1 packed half2 along k-pairs: [64][512]
__device__ uint32_t g_w2h[(HID/2)*DIM];        // w2 packed half2 along k-pairs: [256][128]
__device__ float g_b1f[HID];
__device__ float g_bn1_sum[BATCH*DIM];
__device__ float g_bn1_sq [BATCH*DIM];
__device__ float g_scale1[DIM], g_shift1[DIM];
__device__ float g_bn2_sum[512*DIM];
__device__ float g_bn2_sq [512*DIM];
__device__ float g_scale2[DIM], g_shift2[DIM];

__device__ __forceinline__ float gelu_exact(float v) {
    return 0.5f * v * (1.0f + erff(v * 0.70710678118654752440f));
}
__device__ __forceinline__ void mma_f16(float* c, const uint32_t* a, const uint32_t* b) {
    asm volatile("mma.sync.aligned.m16n8k16.row.col.f32.f16.f16.f32 "
        "{%0,%1,%2,%3}, {%4,%5,%6,%7}, {%8,%9}, {%0,%1,%2,%3};"
        : "+f"(c[0]), "+f"(c[1]), "+f"(c[2]), "+f"(c[3])
        : "r"(a[0]), "r"(a[1]), "r"(a[2]), "r"(a[3]), "r"(b[0]), "r"(b[1]));
}
__device__ __forceinline__ uint32_t pack_h2(float lo, float hi) {
    __half2 h = __floats2half2_rn(lo, hi);
    return *reinterpret_cast<uint32_t*>(&h);
}

#define TSTR 130
#define AS2 68
#define BS2 20
#define G1SMEM ((128*AS2 + 128*BS2)*4 + 128*TSTR*4)   // 111616
#define G2SMEM (128*TSTR*4)                           // 66560

// ======================= fp16 implicit-GEMM conv =======================
#define CAS 52
#define CBS 148
#define CONV_SMEM ((136*CAS + 32*CBS)*4)   // 47232

template<int NOC, int D, int CBASE, int MODE>
__global__ __launch_bounds__(256) void k_conv_h(const float* __restrict__ x,
                                                const float* __restrict__ w,
                                                const float* __restrict__ bias,
                                                float* __restrict__ outp) {
    extern __shared__ uint32_t cs[];
    uint32_t* Af = cs;               // [136][CAS]
    uint32_t* Bf = cs + 136*CAS;     // [32][CBS]
    int tid = threadIdx.x;
    int lane = tid & 31, wid = tid >> 5;
    int g = lane >> 2, t = lane & 3;
    int warp_m = wid >> 1, warp_n = wid & 1;
    int y = blockIdx.x, b = blockIdx.y;

    for (int i = tid; i < 48*136; i += 256) {
        int k2 = i / 136, mp = i - k2*136;
        int ky = k2 >> 4, ic2 = k2 & 15;
        int ry = y + (ky - 1)*D;
        int gx = mp - D;
        float v0 = 0.f, v1 = 0.f;
        if (ry >= 0 && ry < 128 && gx >= 0 && gx < 128) {
            size_t base = (((size_t)b*DIM + CBASE + 2*ic2) << 14) + (ry << 7) + gx;
            v0 = x[base];
            v1 = x[base + HW];
        }
        Af[mp*CAS + k2] = pack_h2(v0, v1);
    }
    for (int i = tid; i < 144*32; i += 256) {
        int k2g = i >> 5, oc = i & 31;
        int tap = k2g / 16, ic2 = k2g & 15;
        float v0 = 0.f, v1 = 0.f;
        if (oc < NOC) {
            v0 = w[(oc*32 + 2*ic2    )*9 + tap];
            v1 = w[(oc*32 + 2*ic2 + 1)*9 + tap];
        }
        Bf[oc*CBS + k2g] = pack_h2(v0, v1);
    }
    __syncthreads();

    float acc[2][2][4] = {};
    int mbase = warp_m*32 + g;
    int nbase = warp_n*16 + g;
    #pragma unroll
    for (int tap = 0; tap < 9; tap++) {
        const int ky = tap / 3, kx = tap % 3;
        #pragma unroll
        for (int kst = 0; kst < 2; kst++) {
            int aB = ky*16 + kst*8;
            int bB = tap*16 + kst*8;
            uint32_t a[2][4], bb[2][2];
            #pragma unroll
            for (int mi = 0; mi < 2; mi++) {
                int col = mbase + mi*16 + kx*D;
                a[mi][0] = Af[col*CAS + aB + t];
                a[mi][1] = Af[(col+8)*CAS + aB + t];
                a[mi][2] = Af[col*CAS + aB + t + 4];
                a[mi][3] = Af[(col+8)*CAS + aB + t + 4];
            }
            #pragma unroll
            for (int nt = 0; nt < 2; nt++) {
                int n = nbase + nt*8;
                bb[nt][0] = Bf[n*CBS + bB + t];
                bb[nt][1] = Bf[n*CBS + bB + t + 4];
            }
            #pragma unroll
            for (int mi = 0; mi < 2; mi++)
                #pragma unroll
                for (int nt = 0; nt < 2; nt++)
                    mma_f16(acc[mi][nt], a[mi], bb[nt]);
        }
    }
    #pragma unroll
    for (int mi = 0; mi < 2; mi++) {
        #pragma unroll
        for (int nt = 0; nt < 2; nt++) {
            int col = warp_n*16 + nt*8 + 2*t;
            #pragma unroll
            for (int cc = 0; cc < 2; cc++) {
                int oc = col + cc;
                if (oc >= NOC) continue;
                float bv = bias[oc];
                int px0 = warp_m*32 + mi*16 + g;
                size_t base;
                if (MODE == 0) base = (((size_t)b*18 + oc) << 14) + (y << 7);
                else           base = (((size_t)b*DIM + 65 + 2*oc) << 14) + (y << 7);
                outp[base + px0]     = acc[mi][nt][cc]     + bv;
                outp[base + px0 + 8] = acc[mi][nt][cc + 2] + bv;
            }
        }
    }
}

// ======================= other conv kernels =======================

#define DSTR 39
__global__ __launch_bounds__(256) void k_dw7_v3(const float* __restrict__ x,
                                                const float* __restrict__ dww,
                                                const float* __restrict__ dwb) {
    __shared__ float s[38*DSTR];
    __shared__ float w[49];
    int tid = threadIdx.x;
    int b = blockIdx.z;
    int c = blockIdx.y;
    int ty0 = (blockIdx.x >> 2) * 32, tx0 = (blockIdx.x & 3) * 32;
    const float* xp = x + ((size_t)b*DIM + 32 + c)*HW;
    #pragma unroll 6
    for (int i = tid; i < 38*38; i += 256) {
        int sy = i / 38, sx = i - sy*38;
        int gy = ty0 + sy - 3, gx = tx0 + sx - 3;
        float v = 0.f;
        if (gy >= 0 && gy < 128 && gx >= 0 && gx < 128) v = xp[gy*WW + gx];
        s[sy*DSTR + sx] = v;
    }
    if (tid < 49) w[tid] = dww[c*49 + tid];
    __syncthreads();
    int txg = (tid & 7) * 4, ty = tid >> 3;
    float a0 = 0.f, a1 = 0.f, a2 = 0.f, a3 = 0.f;
    #pragma unroll
    for (int ky = 0; ky < 7; ky++) {
        const float* sp = s + (ty + ky)*DSTR + txg;
        float r[10];
        #pragma unroll
        for (int j = 0; j < 10; j++) r[j] = sp[j];
        #pragma unroll
        for (int kx = 0; kx < 7; kx++) {
            float wv = w[ky*7 + kx];
            a0 += r[kx]*wv; a1 += r[kx+1]*wv; a2 += r[kx+2]*wv; a3 += r[kx+3]*wv;
        }
    }
    float bias = dwb[c];
    int oldc = 32 + c;
    int newc = (oldc < 64) ? (2*oldc) : (2*(oldc-64)+1);
    float4 o; o.x = a0+bias; o.y = a1+bias; o.z = a2+bias; o.w = a3+bias;
    *(float4*)(g_y + ((size_t)b*DIM + newc)*HW + (ty0+ty)*WW + tx0+txg) = o;
}

__global__ __launch_bounds__(256) void k_deform_v3(const float* __restrict__ x,
                                                   const float* __restrict__ dfw) {
    __shared__ float wk[8][9];
    int tid = threadIdx.x;
    int b = blockIdx.z;
    int c0 = blockIdx.y * 8;
    int hw = blockIdx.x * 256 + tid;
    if (tid < 72) wk[tid/9][tid%9] = dfw[(c0 + tid/9)*9 + tid%9];
    __syncthreads();
    int h = hw >> 7, wc = hw & 127;
    const float* offb = g_off + (size_t)b*18*HW + hw;
    const float* xb = x + (((size_t)b*DIM + c0) << 14);
    float acc[8] = {};
    #pragma unroll
    for (int k = 0; k < 9; k++) {
        float dy = offb[(2*k  )*HW];
        float dx = offb[(2*k+1)*HW];
        float ys = (float)h - 1.0f + (float)(k/3) + dy;
        float xs = (float)wc - 1.0f + (float)(k%3) + dx;
        float y0 = floorf(ys), x0 = floorf(xs);
        float fy = ys - y0, fx = xs - x0;
        float vy0 = (y0 >= 0.f && y0 <= 127.f) ? 1.f : 0.f;
        float vy1 = (y0 >= -1.f && y0 <= 126.f) ? 1.f : 0.f;
        float vx0 = (x0 >= 0.f && x0 <= 127.f) ? 1.f : 0.f;
        float vx1 = (x0 >= -1.f && x0 <= 126.f) ? 1.f : 0.f;
        float w00 = (1.f-fy)*(1.f-fx) * vy0*vx0;
        float w01 = (1.f-fy)*fx       * vy0*vx1;
        float w10 = fy*(1.f-fx)       * vy1*vx0;
        float w11 = fy*fx             * vy1*vx1;
        int yi0 = min(max((int)y0, 0), 127);
        int yi1 = min(max((int)y0 + 1, 0), 127);
        int xi0 = min(max((int)x0, 0), 127);
        int xi1 = min(max((int)x0 + 1, 0), 127);
        int i00 = yi0*128 + xi0;
        int i01 = yi0*128 + xi1;
        int i10 = yi1*128 + xi0;
        int i11 = yi1*128 + xi1;
        #pragma unroll
        for (int cl = 0; cl < 8; cl++) {
            const float* xp = xb + (cl << 14);
            float sv = w00*xp[i00] + w01*xp[i01] + w10*xp[i10] + w11*xp[i11];
            acc[cl] += sv * wk[cl][k];
        }
    }
    #pragma unroll
    for (int cl = 0; cl < 8; cl++)
        g_y[(((size_t)b*DIM + 2*(c0+cl)) << 14) + hw] = acc[cl];
}

// ======================= weight pre-pack (independent of BN; overlapped) ========
__global__ __launch_bounds__(256) void k_pack_w(const float* __restrict__ w1,
                                                const float* __restrict__ w2) {
    int i = blockIdx.x * 256 + threadIdx.x;     // grid 256: 65536 threads
    if (i < 32768) {
        int k2 = i >> 9, n = i & 511;
        g_w1h[i] = pack_h2(w1[(size_t)(2*k2)*HID + n], w1[(size_t)(2*k2+1)*HID + n]);
    } else {
        int j = i - 32768;
        int k2 = j >> 7, n = j & 127;
        g_w2h[j] = pack_h2(w2[(size_t)(2*k2)*DIM + n], w2[(size_t)(2*k2+1)*DIM + n]);
    }
}

// ======================= BN1 (split by producer) =======================
template<int MODE>
__global__ __launch_bounds__(256) void k_bn1_part(void) {
    int nch = (MODE == 0) ? 32 : 96;
    int b = blockIdx.x / nch;
    int j = blockIdx.x % nch;
    int c;
    if (MODE == 0) c = 2*j;
    else           c = (j < 64) ? (2*j + 1) : (64 + 2*(j - 64));
    const float4* p = (const float4*)(g_y + (((size_t)b*DIM + c) << 14));
    float s = 0.f, q = 0.f;
    for (int i = threadIdx.x; i < HW/4; i += 256) {
        float4 v = p[i];
        s += v.x + v.y + v.z + v.w;
        q += v.x*v.x + v.y*v.y + v.z*v.z + v.w*v.w;
    }
    __shared__ float ss[256], qs[256];
    ss[threadIdx.x] = s; qs[threadIdx.x] = q;
    __syncthreads();
    for (int st = 128; st > 0; st >>= 1) {
        if (threadIdx.x < st) { ss[threadIdx.x] += ss[threadIdx.x+st]; qs[threadIdx.x] += qs[threadIdx.x+st]; }
        __syncthreads();
    }
    if (threadIdx.x == 0) { g_bn1_sum[b*DIM + c] = ss[0]; g_bn1_sq[b*DIM + c] = qs[0]; }
}

__global__ __launch_bounds__(512) void k_bn1_fold(const float* __restrict__ g,
                                                  const float* __restrict__ be,
                                                  const float* __restrict__ w1,
                                                  const float* __restrict__ b1) {
    __shared__ float sh_shift[DIM];
    int tid = threadIdx.x;
    if (tid < DIM) {
        float s = 0.f, q = 0.f;
        #pragma unroll
        for (int b = 0; b < BATCH; b++) { s += g_bn1_sum[b*DIM + tid]; q += g_bn1_sq[b*DIM + tid]; }
        float mean = s * (1.0f/NP);
        float var  = q * (1.0f/NP) - mean*mean;
        float rstd = rsqrtf(var + 1e-5f);
        float sc = g[tid] * rstd;
        float sh = be[tid] - mean * sc;
        g_scale1[tid] = sc;
        g_shift1[tid] = sh;
        sh_shift[tid] = sh;
    }
    __syncthreads();
    float bf = b1[tid];
    for (int k = 0; k < DIM; k++)
        bf += sh_shift[k] * w1[k*HID + tid];
    g_b1f[tid] = bf;
}

// ======================= fp16 mma GEMMs =======================
// GEMM1: persistent A; B from pre-packed g_w1h.
__global__ __launch_bounds__(256) void k_gemm1() {
    extern __shared__ uint32_t sm4[];
    uint32_t* Af = sm4;
    uint32_t* Bc = sm4 + 128*AS2;
    float* ts = (float*)(sm4 + 128*AS2 + 128*BS2);
    int tid = threadIdx.x;
    int lane = tid & 31, wid = tid >> 5;
    int g = lane >> 2, t = lane & 3;
    int warp_m = wid >> 2, warp_n = wid & 3;
    int p0 = blockIdx.x * 128;
    int cb = (p0 >> 14) * DIM;
    int hw0 = p0 & (HW-1);

    #pragma unroll
    for (int l = 0; l < 32; l++) {
        int i = tid + l*256;
        int px = i & 127, k2 = i >> 7;
        float v0 = g_y[(size_t)(cb + 2*k2    )*HW + hw0 + px] * g_scale1[2*k2];
        float v1 = g_y[(size_t)(cb + 2*k2 + 1)*HW + hw0 + px] * g_scale1[2*k2 + 1];
        Af[px*AS2 + k2] = pack_h2(v0, v1);
    }

    for (int nt = 0; nt < 4; nt++) {
        int n0 = nt * 128;
        float acc[4][4][4] = {};
        for (int kc = 0; kc < 4; kc++) {
            __syncthreads();
            int kt2 = kc*16;
            #pragma unroll
            for (int l = 0; l < 8; l++) {
                int i = tid + l*256;
                int n = i & 127, k2 = i >> 7;
                Bc[n*BS2 + k2] = g_w1h[(size_t)(kt2 + k2)*HID + n0 + n];
            }
            __syncthreads();
            #pragma unroll
            for (int kst = 0; kst < 2; kst++) {
                int k2A = kc*16 + kst*8;
                int k2B = kst*8;
                uint32_t a[4][4], b[4][2];
                #pragma unroll
                for (int mi = 0; mi < 4; mi++) {
                    int row = warp_m*64 + mi*16 + g;
                    a[mi][0] = Af[row*AS2 + k2A + t];
                    a[mi][1] = Af[(row+8)*AS2 + k2A + t];
                    a[mi][2] = Af[row*AS2 + k2A + t + 4];
                    a[mi][3] = Af[(row+8)*AS2 + k2A + t + 4];
                }
                #pragma unroll
                for (int nf = 0; nf < 4; nf++) {
                    int col = warp_n*32 + nf*8 + g;
                    b[nf][0] = Bc[col*BS2 + k2B + t];
                    b[nf][1] = Bc[col*BS2 + k2B + t + 4];
                }
                #pragma unroll
                for (int mi = 0; mi < 4; mi++)
                    #pragma unroll
                    for (int nf = 0; nf < 4; nf++)
                        mma_f16(acc[mi][nf], a[mi], b[nf]);
            }
        }
        #pragma unroll
        for (int mi = 0; mi < 4; mi++) {
            int row = warp_m*64 + mi*16 + g;
            #pragma unroll
            for (int nf = 0; nf < 4; nf++) {
                int col = warp_n*32 + nf*8 + 2*t;
                float b0v = g_b1f[n0 + col], b1v = g_b1f[n0 + col + 1];
                ts[row*TSTR + col]       = gelu_exact(acc[mi][nf][0] + b0v);
                ts[row*TSTR + col + 1]   = gelu_exact(acc[mi][nf][1] + b1v);
                ts[(row+8)*TSTR + col]   = gelu_exact(acc[mi][nf][2] + b0v);
                ts[(row+8)*TSTR + col+1] = gelu_exact(acc[mi][nf][3] + b1v);
            }
        }
        __syncthreads();
        #pragma unroll
        for (int l = 0; l < 32; l++) {
            int i = tid + l*256;
            int n2 = i >> 7, p = i & 127;
            uint32_t h = pack_h2(ts[p*TSTR + 2*n2], ts[p*TSTR + 2*n2 + 1]);
            g_t2[(size_t)((n0 >> 1) + n2)*NP + p0 + p] = h;
        }
    }
}

// GEMM2 + fused BN2 partials; B from pre-packed g_w2h.
__global__ __launch_bounds__(256) void k_gemm2(const float* __restrict__ b2) {
    extern __shared__ uint32_t sm4[];
    uint32_t* Ac = sm4;
    uint32_t* Bc = sm4 + 128*BS2;
    float* ts = (float*)sm4;
    __shared__ float rs[256], rq[256];
    int tid = threadIdx.x;
    int lane = tid & 31, wid = tid >> 5;
    int g = lane >> 2, t = lane & 3;
    int warp_m = wid >> 2, warp_n = wid & 3;
    int p0 = blockIdx.x * 128;

    #pragma unroll
    for (int l = 0; l < 8; l++) {
        int i = tid + l*256;
        int px = i & 127, k2 = i >> 7;
        Ac[px*BS2 + k2] = g_t2[(size_t)k2*NP + p0 + px];
    }
    #pragma unroll
    for (int l = 0; l < 8; l++) {
        int i = tid + l*256;
        int n = i & 127, k2 = i >> 7;
        Bc[n*BS2 + k2] = g_w2h[(size_t)k2*DIM + n];
    }
    __syncthreads();

    float acc[4][4][4] = {};
    for (int kc = 0; kc < 16; kc++) {
        uint32_t pa[8], pb[8];
        if (kc < 15) {
            int kt2 = (kc+1)*16;
            #pragma unroll
            for (int l = 0; l < 8; l++) {
                int i = tid + l*256;
                int px = i & 127, k2 = i >> 7;
                pa[l] = g_t2[(size_t)(kt2 + k2)*NP + p0 + px];
                pb[l] = g_w2h[(size_t)(kt2 + k2)*DIM + px];
            }
        }
        #pragma unroll
        for (int kst = 0; kst < 2; kst++) {
            int k2b = kst*8;
            uint32_t a[4][4], b[4][2];
            #pragma unroll
            for (int mi = 0; mi < 4; mi++) {
                int row = warp_m*64 + mi*16 + g;
                a[mi][0] = Ac[row*BS2 + k2b + t];
                a[mi][1] = Ac[(row+8)*BS2 + k2b + t];
                a[mi][2] = Ac[row*BS2 + k2b + t + 4];
                a[mi][3] = Ac[(row+8)*BS2 + k2b + t + 4];
            }
            #pragma unroll
            for (int nf = 0; nf < 4; nf++) {
                int col = warp_n*32 + nf*8 + g;
                b[nf][0] = Bc[col*BS2 + k2b + t];
                b[nf][1] = Bc[col*BS2 + k2b + t + 4];
            }
            #pragma unroll
            for (int mi = 0; mi < 4; mi++)
                #pragma unroll
                for (int nf = 0; nf < 4; nf++)
                    mma_f16(acc[mi][nf], a[mi], b[nf]);
        }
        __syncthreads();
        if (kc < 15) {
            #pragma unroll
            for (int l = 0; l < 8; l++) {
                int i = tid + l*256;
                int px = i & 127, k2 = i >> 7;
                Ac[px*BS2 + k2] = pa[l];
                Bc[px*BS2 + k2] = pb[l];
            }
            __syncthreads();
        }
    }
    #pragma unroll
    for (int mi = 0; mi < 4; mi++) {
        int row = warp_m*64 + mi*16 + g;
        #pragma unroll
        for (int nf = 0; nf < 4; nf++) {
            int col = warp_n*32 + nf*8 + 2*t;
            float b0v = b2[col], b1v = b2[col + 1];
            ts[row*TSTR + col]       = acc[mi][nf][0] + b0v;
            ts[row*TSTR + col + 1]   = acc[mi][nf][1] + b1v;
            ts[(row+8)*TSTR + col]   = acc[mi][nf][2] + b0v;
            ts[(row+8)*TSTR + col+1] = acc[mi][nf][3] + b1v;
        }
    }
    __syncthreads();
    #pragma unroll
    for (int l = 0; l < 64; l++) {
        int i = tid + l*256;
        int n = i >> 7, p = i & 127;
        g_c2[(size_t)n*NP + p0 + p] = ts[p*TSTR + n];
    }
    {
        int n = tid & 127;
        int ph = tid >> 7;
        float s = 0.f, q = 0.f;
        for (int p = ph; p < 128; p += 2) {
            float v = ts[p*TSTR + n];
            s += v; q += v*v;
        }
        rs[tid] = s; rq[tid] = q;
        __syncthreads();
        if (tid < 128) {
            g_bn2_sum[blockIdx.x*128 + tid] = rs[tid] + rs[tid+128];
            g_bn2_sq [blockIdx.x*128 + tid] = rq[tid] + rq[tid+128];
        }
    }
}

// ======================= BN2 final + output =======================
__global__ void k_bn2_final(const float* __restrict__ g, const float* __restrict__ be) {
    int c = blockIdx.x;
    int tid = threadIdx.x;
    __shared__ float ss[128], qs[128];
    float s = 0.f, q = 0.f;
    for (int i = tid; i < 512; i += 128) {
        s += g_bn2_sum[i*128 + c];
        q += g_bn2_sq [i*128 + c];
    }
    ss[tid] = s; qs[tid] = q;
    __syncthreads();
    for (int st = 64; st > 0; st >>= 1) {
        if (tid < st) { ss[tid] += ss[tid+st]; qs[tid] += qs[tid+st]; }
        __syncthreads();
    }
    if (tid == 0) {
        float mean = ss[0] * (1.0f/NP);
        float var  = qs[0] * (1.0f/NP) - mean*mean;
        float rstd = rsqrtf(var + 1e-5f);
        float sc = g[c] * rstd;
        g_scale2[c] = sc;
        g_shift2[c] = be[c] - mean * sc;
    }
}
__global__ __launch_bounds__(256) void k_final_v2(const float* __restrict__ x, float* __restrict__ out) {
    int i4 = blockIdx.x * 256 + threadIdx.x;
    int i = i4 << 2;
    int b = i >> 21;
    int c = (i >> 14) & 127;
    int hw = i & 16383;
    float sc = g_scale2[c], sh = g_shift2[c];
    float4 v = *(const float4*)(g_c2 + (size_t)c*NP + (b<<14) + hw);
    float4 xv = *(const float4*)(x + i);
    float4 o;
    o.x = gelu_exact(xv.x + v.x*sc + sh);
    o.y = gelu_exact(xv.y + v.y*sc + sh);
    o.z = gelu_exact(xv.z + v.z*sc + sh);
    o.w = gelu_exact(xv.w + v.w*sc + sh);
    *(float4*)(out + i) = o;
}

// ================================ launch ================================
extern "C" void kernel_launch(void* const* d_in, const int* in_sizes, int n_in,
                              void* d_out, int out_size) {
    const float* x        = (const float*)d_in[0];
    const float* offset_w = (const float*)d_in[1];
    const float* offset_b = (const float*)d_in[2];
    const float* deform_w = (const float*)d_in[3];
    const float* dw_w     = (const float*)d_in[4];
    const float* dw_b     = (const float*)d_in[5];
    const float* dw2_w    = (const float*)d_in[6];
    const float* dw2_b    = (const float*)d_in[7];
    const float* bn1_g    = (const float*)d_in[8];
    const float* bn1_b    = (const float*)d_in[9];
    const float* w1       = (const float*)d_in[10];
    const float* b1       = (const float*)d_in[11];
    const float* w2       = (const float*)d_in[12];
    const float* b2       = (const float*)d_in[13];
    const float* bn2_g    = (const float*)d_in[14];
    const float* bn2_b    = (const float*)d_in[15];
    float* out = (float*)d_out;

    static int inited = 0;
    static cudaStream_t sA, sB, sC;
    static cudaEvent_t e0, eA, eB, eC, eBC;
    if (!inited) {
        cudaFuncSetAttribute(k_gemm1, cudaFuncAttributeMaxDynamicSharedMemorySize, G1SMEM);
        cudaFuncSetAttribute(k_gemm2, cudaFuncAttributeMaxDynamicSharedMemorySize, G2SMEM);
        cudaFuncSetAttribute(k_conv_h<18,1,0,0>, cudaFuncAttributeMaxDynamicSharedMemorySize, CONV_SMEM);
        cudaFuncSetAttribute(k_conv_h<32,2,96,1>, cudaFuncAttributeMaxDynamicSharedMemorySize, CONV_SMEM);
        cudaStreamCreateWithFlags(&sA, cudaStreamNonBlocking);
        cudaStreamCreateWithFlags(&sB, cudaStreamNonBlocking);
        cudaStreamCreateWithFlags(&sC, cudaStreamNonBlocking);
        cudaEventCreateWithFlags(&e0, cudaEventDisableTiming);
        cudaEventCreateWithFlags(&eA, cudaEventDisableTiming);
        cudaEventCreateWithFlags(&eB, cudaEventDisableTiming);
        cudaEventCreateWithFlags(&eC, cudaEventDisableTiming);
        cudaEventCreateWithFlags(&eBC, cudaEventDisableTiming);
        inited = 1;
    }

    float* goffp; cudaGetSymbolAddress((void**)&goffp, g_off);
    float* gyp;   cudaGetSymbolAddress((void**)&gyp, g_y);

    dim3 blk256(256);
    cudaEventRecord(e0, 0);
    // branch A: offset conv -> deform
    cudaStreamWaitEvent(sA, e0, 0);
    k_conv_h<18,1,0,0> <<<dim3(128, BATCH), blk256, CONV_SMEM, sA>>>(x, offset_w, offset_b, goffp);
    k_deform_v3        <<<dim3(64, 4, BATCH), blk256, 0, sA>>>(x, deform_w);
    // branch B: weight pack (hidden) then dilated conv
    cudaStreamWaitEvent(sB, e0, 0);
    k_pack_w<<<256, blk256, 0, sB>>>(w1, w2);
    k_conv_h<32,2,96,1><<<dim3(128, BATCH), blk256, CONV_SMEM, sB>>>(x, dw2_w, dw2_b, gyp);
    cudaEventRecord(eB, sB);
    // branch C: dw7
    cudaStreamWaitEvent(sC, e0, 0);
    k_dw7_v3           <<<dim3(16, GC2, BATCH), blk256, 0, sC>>>(x, dw_w, dw_b);
    cudaEventRecord(eC, sC);

    cudaStreamWaitEvent(sB, eC, 0);
    k_bn1_part<1><<<BATCH*96, blk256, 0, sB>>>();
    cudaEventRecord(eBC, sB);
    k_bn1_part<0><<<BATCH*32, blk256, 0, sA>>>();
    cudaEventRecord(eA, sA);

    cudaStreamWaitEvent(0, eA, 0);
    cudaStreamWaitEvent(0, eBC, 0);
    cudaStreamWaitEvent(0, eB, 0);

    k_bn1_fold<<<1, 512>>>(bn1_g, bn1_b, w1, b1);

    k_gemm1<<<NP/128, 256, G1SMEM>>>();
    k_gemm2<<<NP/128, 256, G2SMEM>>>(b2);

    k_bn2_final<<<DIM, 128>>>(bn2_g, bn2_b);
    k_final_v2<<<(size_t)NP*DIM/1024, blk256>>>(x, out);
}

// round 17
// speedup vs baseline: 1.8178x; 1.0315x over previous
#include <cuda_runtime.h>
#include <cuda_bf16.h>
#include <cuda_fp16.h>
#include <math.h>
#include <stdint.h>

#define BATCH 4
#define DIM 128
#define HH 128
#define WW 128
#define HW (HH*WW)           // 16384
#define NP (BATCH*HW)        // 65536
#define HID 512
#define GC1 32
#define GC2 64
#define GC3 32

// ---------------- scratch ----------------
__device__ float g_off[BATCH*18*HW];
__device__ float g_y[BATCH*DIM*HW];            // shuffled concat, NCHW
__device__ uint32_t g_t2[(size_t)(HID/2)*NP];  // GEMM1 out, half2 packed by n-pairs
__device__ float g_c2[(size_t)DIM*NP];         // GEMM2 out, TRANSPOSED [DIM][NP]
__device__ uint32_t g_w1h[(DIM/2)*HID];        // w1 packed half2 along k-pairs: [64][512]
__device__ uint32_t g_w2h[(HID/2)*DIM];        // w2 packed half2 along k-pairs: [256][128]
__device__ float g_b1f[HID];
__device__ float g_bn1_sum[BATCH*DIM];
__device__ float g_bn1_sq [BATCH*DIM];
__device__ float g_scale1[DIM], g_shift1[DIM];
__device__ float g_bn2_sum[512*DIM];
__device__ float g_bn2_sq [512*DIM];
__device__ float g_scale2[DIM], g_shift2[DIM];

__device__ __forceinline__ float gelu_exact(float v) {
    return 0.5f * v * (1.0f + erff(v * 0.70710678118654752440f));
}
__device__ __forceinline__ void mma_f16(float* c, const uint32_t* a, const uint32_t* b) {
    asm volatile("mma.sync.aligned.m16n8k16.row.col.f32.f16.f16.f32 "
        "{%0,%1,%2,%3}, {%4,%5,%6,%7}, {%8,%9}, {%0,%1,%2,%3};"
        : "+f"(c[0]), "+f"(c[1]), "+f"(c[2]), "+f"(c[3])
        : "r"(a[0]), "r"(a[1]), "r"(a[2]), "r"(a[3]), "r"(b[0]), "r"(b[1]));
}
__device__ __forceinline__ uint32_t pack_h2(float lo, float hi) {
    __half2 h = __floats2half2_rn(lo, hi);
    return *reinterpret_cast<uint32_t*>(&h);
}

#define TSTR 130
#define AS2 68
#define BS2 20
#define G1SMEM ((128*AS2 + 128*BS2)*4 + 128*TSTR*4)   // 111616
#define G2SMEM (128*TSTR*4)                           // 66560

// ======================= fp16 implicit-GEMM conv =======================
#define CAS 52
#define CBS 148
#define CONV_SMEM ((136*CAS + 32*CBS)*4)   // 47232

template<int NOC, int D, int CBASE, int MODE>
__global__ __launch_bounds__(256) void k_conv_h(const float* __restrict__ x,
                                                const float* __restrict__ w,
                                                const float* __restrict__ bias,
                                                float* __restrict__ outp) {
    extern __shared__ uint32_t cs[];
    uint32_t* Af = cs;               // [136][CAS]
    uint32_t* Bf = cs + 136*CAS;     // [32][CBS]
    int tid = threadIdx.x;
    int lane = tid & 31, wid = tid >> 5;
    int g = lane >> 2, t = lane & 3;
    int warp_m = wid >> 1, warp_n = wid & 1;
    int y = blockIdx.x, b = blockIdx.y;

    for (int i = tid; i < 48*136; i += 256) {
        int k2 = i / 136, mp = i - k2*136;
        int ky = k2 >> 4, ic2 = k2 & 15;
        int ry = y + (ky - 1)*D;
        int gx = mp - D;
        float v0 = 0.f, v1 = 0.f;
        if (ry >= 0 && ry < 128 && gx >= 0 && gx < 128) {
            size_t base = (((size_t)b*DIM + CBASE + 2*ic2) << 14) + (ry << 7) + gx;
            v0 = x[base];
            v1 = x[base + HW];
        }
        Af[mp*CAS + k2] = pack_h2(v0, v1);
    }
    for (int i = tid; i < 144*32; i += 256) {
        int k2g = i >> 5, oc = i & 31;
        int tap = k2g / 16, ic2 = k2g & 15;
        float v0 = 0.f, v1 = 0.f;
        if (oc < NOC) {
            v0 = w[(oc*32 + 2*ic2    )*9 + tap];
            v1 = w[(oc*32 + 2*ic2 + 1)*9 + tap];
        }
        Bf[oc*CBS + k2g] = pack_h2(v0, v1);
    }
    __syncthreads();

    float acc[2][2][4] = {};
    int mbase = warp_m*32 + g;
    int nbase = warp_n*16 + g;
    #pragma unroll
    for (int tap = 0; tap < 9; tap++) {
        const int ky = tap / 3, kx = tap % 3;
        #pragma unroll
        for (int kst = 0; kst < 2; kst++) {
            int aB = ky*16 + kst*8;
            int bB = tap*16 + kst*8;
            uint32_t a[2][4], bb[2][2];
            #pragma unroll
            for (int mi = 0; mi < 2; mi++) {
                int col = mbase + mi*16 + kx*D;
                a[mi][0] = Af[col*CAS + aB + t];
                a[mi][1] = Af[(col+8)*CAS + aB + t];
                a[mi][2] = Af[col*CAS + aB + t + 4];
                a[mi][3] = Af[(col+8)*CAS + aB + t + 4];
            }
            #pragma unroll
            for (int nt = 0; nt < 2; nt++) {
                int n = nbase + nt*8;
                bb[nt][0] = Bf[n*CBS + bB + t];
                bb[nt][1] = Bf[n*CBS + bB + t + 4];
            }
            #pragma unroll
            for (int mi = 0; mi < 2; mi++)
                #pragma unroll
                for (int nt = 0; nt < 2; nt++)
                    mma_f16(acc[mi][nt], a[mi], bb[nt]);
        }
    }
    #pragma unroll
    for (int mi = 0; mi < 2; mi++) {
        #pragma unroll
        for (int nt = 0; nt < 2; nt++) {
            int col = warp_n*16 + nt*8 + 2*t;
            #pragma unroll
            for (int cc = 0; cc < 2; cc++) {
                int oc = col + cc;
                if (oc >= NOC) continue;
                float bv = bias[oc];
                int px0 = warp_m*32 + mi*16 + g;
                size_t base;
                if (MODE == 0) base = (((size_t)b*18 + oc) << 14) + (y << 7);
                else           base = (((size_t)b*DIM + 65 + 2*oc) << 14) + (y << 7);
                outp[base + px0]     = acc[mi][nt][cc]     + bv;
                outp[base + px0 + 8] = acc[mi][nt][cc + 2] + bv;
            }
        }
    }
}

// ======================= other conv kernels =======================

#define DSTR 39
__global__ __launch_bounds__(256) void k_dw7_v3(const float* __restrict__ x,
                                                const float* __restrict__ dww,
                                                const float* __restrict__ dwb) {
    __shared__ float s[38*DSTR];
    __shared__ float w[49];
    int tid = threadIdx.x;
    int b = blockIdx.z;
    int c = blockIdx.y;
    int ty0 = (blockIdx.x >> 2) * 32, tx0 = (blockIdx.x & 3) * 32;
    const float* xp = x + ((size_t)b*DIM + 32 + c)*HW;
    #pragma unroll 6
    for (int i = tid; i < 38*38; i += 256) {
        int sy = i / 38, sx = i - sy*38;
        int gy = ty0 + sy - 3, gx = tx0 + sx - 3;
        float v = 0.f;
        if (gy >= 0 && gy < 128 && gx >= 0 && gx < 128) v = xp[gy*WW + gx];
        s[sy*DSTR + sx] = v;
    }
    if (tid < 49) w[tid] = dww[c*49 + tid];
    __syncthreads();
    int txg = (tid & 7) * 4, ty = tid >> 3;
    float a0 = 0.f, a1 = 0.f, a2 = 0.f, a3 = 0.f;
    #pragma unroll
    for (int ky = 0; ky < 7; ky++) {
        const float* sp = s + (ty + ky)*DSTR + txg;
        float r[10];
        #pragma unroll
        for (int j = 0; j < 10; j++) r[j] = sp[j];
        #pragma unroll
        for (int kx = 0; kx < 7; kx++) {
            float wv = w[ky*7 + kx];
            a0 += r[kx]*wv; a1 += r[kx+1]*wv; a2 += r[kx+2]*wv; a3 += r[kx+3]*wv;
        }
    }
    float bias = dwb[c];
    int oldc = 32 + c;
    int newc = (oldc < 64) ? (2*oldc) : (2*(oldc-64)+1);
    float4 o; o.x = a0+bias; o.y = a1+bias; o.z = a2+bias; o.w = a3+bias;
    *(float4*)(g_y + ((size_t)b*DIM + newc)*HW + (ty0+ty)*WW + tx0+txg) = o;
}

__global__ __launch_bounds__(256) void k_deform_v3(const float* __restrict__ x,
                                                   const float* __restrict__ dfw) {
    __shared__ float wk[8][9];
    int tid = threadIdx.x;
    int b = blockIdx.z;
    int c0 = blockIdx.y * 8;
    int hw = blockIdx.x * 256 + tid;
    if (tid < 72) wk[tid/9][tid%9] = dfw[(c0 + tid/9)*9 + tid%9];
    __syncthreads();
    int h = hw >> 7, wc = hw & 127;
    const float* offb = g_off + (size_t)b*18*HW + hw;
    const float* xb = x + (((size_t)b*DIM + c0) << 14);
    float acc[8] = {};
    #pragma unroll
    for (int k = 0; k < 9; k++) {
        float dy = offb[(2*k  )*HW];
        float dx = offb[(2*k+1)*HW];
        float ys = (float)h - 1.0f + (float)(k/3) + dy;
        float xs = (float)wc - 1.0f + (float)(k%3) + dx;
        float y0 = floorf(ys), x0 = floorf(xs);
        float fy = ys - y0, fx = xs - x0;
        float vy0 = (y0 >= 0.f && y0 <= 127.f) ? 1.f : 0.f;
        float vy1 = (y0 >= -1.f && y0 <= 126.f) ? 1.f : 0.f;
        float vx0 = (x0 >= 0.f && x0 <= 127.f) ? 1.f : 0.f;
        float vx1 = (x0 >= -1.f && x0 <= 126.f) ? 1.f : 0.f;
        float w00 = (1.f-fy)*(1.f-fx) * vy0*vx0;
        float w01 = (1.f-fy)*fx       * vy0*vx1;
        float w10 = fy*(1.f-fx)       * vy1*vx0;
        float w11 = fy*fx             * vy1*vx1;
        int yi0 = min(max((int)y0, 0), 127);
        int yi1 = min(max((int)y0 + 1, 0), 127);
        int xi0 = min(max((int)x0, 0), 127);
        int xi1 = min(max((int)x0 + 1, 0), 127);
        int i00 = yi0*128 + xi0;
        int i01 = yi0*128 + xi1;
        int i10 = yi1*128 + xi0;
        int i11 = yi1*128 + xi1;
        #pragma unroll
        for (int cl = 0; cl < 8; cl++) {
            const float* xp = xb + (cl << 14);
            float sv = w00*xp[i00] + w01*xp[i01] + w10*xp[i10] + w11*xp[i11];
            acc[cl] += sv * wk[cl][k];
        }
    }
    #pragma unroll
    for (int cl = 0; cl < 8; cl++)
        g_y[(((size_t)b*DIM + 2*(c0+cl)) << 14) + hw] = acc[cl];
}

// ======================= weight pre-pack =======================
__global__ __launch_bounds__(256) void k_pack_w(const float* __restrict__ w1,
                                                const float* __restrict__ w2) {
    int i = blockIdx.x * 256 + threadIdx.x;
    if (i < 32768) {
        int k2 = i >> 9, n = i & 511;
        g_w1h[i] = pack_h2(w1[(size_t)(2*k2)*HID + n], w1[(size_t)(2*k2+1)*HID + n]);
    } else {
        int j = i - 32768;
        int k2 = j >> 7, n = j & 127;
        g_w2h[j] = pack_h2(w2[(size_t)(2*k2)*DIM + n], w2[(size_t)(2*k2+1)*DIM + n]);
    }
}

// ======================= BN1 (split by producer) =======================
template<int MODE>
__global__ __launch_bounds__(256) void k_bn1_part(void) {
    int nch = (MODE == 0) ? 32 : 96;
    int b = blockIdx.x / nch;
    int j = blockIdx.x % nch;
    int c;
    if (MODE == 0) c = 2*j;
    else           c = (j < 64) ? (2*j + 1) : (64 + 2*(j - 64));
    const float4* p = (const float4*)(g_y + (((size_t)b*DIM + c) << 14));
    float s = 0.f, q = 0.f;
    for (int i = threadIdx.x; i < HW/4; i += 256) {
        float4 v = p[i];
        s += v.x + v.y + v.z + v.w;
        q += v.x*v.x + v.y*v.y + v.z*v.z + v.w*v.w;
    }
    __shared__ float ss[256], qs[256];
    ss[threadIdx.x] = s; qs[threadIdx.x] = q;
    __syncthreads();
    for (int st = 128; st > 0; st >>= 1) {
        if (threadIdx.x < st) { ss[threadIdx.x] += ss[threadIdx.x+st]; qs[threadIdx.x] += qs[threadIdx.x+st]; }
        __syncthreads();
    }
    if (threadIdx.x == 0) { g_bn1_sum[b*DIM + c] = ss[0]; g_bn1_sq[b*DIM + c] = qs[0]; }
}

__global__ __launch_bounds__(512) void k_bn1_fold(const float* __restrict__ g,
                                                  const float* __restrict__ be,
                                                  const float* __restrict__ w1,
                                                  const float* __restrict__ b1) {
    __shared__ float sh_shift[DIM];
    int tid = threadIdx.x;
    if (tid < DIM) {
        float s = 0.f, q = 0.f;
        #pragma unroll
        for (int b = 0; b < BATCH; b++) { s += g_bn1_sum[b*DIM + tid]; q += g_bn1_sq[b*DIM + tid]; }
        float mean = s * (1.0f/NP);
        float var  = q * (1.0f/NP) - mean*mean;
        float rstd = rsqrtf(var + 1e-5f);
        float sc = g[tid] * rstd;
        float sh = be[tid] - mean * sc;
        g_scale1[tid] = sc;
        g_shift1[tid] = sh;
        sh_shift[tid] = sh;
    }
    __syncthreads();
    float bf = b1[tid];
    for (int k = 0; k < DIM; k++)
        bf += sh_shift[k] * w1[k*HID + tid];
    g_b1f[tid] = bf;
}

// ======================= fp16 mma GEMMs (pixel-tile offset for pipelining) ======
__global__ __launch_bounds__(256) void k_gemm1(int pb0) {
    extern __shared__ uint32_t sm4[];
    uint32_t* Af = sm4;
    uint32_t* Bc = sm4 + 128*AS2;
    float* ts = (float*)(sm4 + 128*AS2 + 128*BS2);
    int tid = threadIdx.x;
    int lane = tid & 31, wid = tid >> 5;
    int g = lane >> 2, t = lane & 3;
    int warp_m = wid >> 2, warp_n = wid & 3;
    int p0 = (blockIdx.x + pb0) * 128;
    int cb = (p0 >> 14) * DIM;
    int hw0 = p0 & (HW-1);

    #pragma unroll
    for (int l = 0; l < 32; l++) {
        int i = tid + l*256;
        int px = i & 127, k2 = i >> 7;
        float v0 = g_y[(size_t)(cb + 2*k2    )*HW + hw0 + px] * g_scale1[2*k2];
        float v1 = g_y[(size_t)(cb + 2*k2 + 1)*HW + hw0 + px] * g_scale1[2*k2 + 1];
        Af[px*AS2 + k2] = pack_h2(v0, v1);
    }

    for (int nt = 0; nt < 4; nt++) {
        int n0 = nt * 128;
        float acc[4][4][4] = {};
        for (int kc = 0; kc < 4; kc++) {
            __syncthreads();
            int kt2 = kc*16;
            #pragma unroll
            for (int l = 0; l < 8; l++) {
                int i = tid + l*256;
                int n = i & 127, k2 = i >> 7;
                Bc[n*BS2 + k2] = g_w1h[(size_t)(kt2 + k2)*HID + n0 + n];
            }
            __syncthreads();
            #pragma unroll
            for (int kst = 0; kst < 2; kst++) {
                int k2A = kc*16 + kst*8;
                int k2B = kst*8;
                uint32_t a[4][4], b[4][2];
                #pragma unroll
                for (int mi = 0; mi < 4; mi++) {
                    int row = warp_m*64 + mi*16 + g;
                    a[mi][0] = Af[row*AS2 + k2A + t];
                    a[mi][1] = Af[(row+8)*AS2 + k2A + t];
                    a[mi][2] = Af[row*AS2 + k2A + t + 4];
                    a[mi][3] = Af[(row+8)*AS2 + k2A + t + 4];
                }
                #pragma unroll
                for (int nf = 0; nf < 4; nf++) {
                    int col = warp_n*32 + nf*8 + g;
                    b[nf][0] = Bc[col*BS2 + k2B + t];
                    b[nf][1] = Bc[col*BS2 + k2B + t + 4];
                }
                #pragma unroll
                for (int mi = 0; mi < 4; mi++)
                    #pragma unroll
                    for (int nf = 0; nf < 4; nf++)
                        mma_f16(acc[mi][nf], a[mi], b[nf]);
            }
        }
        #pragma unroll
        for (int mi = 0; mi < 4; mi++) {
            int row = warp_m*64 + mi*16 + g;
            #pragma unroll
            for (int nf = 0; nf < 4; nf++) {
                int col = warp_n*32 + nf*8 + 2*t;
                float b0v = g_b1f[n0 + col], b1v = g_b1f[n0 + col + 1];
                ts[row*TSTR + col]       = gelu_exact(acc[mi][nf][0] + b0v);
                ts[row*TSTR + col + 1]   = gelu_exact(acc[mi][nf][1] + b1v);
                ts[(row+8)*TSTR + col]   = gelu_exact(acc[mi][nf][2] + b0v);
                ts[(row+8)*TSTR + col+1] = gelu_exact(acc[mi][nf][3] + b1v);
            }
        }
        __syncthreads();
        #pragma unroll
        for (int l = 0; l < 32; l++) {
            int i = tid + l*256;
            int n2 = i >> 7, p = i & 127;
            uint32_t h = pack_h2(ts[p*TSTR + 2*n2], ts[p*TSTR + 2*n2 + 1]);
            g_t2[(size_t)((n0 >> 1) + n2)*NP + p0 + p] = h;
        }
    }
}

__global__ __launch_bounds__(256) void k_gemm2(int pb0, const float* __restrict__ b2) {
    extern __shared__ uint32_t sm4[];
    uint32_t* Ac = sm4;
    uint32_t* Bc = sm4 + 128*BS2;
    float* ts = (float*)sm4;
    __shared__ float rs[256], rq[256];
    int tid = threadIdx.x;
    int lane = tid & 31, wid = tid >> 5;
    int g = lane >> 2, t = lane & 3;
    int warp_m = wid >> 2, warp_n = wid & 3;
    int blk = blockIdx.x + pb0;
    int p0 = blk * 128;

    #pragma unroll
    for (int l = 0; l < 8; l++) {
        int i = tid + l*256;
        int px = i & 127, k2 = i >> 7;
        Ac[px*BS2 + k2] = g_t2[(size_t)k2*NP + p0 + px];
    }
    #pragma unroll
    for (int l = 0; l < 8; l++) {
        int i = tid + l*256;
        int n = i & 127, k2 = i >> 7;
        Bc[n*BS2 + k2] = g_w2h[(size_t)k2*DIM + n];
    }
    __syncthreads();

    float acc[4][4][4] = {};
    for (int kc = 0; kc < 16; kc++) {
        uint32_t pa[8], pb[8];
        if (kc < 15) {
            int kt2 = (kc+1)*16;
            #pragma unroll
            for (int l = 0; l < 8; l++) {
                int i = tid + l*256;
                int px = i & 127, k2 = i >> 7;
                pa[l] = g_t2[(size_t)(kt2 + k2)*NP + p0 + px];
                pb[l] = g_w2h[(size_t)(kt2 + k2)*DIM + px];
            }
        }
        #pragma unroll
        for (int kst = 0; kst < 2; kst++) {
            int k2b = kst*8;
            uint32_t a[4][4], b[4][2];
            #pragma unroll
            for (int mi = 0; mi < 4; mi++) {
                int row = warp_m*64 + mi*16 + g;
                a[mi][0] = Ac[row*BS2 + k2b + t];
                a[mi][1] = Ac[(row+8)*BS2 + k2b + t];
                a[mi][2] = Ac[row*BS2 + k2b + t + 4];
                a[mi][3] = Ac[(row+8)*BS2 + k2b + t + 4];
            }
            #pragma unroll
            for (int nf = 0; nf < 4; nf++) {
                int col = warp_n*32 + nf*8 + g;
                b[nf][0] = Bc[col*BS2 + k2b + t];
                b[nf][1] = Bc[col*BS2 + k2b + t + 4];
            }
            #pragma unroll
            for (int mi = 0; mi < 4; mi++)
                #pragma unroll
                for (int nf = 0; nf < 4; nf++)
                    mma_f16(acc[mi][nf], a[mi], b[nf]);
        }
        __syncthreads();
        if (kc < 15) {
            #pragma unroll
            for (int l = 0; l < 8; l++) {
                int i = tid + l*256;
                int px = i & 127, k2 = i >> 7;
                Ac[px*BS2 + k2] = pa[l];
                Bc[px*BS2 + k2] = pb[l];
            }
            __syncthreads();
        }
    }
    #pragma unroll
    for (int mi = 0; mi < 4; mi++) {
        int row = warp_m*64 + mi*16 + g;
        #pragma unroll
        for (int nf = 0; nf < 4; nf++) {
            int col = warp_n*32 + nf*8 + 2*t;
            float b0v = b2[col], b1v = b2[col + 1];
            ts[row*TSTR + col]       = acc[mi][nf][0] + b0v;
            ts[row*TSTR + col + 1]   = acc[mi][nf][1] + b1v;
            ts[(row+8)*TSTR + col]   = acc[mi][nf][2] + b0v;
            ts[(row+8)*TSTR + col+1] = acc[mi][nf][3] + b1v;
        }
    }
    __syncthreads();
    #pragma unroll
    for (int l = 0; l < 64; l++) {
        int i = tid + l*256;
        int n = i >> 7, p = i & 127;
        g_c2[(size_t)n*NP + p0 + p] = ts[p*TSTR + n];
    }
    {
        int n = tid & 127;
        int ph = tid >> 7;
        float s = 0.f, q = 0.f;
        for (int p = ph; p < 128; p += 2) {
            float v = ts[p*TSTR + n];
            s += v; q += v*v;
        }
        rs[tid] = s; rq[tid] = q;
        __syncthreads();
        if (tid < 128) {
            g_bn2_sum[blk*128 + tid] = rs[tid] + rs[tid+128];
            g_bn2_sq [blk*128 + tid] = rq[tid] + rq[tid+128];
        }
    }
}

// ======================= BN2 final + output =======================
__global__ void k_bn2_final(const float* __restrict__ g, const float* __restrict__ be) {
    int c = blockIdx.x;
    int tid = threadIdx.x;
    __shared__ float ss[128], qs[128];
    float s = 0.f, q = 0.f;
    for (int i = tid; i < 512; i += 128) {
        s += g_bn2_sum[i*128 + c];
        q += g_bn2_sq [i*128 + c];
    }
    ss[tid] = s; qs[tid] = q;
    __syncthreads();
    for (int st = 64; st > 0; st >>= 1) {
        if (tid < st) { ss[tid] += ss[tid+st]; qs[tid] += qs[tid+st]; }
        __syncthreads();
    }
    if (tid == 0) {
        float mean = ss[0] * (1.0f/NP);
        float var  = qs[0] * (1.0f/NP) - mean*mean;
        float rstd = rsqrtf(var + 1e-5f);
        float sc = g[c] * rstd;
        g_scale2[c] = sc;
        g_shift2[c] = be[c] - mean * sc;
    }
}
__global__ __launch_bounds__(256) void k_final_v2(const float* __restrict__ x, float* __restrict__ out) {
    int i4 = blockIdx.x * 256 + threadIdx.x;
    int i = i4 << 2;
    int b = i >> 21;
    int c = (i >> 14) & 127;
    int hw = i & 16383;
    float sc = g_scale2[c], sh = g_shift2[c];
    float4 v = *(const float4*)(g_c2 + (size_t)c*NP + (b<<14) + hw);
    float4 xv = *(const float4*)(x + i);
    float4 o;
    o.x = gelu_exact(xv.x + v.x*sc + sh);
    o.y = gelu_exact(xv.y + v.y*sc + sh);
    o.z = gelu_exact(xv.z + v.z*sc + sh);
    o.w = gelu_exact(xv.w + v.w*sc + sh);
    *(float4*)(out + i) = o;
}

// ================================ launch ================================
extern "C" void kernel_launch(void* const* d_in, const int* in_sizes, int n_in,
                              void* d_out, int out_size) {
    const float* x        = (const float*)d_in[0];
    const float* offset_w = (const float*)d_in[1];
    const float* offset_b = (const float*)d_in[2];
    const float* deform_w = (const float*)d_in[3];
    const float* dw_w     = (const float*)d_in[4];
    const float* dw_b     = (const float*)d_in[5];
    const float* dw2_w    = (const float*)d_in[6];
    const float* dw2_b    = (const float*)d_in[7];
    const float* bn1_g    = (const float*)d_in[8];
    const float* bn1_b    = (const float*)d_in[9];
    const float* w1       = (const float*)d_in[10];
    const float* b1       = (const float*)d_in[11];
    const float* w2       = (const float*)d_in[12];
    const float* b2       = (const float*)d_in[13];
    const float* bn2_g    = (const float*)d_in[14];
    const float* bn2_b    = (const float*)d_in[15];
    float* out = (float*)d_out;

    static int inited = 0;
    static cudaStream_t sA, sB, sC;
    static cudaEvent_t e0, eA, eB, eC, eBC, eG1, eG2;
    if (!inited) {
        cudaFuncSetAttribute(k_gemm1, cudaFuncAttributeMaxDynamicSharedMemorySize, G1SMEM);
        cudaFuncSetAttribute(k_gemm2, cudaFuncAttributeMaxDynamicSharedMemorySize, G2SMEM);
        cudaFuncSetAttribute(k_conv_h<18,1,0,0>, cudaFuncAttributeMaxDynamicSharedMemorySize, CONV_SMEM);
        cudaFuncSetAttribute(k_conv_h<32,2,96,1>, cudaFuncAttributeMaxDynamicSharedMemorySize, CONV_SMEM);
        cudaStreamCreateWithFlags(&sA, cudaStreamNonBlocking);
        cudaStreamCreateWithFlags(&sB, cudaStreamNonBlocking);
        cudaStreamCreateWithFlags(&sC, cudaStreamNonBlocking);
        cudaEventCreateWithFlags(&e0, cudaEventDisableTiming);
        cudaEventCreateWithFlags(&eA, cudaEventDisableTiming);
        cudaEventCreateWithFlags(&eB, cudaEventDisableTiming);
        cudaEventCreateWithFlags(&eC, cudaEventDisableTiming);
        cudaEventCreateWithFlags(&eBC, cudaEventDisableTiming);
        cudaEventCreateWithFlags(&eG1, cudaEventDisableTiming);
        cudaEventCreateWithFlags(&eG2, cudaEventDisableTiming);
        inited = 1;
    }

    float* goffp; cudaGetSymbolAddress((void**)&goffp, g_off);
    float* gyp;   cudaGetSymbolAddress((void**)&gyp, g_y);

    dim3 blk256(256);
    cudaEventRecord(e0, 0);
    // branch A: offset conv -> deform
    cudaStreamWaitEvent(sA, e0, 0);
    k_conv_h<18,1,0,0> <<<dim3(128, BATCH), blk256, CONV_SMEM, sA>>>(x, offset_w, offset_b, goffp);
    k_deform_v3        <<<dim3(64, 4, BATCH), blk256, 0, sA>>>(x, deform_w);
    // branch B: weight pack (hidden) then dilated conv
    cudaStreamWaitEvent(sB, e0, 0);
    k_pack_w<<<256, blk256, 0, sB>>>(w1, w2);
    k_conv_h<32,2,96,1><<<dim3(128, BATCH), blk256, CONV_SMEM, sB>>>(x, dw2_w, dw2_b, gyp);
    cudaEventRecord(eB, sB);
    // branch C: dw7
    cudaStreamWaitEvent(sC, e0, 0);
    k_dw7_v3           <<<dim3(16, GC2, BATCH), blk256, 0, sC>>>(x, dw_w, dw_b);
    cudaEventRecord(eC, sC);

    cudaStreamWaitEvent(sB, eC, 0);
    k_bn1_part<1><<<BATCH*96, blk256, 0, sB>>>();
    cudaEventRecord(eBC, sB);
    k_bn1_part<0><<<BATCH*32, blk256, 0, sA>>>();
    cudaEventRecord(eA, sA);

    cudaStreamWaitEvent(0, eA, 0);
    cudaStreamWaitEvent(0, eBC, 0);
    cudaStreamWaitEvent(0, eB, 0);

    k_bn1_fold<<<1, 512>>>(bn1_g, bn1_b, w1, b1);

    // pipelined GEMMs: g1a -> [g1b || g2a] -> g2b
    k_gemm1<<<256, 256, G1SMEM>>>(0);
    cudaEventRecord(eG1, 0);
    k_gemm1<<<256, 256, G1SMEM>>>(256);
    cudaStreamWaitEvent(sB, eG1, 0);
    k_gemm2<<<256, 256, G2SMEM, sB>>>(0, b2);
    cudaEventRecord(eG2, sB);
    k_gemm2<<<256, 256, G2SMEM>>>(256, b2);
    cudaStreamWaitEvent(0, eG2, 0);

    k_bn2_final<<<DIM, 128>>>(bn2_g, bn2_b);
    k_final_v2<<<(size_t)NP*DIM/1024, blk256>>>(x, out);
}